// round 5
// baseline (speedup 1.0000x reference)
#include <cuda_runtime.h>

#define EPSF 1e-10f
#define NI 100000
#define NU 100000
#define NR 6
#define BB 512
#define PP 100
#define QQ 40
#define P2 40
#define XS 12  // XT row stride (floats)

typedef unsigned long long ull;

// ---------------- persistent scratch (static device memory) -----------------
__device__ float g_iP[NI * 64];            // item_table @ W1_top
__device__ float g_uPA1[NU * 64];          // user_table @ A1_bot
__device__ float g_rP[NR * 64];            // rate_table @ W1_bot + gv_b1
__device__ float g_Wf[64 * 64];            // W2 @ A1_top
__device__ float g_bf[64];                 // b2 @ A1_top + b1a
__device__ float g_T12[(long)NR * NI * 128]; // interleaved: [0:64)=T1, [64:128)=T2
__device__ float g_hoI[BB * QQ * 64];
__device__ float g_hiI[BB * 64];
__device__ float g_hiS[BB * 64];

// ------------------------- f32x2 packed helpers ----------------------------
__device__ __forceinline__ ull pk2(float lo, float hi) {
  ull r; asm("mov.b64 %0, {%1,%2};" : "=l"(r) : "f"(lo), "f"(hi)); return r;
}
__device__ __forceinline__ void fma2(ull& d, ull a, ull b) {
  asm("fma.rn.f32x2 %0, %1, %2, %0;" : "+l"(d) : "l"(a), "l"(b));
}
__device__ __forceinline__ void upk(ull v, float& lo, float& hi) {
  asm("mov.b64 {%0,%1}, %2;" : "=f"(lo), "=f"(hi) : "l"(v));
}

// ---------------------------------------------------------------------------
// legacy warp GEMM (5 rows), used by tail kernels k2b / k3
// ---------------------------------------------------------------------------
template <int K>
__device__ __forceinline__ void wgemm(const float* __restrict__ sXT,
                                      const float* __restrict__ sW,
                                      int lane, float acc[5][2]) {
#pragma unroll 8
  for (int k = 0; k < K; k++) {
    float2 w = *reinterpret_cast<const float2*>(sW + k * 64 + 2 * lane);
    float4 x4 = *reinterpret_cast<const float4*>(sXT + k * 8);
    float x5 = sXT[k * 8 + 4];
    acc[0][0] = fmaf(x4.x, w.x, acc[0][0]); acc[0][1] = fmaf(x4.x, w.y, acc[0][1]);
    acc[1][0] = fmaf(x4.y, w.x, acc[1][0]); acc[1][1] = fmaf(x4.y, w.y, acc[1][1]);
    acc[2][0] = fmaf(x4.z, w.x, acc[2][0]); acc[2][1] = fmaf(x4.z, w.y, acc[2][1]);
    acc[3][0] = fmaf(x4.w, w.x, acc[3][0]); acc[3][1] = fmaf(x4.w, w.y, acc[3][1]);
    acc[4][0] = fmaf(x5,  w.x, acc[4][0]);  acc[4][1] = fmaf(x5,  w.y, acc[4][1]);
  }
}
__device__ __forceinline__ void wtrans(float* sT, int lane, const float acc[5][2]) {
#pragma unroll
  for (int j = 0; j < 5; j++) {
    sT[(2 * lane) * 8 + j]     = acc[j][0];
    sT[(2 * lane + 1) * 8 + j] = acc[j][1];
  }
}

// ---------------------------------------------------------------------------
// K0_pre: rP = rate@W1_bot + b1 ; Wf = W2@A1_top ; bf = b2@A1_top + b1a
// ---------------------------------------------------------------------------
__global__ __launch_bounds__(1024) void k0_pre(
    const float* __restrict__ rate_table, const float* __restrict__ gv_W1,
    const float* __restrict__ gv_b1, const float* __restrict__ gv_W2,
    const float* __restrict__ gv_b2, const float* __restrict__ atti_W1,
    const float* __restrict__ atti_b1) {
  int t = threadIdx.x;
  if (t < NR * 64) {
    int r = t >> 6, c = t & 63;
    float s = gv_b1[c];
    const float* W1b = gv_W1 + 4096;
#pragma unroll 8
    for (int k = 0; k < 64; k++) s = fmaf(rate_table[r * 64 + k], W1b[k * 64 + c], s);
    g_rP[t] = s;
  }
#pragma unroll
  for (int e = 0; e < 4; e++) {
    int idx = t + e * 1024;
    int k = idx >> 6, c = idx & 63;
    float s = 0.f;
#pragma unroll 8
    for (int j = 0; j < 64; j++) s = fmaf(gv_W2[k * 64 + j], atti_W1[j * 64 + c], s);
    g_Wf[idx] = s;
  }
  if (t < 64) {
    float s = atti_b1[t];
#pragma unroll 8
    for (int j = 0; j < 64; j++) s = fmaf(gv_b2[j], atti_W1[j * 64 + t], s);
    g_bf[t] = s;
  }
}

// ---------------------------------------------------------------------------
// K0_proj (FFMA2)
// ---------------------------------------------------------------------------
#define SMEM_K0P ((4096 + 4096 + 8 * 64 * XS) * 4)
__global__ __launch_bounds__(256) void k0_proj(
    const float* __restrict__ item_table, const float* __restrict__ user_table,
    const float* __restrict__ gv_W1, const float* __restrict__ atti_W1) {
  extern __shared__ float sm[];
  float* sWa = sm;
  float* sWb = sm + 4096;
  float* sXT = sm + 8192;

  int tid = threadIdx.x, lane = tid & 31, w = tid >> 5;
  for (int i = tid; i < 4096; i += 256) { sWa[i] = gv_W1[i]; sWb[i] = atti_W1[4096 + i]; }
  __syncthreads();
  float* myXT = sXT + w * (64 * XS);

  for (int it = 0; it < 5; it++) {
    int rid0 = blockIdx.x * 400 + it * 80 + w * 10;
    bool half2 = (rid0 >= NI);
    const float* src = half2 ? user_table : item_table;
    const float* sW = half2 ? sWb : sWa;
    float* dst = half2 ? g_uPA1 : g_iP;
    int base = half2 ? (rid0 - NI) : rid0;
#pragma unroll
    for (int j = 0; j < 10; j++) {
      const float* sp = src + (long)(base + j) * 64;
      myXT[lane * XS + j] = sp[lane];
      myXT[(lane + 32) * XS + j] = sp[lane + 32];
    }
    __syncwarp();
    ull a0[5], a1[5];
#pragma unroll
    for (int p = 0; p < 5; p++) { a0[p] = 0ull; a1[p] = 0ull; }
#pragma unroll 8
    for (int k = 0; k < 64; k++) {
      float4 xa = *reinterpret_cast<const float4*>(myXT + k * XS);
      float4 xb = *reinterpret_cast<const float4*>(myXT + k * XS + 4);
      float2 xc = *reinterpret_cast<const float2*>(myXT + k * XS + 8);
      ull xp0 = pk2(xa.x, xa.y), xp1 = pk2(xa.z, xa.w);
      ull xp2 = pk2(xb.x, xb.y), xp3 = pk2(xb.z, xb.w);
      ull xp4 = pk2(xc.x, xc.y);
      float2 wv = *reinterpret_cast<const float2*>(sW + k * 64 + 2 * lane);
      ull w0 = pk2(wv.x, wv.x), w1 = pk2(wv.y, wv.y);
      fma2(a0[0], xp0, w0); fma2(a1[0], xp0, w1);
      fma2(a0[1], xp1, w0); fma2(a1[1], xp1, w1);
      fma2(a0[2], xp2, w0); fma2(a1[2], xp2, w1);
      fma2(a0[3], xp3, w0); fma2(a1[3], xp3, w1);
      fma2(a0[4], xp4, w0); fma2(a1[4], xp4, w1);
    }
#pragma unroll
    for (int p = 0; p < 5; p++) {
      float r0c0, r1c0, r0c1, r1c1;
      upk(a0[p], r0c0, r1c0); upk(a1[p], r0c1, r1c1);
      *reinterpret_cast<float2*>(dst + (long)(base + 2 * p) * 64 + 2 * lane) =
          make_float2(r0c0, r0c1);
      *reinterpret_cast<float2*>(dst + (long)(base + 2 * p + 1) * 64 + 2 * lane) =
          make_float2(r1c0, r1c1);
    }
    __syncwarp();
  }
}

// ---------------------------------------------------------------------------
// K0_combo (FFMA2, fused dual GEMM) -> g_T12 interleaved
// ---------------------------------------------------------------------------
#define SMEM_K0C ((4096 + 4096 + 8 * 64 * XS + 384 + 64 + 64) * 4)
__global__ __launch_bounds__(256) void k0_combo(
    const float* __restrict__ gv_W2, const float* __restrict__ gv_b2) {
  extern __shared__ float sm[];
  float* sW2 = sm;
  float* sWf = sm + 4096;
  float* sXT = sm + 8192;
  float* srP = sm + 8192 + 6144;
  float* sb2 = srP + 384;
  float* sbf = sb2 + 64;

  int tid = threadIdx.x, lane = tid & 31, w = tid >> 5;
  for (int i = tid; i < 4096; i += 256) { sW2[i] = gv_W2[i]; sWf[i] = g_Wf[i]; }
  for (int i = tid; i < 384; i += 256) srP[i] = g_rP[i];
  if (tid < 64) { sb2[tid] = gv_b2[tid]; sbf[tid] = g_bf[tid]; }
  __syncthreads();
  float* myXT = sXT + w * (64 * XS);

  float2 bb1 = *reinterpret_cast<const float2*>(sb2 + 2 * lane);
  float2 bb2 = *reinterpret_cast<const float2*>(sbf + 2 * lane);
  ull b10 = pk2(bb1.x, bb1.x), b11 = pk2(bb1.y, bb1.y);
  ull b20 = pk2(bb2.x, bb2.x), b21 = pk2(bb2.y, bb2.y);

  for (int it = 0; it < 4; it++) {
    int rid0 = blockIdx.x * 320 + it * 80 + w * 10;
    int r = rid0 / NI;
    int i0 = rid0 - r * NI;
    const float* rp = srP + r * 64;
    float rp0 = rp[lane], rp1 = rp[lane + 32];
#pragma unroll
    for (int j = 0; j < 10; j++) {
      const float* ip = g_iP + (long)(i0 + j) * 64;
      myXT[lane * XS + j] = fmaxf(ip[lane] + rp0, 0.f);
      myXT[(lane + 32) * XS + j] = fmaxf(ip[lane + 32] + rp1, 0.f);
    }
    __syncwarp();
    ull a10[5], a11[5], a20[5], a21[5];
#pragma unroll
    for (int p = 0; p < 5; p++) { a10[p] = b10; a11[p] = b11; a20[p] = b20; a21[p] = b21; }
#pragma unroll 8
    for (int k = 0; k < 64; k++) {
      float4 xa = *reinterpret_cast<const float4*>(myXT + k * XS);
      float4 xb = *reinterpret_cast<const float4*>(myXT + k * XS + 4);
      float2 xc = *reinterpret_cast<const float2*>(myXT + k * XS + 8);
      ull xp0 = pk2(xa.x, xa.y), xp1 = pk2(xa.z, xa.w);
      ull xp2 = pk2(xb.x, xb.y), xp3 = pk2(xb.z, xb.w);
      ull xp4 = pk2(xc.x, xc.y);
      float2 w1v = *reinterpret_cast<const float2*>(sW2 + k * 64 + 2 * lane);
      float2 w2v = *reinterpret_cast<const float2*>(sWf + k * 64 + 2 * lane);
      ull w10 = pk2(w1v.x, w1v.x), w11 = pk2(w1v.y, w1v.y);
      ull w20 = pk2(w2v.x, w2v.x), w21 = pk2(w2v.y, w2v.y);
      fma2(a10[0], xp0, w10); fma2(a11[0], xp0, w11);
      fma2(a10[1], xp1, w10); fma2(a11[1], xp1, w11);
      fma2(a10[2], xp2, w10); fma2(a11[2], xp2, w11);
      fma2(a10[3], xp3, w10); fma2(a11[3], xp3, w11);
      fma2(a10[4], xp4, w10); fma2(a11[4], xp4, w11);
      fma2(a20[0], xp0, w20); fma2(a21[0], xp0, w21);
      fma2(a20[1], xp1, w20); fma2(a21[1], xp1, w21);
      fma2(a20[2], xp2, w20); fma2(a21[2], xp2, w21);
      fma2(a20[3], xp3, w20); fma2(a21[3], xp3, w21);
      fma2(a20[4], xp4, w20); fma2(a21[4], xp4, w21);
    }
#pragma unroll
    for (int p = 0; p < 5; p++) {
      float r0c0, r1c0, r0c1, r1c1;
      long o0 = (long)(rid0 + 2 * p) * 128 + 2 * lane;
      long o1 = (long)(rid0 + 2 * p + 1) * 128 + 2 * lane;
      upk(a10[p], r0c0, r1c0); upk(a11[p], r0c1, r1c1);
      *reinterpret_cast<float2*>(g_T12 + o0) = make_float2(r0c0, r0c1);
      *reinterpret_cast<float2*>(g_T12 + o1) = make_float2(r1c0, r1c1);
      upk(a20[p], r0c0, r1c0); upk(a21[p], r0c1, r1c1);
      *reinterpret_cast<float2*>(g_T12 + o0 + 64) = make_float2(r0c0, r0c1);
      *reinterpret_cast<float2*>(g_T12 + o1 + 64) = make_float2(r1c0, r1c1);
    }
    __syncwarp();
  }
}

// ---------------------------------------------------------------------------
// K2s1: merged gather/attention kernel.
//  blocks [0, 2560): social branch — 8 warps, warp w handles gid=bx*8+w.
//    Phase A: one T2 row per LANE (private 256B gather, relu-dot, exp) — no
//    per-row shuffle chains. Phase B: 40 independent coalesced T1 loads.
//  blocks [2560, 3072): item branch (b = bx-2560), round-4 k1 logic.
// smem floats: sAgg 4096 | sbAgg 64 | sA2 64 | sPC 8*64 | sAl 8*40 | sRid 8*40 | sZ 8*64
// ---------------------------------------------------------------------------
#define SMEM_K2S1 ((4096 + 64 + 64 + 512 + 320 + 320 + 512) * 4)
__global__ __launch_bounds__(256) void k2s1_attn(
    const int* __restrict__ uids,
    const int* __restrict__ u_user, const int* __restrict__ u_user_item,
    const int* __restrict__ u_item,
    const float* __restrict__ agg_W, const float* __restrict__ agg_b,
    const float* __restrict__ atti_W2, const float* __restrict__ atti_b2) {
  extern __shared__ float sm[];
  float* sAgg = sm;               // 4096
  float* sbAgg = sm + 4096;       // 64
  float* sA2 = sm + 4160;         // 64
  float* sPC = sm + 4224;         // 8*64
  float* sAl = sm + 4736;         // 8*40
  int*   iRid = reinterpret_cast<int*>(sm + 5056);  // 8*40
  float* sZ = sm + 5376;          // 8*64

  int bx = blockIdx.x, tid = threadIdx.x, lane = tid & 31, w = tid >> 5;
  for (int i = tid; i < 4096; i += 256) sAgg[i] = agg_W[i];
  if (tid < 64) { sbAgg[tid] = agg_b[tid]; sA2[tid] = atti_W2[tid]; }
  __syncthreads();
  float cb = atti_b2[0];

  if (bx < 2560) {
    // ---------------- social branch: one warp per (b,q) ----------------
    int gid = bx * 8 + w;
    int u = u_user[gid];
    sPC[w * 64 + lane] = g_uPA1[(long)u * 64 + lane];
    sPC[w * 64 + 32 + lane] = g_uPA1[(long)u * 64 + 32 + lane];
    __syncwarp();
    const int2* ip = reinterpret_cast<const int2*>(u_user_item + (long)gid * (P2 * 2));
    const float4* pcp = reinterpret_cast<const float4*>(sPC + w * 64);
    const float4* a2p = reinterpret_cast<const float4*>(sA2);

    float myden = 0.f;
#pragma unroll
    for (int pass = 0; pass < 2; pass++) {
      int r = pass * 32 + lane;
      bool act = (r < P2);
      float alpha = 0.f; int rid = 0;
      if (act) {
        int2 idx = ip[r];
        float m = (idx.x > 0) ? 1.f : 0.f;
        rid = idx.y * NI + idx.x;
        const float4* t2p = reinterpret_cast<const float4*>(g_T12 + (long)rid * 128 + 64);
        float s0 = 0.f, s1 = 0.f, s2 = 0.f, s3 = 0.f;
#pragma unroll
        for (int kk = 0; kk < 16; kk++) {
          float4 t2 = t2p[kk];
          float4 pc = pcp[kk];
          float4 a2 = a2p[kk];
          s0 = fmaf(fmaxf(fmaf(m, pc.x, t2.x), 0.f), a2.x, s0);
          s1 = fmaf(fmaxf(fmaf(m, pc.y, t2.y), 0.f), a2.y, s1);
          s2 = fmaf(fmaxf(fmaf(m, pc.z, t2.z), 0.f), a2.z, s2);
          s3 = fmaf(fmaxf(fmaf(m, pc.w, t2.w), 0.f), a2.w, s3);
        }
        alpha = __expf((s0 + s1) + (s2 + s3) + cb) * m;
        sAl[w * 40 + r] = alpha;
        iRid[w * 40 + r] = rid;
      }
      myden += alpha;
    }
#pragma unroll
    for (int o = 16; o; o >>= 1) myden += __shfl_xor_sync(0xffffffffu, myden, o);
    float dinv = 1.f / (myden + EPSF);
    __syncwarp();

    float ax = 0.f, ay = 0.f;
#pragma unroll 8
    for (int r = 0; r < P2; r++) {
      float al = sAl[w * 40 + r];
      int rid = iRid[w * 40 + r];
      float2 t1 = *reinterpret_cast<const float2*>(g_T12 + (long)rid * 128 + 2 * lane);
      ax = fmaf(al, t1.x, ax); ay = fmaf(al, t1.y, ay);
    }
    sZ[w * 64 + 2 * lane] = ax * dinv;
    sZ[w * 64 + 2 * lane + 1] = ay * dinv;
    __syncwarp();
    float ox = sbAgg[2 * lane], oy = sbAgg[2 * lane + 1];
#pragma unroll 8
    for (int k = 0; k < 64; k++) {
      float zk = sZ[w * 64 + k];
      float2 wk = *reinterpret_cast<const float2*>(sAgg + k * 64 + 2 * lane);
      ox = fmaf(zk, wk.x, ox); oy = fmaf(zk, wk.y, oy);
    }
    *reinterpret_cast<float2*>(g_hoI + (long)gid * 64 + 2 * lane) =
        make_float2(fmaxf(ox, 0.f), fmaxf(oy, 0.f));
  } else {
    // ---------------- item branch: one CTA per b ----------------
    int b = bx - 2560;
    float* sPx = sZ;          // 8*64
    float* sPd = sAl;         // 8
    float* sZf = sPC;         // 64

    int u = uids[b];
    float2 pc = *reinterpret_cast<const float2*>(g_uPA1 + (long)u * 64 + 2 * lane);
    float2 a2 = *reinterpret_cast<const float2*>(sA2 + 2 * lane);
    const int2* ip = reinterpret_cast<const int2*>(u_item + (long)b * (PP * 2));

    float den = 0.f, ax = 0.f, ay = 0.f;
    for (int r = w; r < PP; r += 8) {
      int2 idx = ip[r];
      float m = (idx.x > 0) ? 1.f : 0.f;
      long off = ((long)idx.y * NI + idx.x) * 128 + 2 * lane;
      float2 t2 = *reinterpret_cast<const float2*>(g_T12 + off + 64);
      float2 t1 = *reinterpret_cast<const float2*>(g_T12 + off);
      float p = fmaxf(t2.x + m * pc.x, 0.f) * a2.x + fmaxf(t2.y + m * pc.y, 0.f) * a2.y;
#pragma unroll
      for (int o = 16; o; o >>= 1) p += __shfl_xor_sync(0xffffffffu, p, o);
      float al = __expf(p + cb) * m;
      den += al;
      ax = fmaf(al, t1.x, ax); ay = fmaf(al, t1.y, ay);
    }
    sPx[w * 64 + 2 * lane] = ax;
    sPx[w * 64 + 2 * lane + 1] = ay;
    if (lane == 0) sPd[w] = den;
    __syncthreads();
    if (tid < 64) {
      float z = 0.f, d = 0.f;
#pragma unroll
      for (int ww = 0; ww < 8; ww++) { z += sPx[ww * 64 + tid]; d += sPd[ww]; }
      sZf[tid] = z * (1.f / (d + EPSF));
    }
    __syncthreads();
    if (tid < 64) {
      float s = sbAgg[tid];
#pragma unroll 8
      for (int k = 0; k < 64; k++) s = fmaf(sZf[k], sAgg[k * 64 + tid], s);
      g_hiI[b * 64 + tid] = fmaxf(s, 0.f);
    }
  }
}

// ---------------------------------------------------------------------------
// K2b: beta attention over q + h_iS (unchanged).
// ---------------------------------------------------------------------------
#define SMEM_K2B (20784 * 4)
__global__ __launch_bounds__(256) void k2b_user(
    const int* __restrict__ u_user, const float* __restrict__ user_table,
    const float* __restrict__ attu_W1, const float* __restrict__ attu_b1,
    const float* __restrict__ attu_W2, const float* __restrict__ attu_b2,
    const float* __restrict__ aggn_W, const float* __restrict__ aggn_b) {
  extern __shared__ float sm[];
  float* sU1 = sm;             float* sAggn = sm + 8192;
  float* sw2u = sm + 12288;    float* sb1u = sm + 12352;
  float* sbAggn = sm + 12416;  float* sZ = sm + 12480;
  float* sBeta = sm + 12544;   float* sRed = sm + 12584;
  float* sXT = sm + 12592;

  int b = blockIdx.x, tid = threadIdx.x, lane = tid & 31, w = tid >> 5;
  for (int i = tid; i < 8192; i += 256) sU1[i] = attu_W1[i];
  for (int i = tid; i < 4096; i += 256) sAggn[i] = aggn_W[i];
  if (tid < 64) { sw2u[tid] = attu_W2[tid]; sb1u[tid] = attu_b1[tid]; sbAggn[tid] = aggn_b[tid]; }
  __syncthreads();
  float cb2u = attu_b2[0];
  float* myXT = sXT + w * 1024;
  int rowbase = w * 5;
  float msk[5];
#pragma unroll
  for (int j = 0; j < 5; j++) {
    int row = rowbase + j;
    int uq = u_user[b * 40 + row];
    msk[j] = (uq > 0) ? 1.f : 0.f;
    const float* hp = g_hoI + (long)(b * 40 + row) * 64;
    const float* up = user_table + (long)uq * 64;
    myXT[lane * 8 + j] = hp[lane]; myXT[(lane + 32) * 8 + j] = hp[lane + 32];
    myXT[(lane + 64) * 8 + j] = up[lane]; myXT[(lane + 96) * 8 + j] = up[lane + 32];
  }
  __syncwarp();
  float acc[5][2];
#pragma unroll
  for (int j = 0; j < 5; j++) { acc[j][0] = sb1u[2 * lane]; acc[j][1] = sb1u[2 * lane + 1]; }
  wgemm<128>(myXT, sU1, lane, acc);
  float w0 = sw2u[2 * lane], w1 = sw2u[2 * lane + 1];
#pragma unroll
  for (int j = 0; j < 5; j++) {
    float p = fmaf(fmaxf(acc[j][0], 0.f), w0, fmaxf(acc[j][1], 0.f) * w1);
#pragma unroll
    for (int o = 16; o; o >>= 1) p += __shfl_xor_sync(0xffffffffu, p, o);
    if (lane == 0) sBeta[rowbase + j] = expf(p + cb2u) * msk[j];
  }
  __syncthreads();
  if (tid < 32) {
    float s = 0.f;
    for (int r = lane; r < 40; r += 32) s += sBeta[r];
#pragma unroll
    for (int o = 16; o; o >>= 1) s += __shfl_xor_sync(0xffffffffu, s, o);
    if (lane == 0) sRed[0] = s;
  }
  __syncthreads();
  float dinv = 1.f / (sRed[0] + EPSF);
  if (tid < 64) {
    float s = 0.f;
    for (int r = 0; r < 40; r++) s = fmaf(sBeta[r], g_hoI[(long)(b * 40 + r) * 64 + tid], s);
    sZ[tid] = s * dinv;
  }
  __syncthreads();
  if (tid < 64) {
    float s = sbAggn[tid];
    for (int k = 0; k < 64; k++) s = fmaf(sZ[k], sAggn[k * 64 + tid], s);
    g_hiS[b * 64 + tid] = fmaxf(s, 0.f);
  }
}

// ---------------------------------------------------------------------------
// K3: final 3-layer combine MLP (unchanged).
// ---------------------------------------------------------------------------
#define SMEM_K3 (24768 * 4)
__global__ __launch_bounds__(256) void k3_final(
    const float* __restrict__ cm_W1, const float* __restrict__ cm_b1,
    const float* __restrict__ cm_W2, const float* __restrict__ cm_b2,
    const float* __restrict__ cm_W3, const float* __restrict__ cm_b3,
    float* __restrict__ out) {
  extern __shared__ float sm[];
  float* sC1 = sm;          float* sC2 = sm + 8192;   float* sC3 = sm + 12288;
  float* sb1 = sm + 16384;  float* sb2 = sm + 16448;  float* sb3 = sm + 16512;
  float* sXT = sm + 16576;

  int tid = threadIdx.x, lane = tid & 31, w = tid >> 5;
  for (int i = tid; i < 8192; i += 256) sC1[i] = cm_W1[i];
  for (int i = tid; i < 4096; i += 256) { sC2[i] = cm_W2[i]; sC3[i] = cm_W3[i]; }
  if (tid < 64) { sb1[tid] = cm_b1[tid]; sb2[tid] = cm_b2[tid]; sb3[tid] = cm_b3[tid]; }
  __syncthreads();
  float* myXT = sXT + w * 1024;
  int rowbase = blockIdx.x * 40 + w * 5;
#pragma unroll
  for (int j = 0; j < 5; j++) {
    int row = rowbase + j;
    float x0 = 0, x1 = 0, x2 = 0, x3 = 0;
    if (row < BB) {
      x0 = g_hiI[row * 64 + lane]; x1 = g_hiI[row * 64 + 32 + lane];
      x2 = g_hiS[row * 64 + lane]; x3 = g_hiS[row * 64 + 32 + lane];
    }
    myXT[lane * 8 + j] = x0; myXT[(lane + 32) * 8 + j] = x1;
    myXT[(lane + 64) * 8 + j] = x2; myXT[(lane + 96) * 8 + j] = x3;
  }
  __syncwarp();
  float acc[5][2];
#pragma unroll
  for (int j = 0; j < 5; j++) { acc[j][0] = sb1[2 * lane]; acc[j][1] = sb1[2 * lane + 1]; }
  wgemm<128>(myXT, sC1, lane, acc);
#pragma unroll
  for (int j = 0; j < 5; j++) { acc[j][0] = fmaxf(acc[j][0], 0.f); acc[j][1] = fmaxf(acc[j][1], 0.f); }
  __syncwarp(); wtrans(myXT, lane, acc); __syncwarp();
#pragma unroll
  for (int j = 0; j < 5; j++) { acc[j][0] = sb2[2 * lane]; acc[j][1] = sb2[2 * lane + 1]; }
  wgemm<64>(myXT, sC2, lane, acc);
#pragma unroll
  for (int j = 0; j < 5; j++) { acc[j][0] = fmaxf(acc[j][0], 0.f); acc[j][1] = fmaxf(acc[j][1], 0.f); }
  __syncwarp(); wtrans(myXT, lane, acc); __syncwarp();
#pragma unroll
  for (int j = 0; j < 5; j++) { acc[j][0] = sb3[2 * lane]; acc[j][1] = sb3[2 * lane + 1]; }
  wgemm<64>(myXT, sC3, lane, acc);
#pragma unroll
  for (int j = 0; j < 5; j++) {
    int row = rowbase + j;
    if (row < BB) {
      out[row * 64 + 2 * lane]     = fmaxf(acc[j][0], 0.f);
      out[row * 64 + 2 * lane + 1] = fmaxf(acc[j][1], 0.f);
    }
  }
}

// ---------------------------------------------------------------------------
extern "C" void kernel_launch(void* const* d_in, const int* in_sizes, int n_in,
                              void* d_out, int out_size) {
  const int* uids        = (const int*)d_in[0];
  const int* u_item      = (const int*)d_in[1];
  const int* u_user      = (const int*)d_in[2];
  const int* u_user_item = (const int*)d_in[3];
  const float* user_table = (const float*)d_in[4];
  const float* item_table = (const float*)d_in[5];
  const float* rate_table = (const float*)d_in[6];
  const float* gv_W1 = (const float*)d_in[7];   const float* gv_b1 = (const float*)d_in[8];
  const float* gv_W2 = (const float*)d_in[9];   const float* gv_b2 = (const float*)d_in[10];
  const float* atti_W1 = (const float*)d_in[11]; const float* atti_b1 = (const float*)d_in[12];
  const float* atti_W2 = (const float*)d_in[13]; const float* atti_b2 = (const float*)d_in[14];
  const float* agg_W = (const float*)d_in[15];   const float* agg_b = (const float*)d_in[16];
  const float* attu_W1 = (const float*)d_in[17]; const float* attu_b1 = (const float*)d_in[18];
  const float* attu_W2 = (const float*)d_in[19]; const float* attu_b2 = (const float*)d_in[20];
  const float* aggn_W = (const float*)d_in[21];  const float* aggn_b = (const float*)d_in[22];
  const float* cm_W1 = (const float*)d_in[23];   const float* cm_b1 = (const float*)d_in[24];
  const float* cm_W2 = (const float*)d_in[25];   const float* cm_b2 = (const float*)d_in[26];
  const float* cm_W3 = (const float*)d_in[27];   const float* cm_b3 = (const float*)d_in[28];
  float* out = (float*)d_out;

  cudaFuncSetAttribute(k0_proj,   cudaFuncAttributeMaxDynamicSharedMemorySize, SMEM_K0P);
  cudaFuncSetAttribute(k0_combo,  cudaFuncAttributeMaxDynamicSharedMemorySize, SMEM_K0C);
  cudaFuncSetAttribute(k2s1_attn, cudaFuncAttributeMaxDynamicSharedMemorySize, SMEM_K2S1);
  cudaFuncSetAttribute(k2b_user,  cudaFuncAttributeMaxDynamicSharedMemorySize, SMEM_K2B);
  cudaFuncSetAttribute(k3_final,  cudaFuncAttributeMaxDynamicSharedMemorySize, SMEM_K3);

  k0_pre<<<1, 1024>>>(rate_table, gv_W1, gv_b1, gv_W2, gv_b2, atti_W1, atti_b1);
  k0_proj<<<500, 256, SMEM_K0P>>>(item_table, user_table, gv_W1, atti_W1);
  k0_combo<<<1875, 256, SMEM_K0C>>>(gv_W2, gv_b2);
  k2s1_attn<<<3072, 256, SMEM_K2S1>>>(uids, u_user, u_user_item, u_item,
                                      agg_W, agg_b, atti_W2, atti_b2);
  k2b_user<<<512, 256, SMEM_K2B>>>(u_user, user_table, attu_W1, attu_b1, attu_W2,
                                   attu_b2, aggn_W, aggn_b);
  k3_final<<<13, 256, SMEM_K3>>>(cm_W1, cm_b1, cm_W2, cm_b2, cm_W3, cm_b3, out);
}

// round 6
// speedup vs baseline: 1.3106x; 1.3106x over previous
#include <cuda_runtime.h>

#define EPSF 1e-10f
#define NI 100000
#define NU 100000
#define NR 6
#define BB 512
#define PP 100
#define QQ 40
#define P2 40
#define XS 12  // XT row stride (floats)

typedef unsigned long long ull;

// ---------------- persistent scratch (static device memory) -----------------
__device__ float g_iP[NI * 64];            // item_table @ W1_top
__device__ float g_uPA1[NU * 64];          // user_table @ A1_bot
__device__ float g_rP[NR * 64];            // rate_table @ W1_bot + gv_b1
__device__ float g_Wf[64 * 64];            // W2 @ A1_top
__device__ float g_bf[64];                 // b2 @ A1_top + b1a
__device__ float g_T12[(long)NR * NI * 128]; // interleaved: [0:64)=T1, [64:128)=T2
__device__ float g_hoI[BB * QQ * 64];
__device__ float g_hiI[BB * 64];
__device__ float g_hiS[BB * 64];

// ------------------------- f32x2 packed helpers ----------------------------
__device__ __forceinline__ ull pk2(float lo, float hi) {
  ull r; asm("mov.b64 %0, {%1,%2};" : "=l"(r) : "f"(lo), "f"(hi)); return r;
}
__device__ __forceinline__ void fma2(ull& d, ull a, ull b) {
  asm("fma.rn.f32x2 %0, %1, %2, %0;" : "+l"(d) : "l"(a), "l"(b));
}
__device__ __forceinline__ void upk(ull v, float& lo, float& hi) {
  asm("mov.b64 {%0,%1}, %2;" : "=f"(lo), "=f"(hi) : "l"(v));
}

// ---------------------------------------------------------------------------
// legacy warp GEMM (5 rows), used by tail kernels k2b / k3
// ---------------------------------------------------------------------------
template <int K>
__device__ __forceinline__ void wgemm(const float* __restrict__ sXT,
                                      const float* __restrict__ sW,
                                      int lane, float acc[5][2]) {
#pragma unroll 8
  for (int k = 0; k < K; k++) {
    float2 w = *reinterpret_cast<const float2*>(sW + k * 64 + 2 * lane);
    float4 x4 = *reinterpret_cast<const float4*>(sXT + k * 8);
    float x5 = sXT[k * 8 + 4];
    acc[0][0] = fmaf(x4.x, w.x, acc[0][0]); acc[0][1] = fmaf(x4.x, w.y, acc[0][1]);
    acc[1][0] = fmaf(x4.y, w.x, acc[1][0]); acc[1][1] = fmaf(x4.y, w.y, acc[1][1]);
    acc[2][0] = fmaf(x4.z, w.x, acc[2][0]); acc[2][1] = fmaf(x4.z, w.y, acc[2][1]);
    acc[3][0] = fmaf(x4.w, w.x, acc[3][0]); acc[3][1] = fmaf(x4.w, w.y, acc[3][1]);
    acc[4][0] = fmaf(x5,  w.x, acc[4][0]);  acc[4][1] = fmaf(x5,  w.y, acc[4][1]);
  }
}
__device__ __forceinline__ void wtrans(float* sT, int lane, const float acc[5][2]) {
#pragma unroll
  for (int j = 0; j < 5; j++) {
    sT[(2 * lane) * 8 + j]     = acc[j][0];
    sT[(2 * lane + 1) * 8 + j] = acc[j][1];
  }
}

// ---------------------------------------------------------------------------
// K0_pre
// ---------------------------------------------------------------------------
__global__ __launch_bounds__(1024) void k0_pre(
    const float* __restrict__ rate_table, const float* __restrict__ gv_W1,
    const float* __restrict__ gv_b1, const float* __restrict__ gv_W2,
    const float* __restrict__ gv_b2, const float* __restrict__ atti_W1,
    const float* __restrict__ atti_b1) {
  int t = threadIdx.x;
  if (t < NR * 64) {
    int r = t >> 6, c = t & 63;
    float s = gv_b1[c];
    const float* W1b = gv_W1 + 4096;
#pragma unroll 8
    for (int k = 0; k < 64; k++) s = fmaf(rate_table[r * 64 + k], W1b[k * 64 + c], s);
    g_rP[t] = s;
  }
#pragma unroll
  for (int e = 0; e < 4; e++) {
    int idx = t + e * 1024;
    int k = idx >> 6, c = idx & 63;
    float s = 0.f;
#pragma unroll 8
    for (int j = 0; j < 64; j++) s = fmaf(gv_W2[k * 64 + j], atti_W1[j * 64 + c], s);
    g_Wf[idx] = s;
  }
  if (t < 64) {
    float s = atti_b1[t];
#pragma unroll 8
    for (int j = 0; j < 64; j++) s = fmaf(gv_b2[j], atti_W1[j * 64 + t], s);
    g_bf[t] = s;
  }
}

// ---------------------------------------------------------------------------
// K0_proj (FFMA2)
// ---------------------------------------------------------------------------
#define SMEM_K0P ((4096 + 4096 + 8 * 64 * XS) * 4)
__global__ __launch_bounds__(256) void k0_proj(
    const float* __restrict__ item_table, const float* __restrict__ user_table,
    const float* __restrict__ gv_W1, const float* __restrict__ atti_W1) {
  extern __shared__ float sm[];
  float* sWa = sm;
  float* sWb = sm + 4096;
  float* sXT = sm + 8192;

  int tid = threadIdx.x, lane = tid & 31, w = tid >> 5;
  for (int i = tid; i < 4096; i += 256) { sWa[i] = gv_W1[i]; sWb[i] = atti_W1[4096 + i]; }
  __syncthreads();
  float* myXT = sXT + w * (64 * XS);

  for (int it = 0; it < 5; it++) {
    int rid0 = blockIdx.x * 400 + it * 80 + w * 10;
    bool half2 = (rid0 >= NI);
    const float* src = half2 ? user_table : item_table;
    const float* sW = half2 ? sWb : sWa;
    float* dst = half2 ? g_uPA1 : g_iP;
    int base = half2 ? (rid0 - NI) : rid0;
#pragma unroll
    for (int j = 0; j < 10; j++) {
      const float* sp = src + (long)(base + j) * 64;
      myXT[lane * XS + j] = sp[lane];
      myXT[(lane + 32) * XS + j] = sp[lane + 32];
    }
    __syncwarp();
    ull a0[5], a1[5];
#pragma unroll
    for (int p = 0; p < 5; p++) { a0[p] = 0ull; a1[p] = 0ull; }
#pragma unroll 8
    for (int k = 0; k < 64; k++) {
      float4 xa = *reinterpret_cast<const float4*>(myXT + k * XS);
      float4 xb = *reinterpret_cast<const float4*>(myXT + k * XS + 4);
      float2 xc = *reinterpret_cast<const float2*>(myXT + k * XS + 8);
      ull xp0 = pk2(xa.x, xa.y), xp1 = pk2(xa.z, xa.w);
      ull xp2 = pk2(xb.x, xb.y), xp3 = pk2(xb.z, xb.w);
      ull xp4 = pk2(xc.x, xc.y);
      float2 wv = *reinterpret_cast<const float2*>(sW + k * 64 + 2 * lane);
      ull w0 = pk2(wv.x, wv.x), w1 = pk2(wv.y, wv.y);
      fma2(a0[0], xp0, w0); fma2(a1[0], xp0, w1);
      fma2(a0[1], xp1, w0); fma2(a1[1], xp1, w1);
      fma2(a0[2], xp2, w0); fma2(a1[2], xp2, w1);
      fma2(a0[3], xp3, w0); fma2(a1[3], xp3, w1);
      fma2(a0[4], xp4, w0); fma2(a1[4], xp4, w1);
    }
#pragma unroll
    for (int p = 0; p < 5; p++) {
      float r0c0, r1c0, r0c1, r1c1;
      upk(a0[p], r0c0, r1c0); upk(a1[p], r0c1, r1c1);
      *reinterpret_cast<float2*>(dst + (long)(base + 2 * p) * 64 + 2 * lane) =
          make_float2(r0c0, r0c1);
      *reinterpret_cast<float2*>(dst + (long)(base + 2 * p + 1) * 64 + 2 * lane) =
          make_float2(r1c0, r1c1);
    }
    __syncwarp();
  }
}

// ---------------------------------------------------------------------------
// K0_combo (FFMA2, fused dual GEMM) -> g_T12 interleaved
// ---------------------------------------------------------------------------
#define SMEM_K0C ((4096 + 4096 + 8 * 64 * XS + 384 + 64 + 64) * 4)
__global__ __launch_bounds__(256) void k0_combo(
    const float* __restrict__ gv_W2, const float* __restrict__ gv_b2) {
  extern __shared__ float sm[];
  float* sW2 = sm;
  float* sWf = sm + 4096;
  float* sXT = sm + 8192;
  float* srP = sm + 8192 + 6144;
  float* sb2 = srP + 384;
  float* sbf = sb2 + 64;

  int tid = threadIdx.x, lane = tid & 31, w = tid >> 5;
  for (int i = tid; i < 4096; i += 256) { sW2[i] = gv_W2[i]; sWf[i] = g_Wf[i]; }
  for (int i = tid; i < 384; i += 256) srP[i] = g_rP[i];
  if (tid < 64) { sb2[tid] = gv_b2[tid]; sbf[tid] = g_bf[tid]; }
  __syncthreads();
  float* myXT = sXT + w * (64 * XS);

  float2 bb1 = *reinterpret_cast<const float2*>(sb2 + 2 * lane);
  float2 bb2 = *reinterpret_cast<const float2*>(sbf + 2 * lane);
  ull b10 = pk2(bb1.x, bb1.x), b11 = pk2(bb1.y, bb1.y);
  ull b20 = pk2(bb2.x, bb2.x), b21 = pk2(bb2.y, bb2.y);

  for (int it = 0; it < 4; it++) {
    int rid0 = blockIdx.x * 320 + it * 80 + w * 10;
    int r = rid0 / NI;
    int i0 = rid0 - r * NI;
    const float* rp = srP + r * 64;
    float rp0 = rp[lane], rp1 = rp[lane + 32];
#pragma unroll
    for (int j = 0; j < 10; j++) {
      const float* ip = g_iP + (long)(i0 + j) * 64;
      myXT[lane * XS + j] = fmaxf(ip[lane] + rp0, 0.f);
      myXT[(lane + 32) * XS + j] = fmaxf(ip[lane + 32] + rp1, 0.f);
    }
    __syncwarp();
    ull a10[5], a11[5], a20[5], a21[5];
#pragma unroll
    for (int p = 0; p < 5; p++) { a10[p] = b10; a11[p] = b11; a20[p] = b20; a21[p] = b21; }
#pragma unroll 8
    for (int k = 0; k < 64; k++) {
      float4 xa = *reinterpret_cast<const float4*>(myXT + k * XS);
      float4 xb = *reinterpret_cast<const float4*>(myXT + k * XS + 4);
      float2 xc = *reinterpret_cast<const float2*>(myXT + k * XS + 8);
      ull xp0 = pk2(xa.x, xa.y), xp1 = pk2(xa.z, xa.w);
      ull xp2 = pk2(xb.x, xb.y), xp3 = pk2(xb.z, xb.w);
      ull xp4 = pk2(xc.x, xc.y);
      float2 w1v = *reinterpret_cast<const float2*>(sW2 + k * 64 + 2 * lane);
      float2 w2v = *reinterpret_cast<const float2*>(sWf + k * 64 + 2 * lane);
      ull w10 = pk2(w1v.x, w1v.x), w11 = pk2(w1v.y, w1v.y);
      ull w20 = pk2(w2v.x, w2v.x), w21 = pk2(w2v.y, w2v.y);
      fma2(a10[0], xp0, w10); fma2(a11[0], xp0, w11);
      fma2(a10[1], xp1, w10); fma2(a11[1], xp1, w11);
      fma2(a10[2], xp2, w10); fma2(a11[2], xp2, w11);
      fma2(a10[3], xp3, w10); fma2(a11[3], xp3, w11);
      fma2(a10[4], xp4, w10); fma2(a11[4], xp4, w11);
      fma2(a20[0], xp0, w20); fma2(a21[0], xp0, w21);
      fma2(a20[1], xp1, w20); fma2(a21[1], xp1, w21);
      fma2(a20[2], xp2, w20); fma2(a21[2], xp2, w21);
      fma2(a20[3], xp3, w20); fma2(a21[3], xp3, w21);
      fma2(a20[4], xp4, w20); fma2(a21[4], xp4, w21);
    }
#pragma unroll
    for (int p = 0; p < 5; p++) {
      float r0c0, r1c0, r0c1, r1c1;
      long o0 = (long)(rid0 + 2 * p) * 128 + 2 * lane;
      long o1 = (long)(rid0 + 2 * p + 1) * 128 + 2 * lane;
      upk(a10[p], r0c0, r1c0); upk(a11[p], r0c1, r1c1);
      *reinterpret_cast<float2*>(g_T12 + o0) = make_float2(r0c0, r0c1);
      *reinterpret_cast<float2*>(g_T12 + o1) = make_float2(r1c0, r1c1);
      upk(a20[p], r0c0, r1c0); upk(a21[p], r0c1, r1c1);
      *reinterpret_cast<float2*>(g_T12 + o0 + 64) = make_float2(r0c0, r0c1);
      *reinterpret_cast<float2*>(g_T12 + o1 + 64) = make_float2(r1c0, r1c1);
    }
    __syncwarp();
  }
}

// ---------------------------------------------------------------------------
// K2s1: merged attention kernel, register-frugal oct-slice geometry.
//  Warp handles one aggregation unit; within phase A, 8 lanes cover one row
//  (8 cols each, 3-step shfl), 4 rows in flight per warp-iteration.
//  blocks [0,64): item branch, warp w -> b = bx*8+w (P=100 rows).
//  blocks [64, 64+2560): social branch, warp w -> gid = (bx-64)*8+w (P=40).
// ---------------------------------------------------------------------------
__global__ __launch_bounds__(256) void k2s1_attn(
    const int* __restrict__ uids,
    const int* __restrict__ u_user, const int* __restrict__ u_user_item,
    const int* __restrict__ u_item,
    const float* __restrict__ agg_W, const float* __restrict__ agg_b,
    const float* __restrict__ atti_W2, const float* __restrict__ atti_b2) {
  __shared__ float sAgg[4096];
  __shared__ float sbAgg[64];
  __shared__ float sA2[64];
  __shared__ float sAl[8][100];
  __shared__ int   sRid[8][100];
  __shared__ float sZ[8][64];

  int bx = blockIdx.x, tid = threadIdx.x, lane = tid & 31, w = tid >> 5;
  for (int i = tid; i < 4096; i += 256) sAgg[i] = agg_W[i];
  if (tid < 64) { sbAgg[tid] = agg_b[tid]; sA2[tid] = atti_W2[tid]; }
  __syncthreads();
  float cb = atti_b2[0];

  bool item = (bx < 64);
  int unit = item ? (bx * 8 + w) : ((bx - 64) * 8 + w);  // b or gid
  int P = item ? PP : P2;
  int u = item ? uids[unit] : u_user[unit];
  const int2* ips = reinterpret_cast<const int2*>(
      item ? (u_item + (long)unit * (PP * 2)) : (u_user_item + (long)unit * (P2 * 2)));
  float* outp = item ? (g_hiI + (long)unit * 64) : (g_hoI + (long)unit * 64);

  int li = lane & 7, oct = lane >> 3;  // 8 lanes per row, 4 rows per iter
  const float* uP = g_uPA1 + (long)u * 64 + li * 8;
  float4 pcr0 = *reinterpret_cast<const float4*>(uP);
  float4 pcr1 = *reinterpret_cast<const float4*>(uP + 4);
  float4 a2r0 = *reinterpret_cast<const float4*>(sA2 + li * 8);
  float4 a2r1 = *reinterpret_cast<const float4*>(sA2 + li * 8 + 4);

  float den = 0.f;
  int niter = P >> 2;  // 40->10, 100->25 (exact)
  for (int it = 0; it < niter; it++) {
    int r = it * 4 + oct;
    int2 idx = ips[r];
    float m = (idx.x > 0) ? 1.f : 0.f;
    int rid = idx.y * NI + idx.x;
    const float4* t2p = reinterpret_cast<const float4*>(
        g_T12 + (long)rid * 128 + 64 + li * 8);
    float4 t2a = t2p[0], t2b = t2p[1];
    float s;
    s = fmaxf(fmaf(m, pcr0.x, t2a.x), 0.f) * a2r0.x;
    s = fmaf(fmaxf(fmaf(m, pcr0.y, t2a.y), 0.f), a2r0.y, s);
    s = fmaf(fmaxf(fmaf(m, pcr0.z, t2a.z), 0.f), a2r0.z, s);
    s = fmaf(fmaxf(fmaf(m, pcr0.w, t2a.w), 0.f), a2r0.w, s);
    s = fmaf(fmaxf(fmaf(m, pcr1.x, t2b.x), 0.f), a2r1.x, s);
    s = fmaf(fmaxf(fmaf(m, pcr1.y, t2b.y), 0.f), a2r1.y, s);
    s = fmaf(fmaxf(fmaf(m, pcr1.z, t2b.z), 0.f), a2r1.z, s);
    s = fmaf(fmaxf(fmaf(m, pcr1.w, t2b.w), 0.f), a2r1.w, s);
    s += __shfl_xor_sync(0xffffffffu, s, 1);
    s += __shfl_xor_sync(0xffffffffu, s, 2);
    s += __shfl_xor_sync(0xffffffffu, s, 4);
    if (li == 0) {
      float al = __expf(s + cb) * m;
      sAl[w][r] = al;
      sRid[w][r] = rid;
      den += al;
    }
  }
#pragma unroll
  for (int o = 16; o; o >>= 1) den += __shfl_xor_sync(0xffffffffu, den, o);
  float dinv = 1.f / (den + EPSF);
  __syncwarp();

  // Phase B: weighted T1 sum (coalesced, independent iterations)
  float ax = 0.f, ay = 0.f;
#pragma unroll 4
  for (int r = 0; r < P; r++) {
    float al = sAl[w][r];
    int rid = sRid[w][r];
    float2 t1 = *reinterpret_cast<const float2*>(g_T12 + (long)rid * 128 + 2 * lane);
    ax = fmaf(al, t1.x, ax); ay = fmaf(al, t1.y, ay);
  }
  sZ[w][2 * lane] = ax * dinv;
  sZ[w][2 * lane + 1] = ay * dinv;
  __syncwarp();

  // agg GEMM + relu
  float ox = sbAgg[2 * lane], oy = sbAgg[2 * lane + 1];
#pragma unroll 8
  for (int k = 0; k < 64; k++) {
    float zk = sZ[w][k];
    float2 wk = *reinterpret_cast<const float2*>(sAgg + k * 64 + 2 * lane);
    ox = fmaf(zk, wk.x, ox); oy = fmaf(zk, wk.y, oy);
  }
  *reinterpret_cast<float2*>(outp + 2 * lane) =
      make_float2(fmaxf(ox, 0.f), fmaxf(oy, 0.f));
}

// ---------------------------------------------------------------------------
// K2b: beta attention over q + h_iS (unchanged).
// ---------------------------------------------------------------------------
#define SMEM_K2B (20784 * 4)
__global__ __launch_bounds__(256) void k2b_user(
    const int* __restrict__ u_user, const float* __restrict__ user_table,
    const float* __restrict__ attu_W1, const float* __restrict__ attu_b1,
    const float* __restrict__ attu_W2, const float* __restrict__ attu_b2,
    const float* __restrict__ aggn_W, const float* __restrict__ aggn_b) {
  extern __shared__ float sm[];
  float* sU1 = sm;             float* sAggn = sm + 8192;
  float* sw2u = sm + 12288;    float* sb1u = sm + 12352;
  float* sbAggn = sm + 12416;  float* sZ = sm + 12480;
  float* sBeta = sm + 12544;   float* sRed = sm + 12584;
  float* sXT = sm + 12592;

  int b = blockIdx.x, tid = threadIdx.x, lane = tid & 31, w = tid >> 5;
  for (int i = tid; i < 8192; i += 256) sU1[i] = attu_W1[i];
  for (int i = tid; i < 4096; i += 256) sAggn[i] = aggn_W[i];
  if (tid < 64) { sw2u[tid] = attu_W2[tid]; sb1u[tid] = attu_b1[tid]; sbAggn[tid] = aggn_b[tid]; }
  __syncthreads();
  float cb2u = attu_b2[0];
  float* myXT = sXT + w * 1024;
  int rowbase = w * 5;
  float msk[5];
#pragma unroll
  for (int j = 0; j < 5; j++) {
    int row = rowbase + j;
    int uq = u_user[b * 40 + row];
    msk[j] = (uq > 0) ? 1.f : 0.f;
    const float* hp = g_hoI + (long)(b * 40 + row) * 64;
    const float* up = user_table + (long)uq * 64;
    myXT[lane * 8 + j] = hp[lane]; myXT[(lane + 32) * 8 + j] = hp[lane + 32];
    myXT[(lane + 64) * 8 + j] = up[lane]; myXT[(lane + 96) * 8 + j] = up[lane + 32];
  }
  __syncwarp();
  float acc[5][2];
#pragma unroll
  for (int j = 0; j < 5; j++) { acc[j][0] = sb1u[2 * lane]; acc[j][1] = sb1u[2 * lane + 1]; }
  wgemm<128>(myXT, sU1, lane, acc);
  float w0 = sw2u[2 * lane], w1 = sw2u[2 * lane + 1];
#pragma unroll
  for (int j = 0; j < 5; j++) {
    float p = fmaf(fmaxf(acc[j][0], 0.f), w0, fmaxf(acc[j][1], 0.f) * w1);
#pragma unroll
    for (int o = 16; o; o >>= 1) p += __shfl_xor_sync(0xffffffffu, p, o);
    if (lane == 0) sBeta[rowbase + j] = expf(p + cb2u) * msk[j];
  }
  __syncthreads();
  if (tid < 32) {
    float s = 0.f;
    for (int r = lane; r < 40; r += 32) s += sBeta[r];
#pragma unroll
    for (int o = 16; o; o >>= 1) s += __shfl_xor_sync(0xffffffffu, s, o);
    if (lane == 0) sRed[0] = s;
  }
  __syncthreads();
  float dinv = 1.f / (sRed[0] + EPSF);
  if (tid < 64) {
    float s = 0.f;
    for (int r = 0; r < 40; r++) s = fmaf(sBeta[r], g_hoI[(long)(b * 40 + r) * 64 + tid], s);
    sZ[tid] = s * dinv;
  }
  __syncthreads();
  if (tid < 64) {
    float s = sbAggn[tid];
    for (int k = 0; k < 64; k++) s = fmaf(sZ[k], sAggn[k * 64 + tid], s);
    g_hiS[b * 64 + tid] = fmaxf(s, 0.f);
  }
}

// ---------------------------------------------------------------------------
// K3: final 3-layer combine MLP (unchanged).
// ---------------------------------------------------------------------------
#define SMEM_K3 (24768 * 4)
__global__ __launch_bounds__(256) void k3_final(
    const float* __restrict__ cm_W1, const float* __restrict__ cm_b1,
    const float* __restrict__ cm_W2, const float* __restrict__ cm_b2,
    const float* __restrict__ cm_W3, const float* __restrict__ cm_b3,
    float* __restrict__ out) {
  extern __shared__ float sm[];
  float* sC1 = sm;          float* sC2 = sm + 8192;   float* sC3 = sm + 12288;
  float* sb1 = sm + 16384;  float* sb2 = sm + 16448;  float* sb3 = sm + 16512;
  float* sXT = sm + 16576;

  int tid = threadIdx.x, lane = tid & 31, w = tid >> 5;
  for (int i = tid; i < 8192; i += 256) sC1[i] = cm_W1[i];
  for (int i = tid; i < 4096; i += 256) { sC2[i] = cm_W2[i]; sC3[i] = cm_W3[i]; }
  if (tid < 64) { sb1[tid] = cm_b1[tid]; sb2[tid] = cm_b2[tid]; sb3[tid] = cm_b3[tid]; }
  __syncthreads();
  float* myXT = sXT + w * 1024;
  int rowbase = blockIdx.x * 40 + w * 5;
#pragma unroll
  for (int j = 0; j < 5; j++) {
    int row = rowbase + j;
    float x0 = 0, x1 = 0, x2 = 0, x3 = 0;
    if (row < BB) {
      x0 = g_hiI[row * 64 + lane]; x1 = g_hiI[row * 64 + 32 + lane];
      x2 = g_hiS[row * 64 + lane]; x3 = g_hiS[row * 64 + 32 + lane];
    }
    myXT[lane * 8 + j] = x0; myXT[(lane + 32) * 8 + j] = x1;
    myXT[(lane + 64) * 8 + j] = x2; myXT[(lane + 96) * 8 + j] = x3;
  }
  __syncwarp();
  float acc[5][2];
#pragma unroll
  for (int j = 0; j < 5; j++) { acc[j][0] = sb1[2 * lane]; acc[j][1] = sb1[2 * lane + 1]; }
  wgemm<128>(myXT, sC1, lane, acc);
#pragma unroll
  for (int j = 0; j < 5; j++) { acc[j][0] = fmaxf(acc[j][0], 0.f); acc[j][1] = fmaxf(acc[j][1], 0.f); }
  __syncwarp(); wtrans(myXT, lane, acc); __syncwarp();
#pragma unroll
  for (int j = 0; j < 5; j++) { acc[j][0] = sb2[2 * lane]; acc[j][1] = sb2[2 * lane + 1]; }
  wgemm<64>(myXT, sC2, lane, acc);
#pragma unroll
  for (int j = 0; j < 5; j++) { acc[j][0] = fmaxf(acc[j][0], 0.f); acc[j][1] = fmaxf(acc[j][1], 0.f); }
  __syncwarp(); wtrans(myXT, lane, acc); __syncwarp();
#pragma unroll
  for (int j = 0; j < 5; j++) { acc[j][0] = sb3[2 * lane]; acc[j][1] = sb3[2 * lane + 1]; }
  wgemm<64>(myXT, sC3, lane, acc);
#pragma unroll
  for (int j = 0; j < 5; j++) {
    int row = rowbase + j;
    if (row < BB) {
      out[row * 64 + 2 * lane]     = fmaxf(acc[j][0], 0.f);
      out[row * 64 + 2 * lane + 1] = fmaxf(acc[j][1], 0.f);
    }
  }
}

// ---------------------------------------------------------------------------
extern "C" void kernel_launch(void* const* d_in, const int* in_sizes, int n_in,
                              void* d_out, int out_size) {
  const int* uids        = (const int*)d_in[0];
  const int* u_item      = (const int*)d_in[1];
  const int* u_user      = (const int*)d_in[2];
  const int* u_user_item = (const int*)d_in[3];
  const float* user_table = (const float*)d_in[4];
  const float* item_table = (const float*)d_in[5];
  const float* rate_table = (const float*)d_in[6];
  const float* gv_W1 = (const float*)d_in[7];   const float* gv_b1 = (const float*)d_in[8];
  const float* gv_W2 = (const float*)d_in[9];   const float* gv_b2 = (const float*)d_in[10];
  const float* atti_W1 = (const float*)d_in[11]; const float* atti_b1 = (const float*)d_in[12];
  const float* atti_W2 = (const float*)d_in[13]; const float* atti_b2 = (const float*)d_in[14];
  const float* agg_W = (const float*)d_in[15];   const float* agg_b = (const float*)d_in[16];
  const float* attu_W1 = (const float*)d_in[17]; const float* attu_b1 = (const float*)d_in[18];
  const float* attu_W2 = (const float*)d_in[19]; const float* attu_b2 = (const float*)d_in[20];
  const float* aggn_W = (const float*)d_in[21];  const float* aggn_b = (const float*)d_in[22];
  const float* cm_W1 = (const float*)d_in[23];   const float* cm_b1 = (const float*)d_in[24];
  const float* cm_W2 = (const float*)d_in[25];   const float* cm_b2 = (const float*)d_in[26];
  const float* cm_W3 = (const float*)d_in[27];   const float* cm_b3 = (const float*)d_in[28];
  float* out = (float*)d_out;

  cudaFuncSetAttribute(k0_proj,  cudaFuncAttributeMaxDynamicSharedMemorySize, SMEM_K0P);
  cudaFuncSetAttribute(k0_combo, cudaFuncAttributeMaxDynamicSharedMemorySize, SMEM_K0C);
  cudaFuncSetAttribute(k2b_user, cudaFuncAttributeMaxDynamicSharedMemorySize, SMEM_K2B);
  cudaFuncSetAttribute(k3_final, cudaFuncAttributeMaxDynamicSharedMemorySize, SMEM_K3);

  k0_pre<<<1, 1024>>>(rate_table, gv_W1, gv_b1, gv_W2, gv_b2, atti_W1, atti_b1);
  k0_proj<<<500, 256, SMEM_K0P>>>(item_table, user_table, gv_W1, atti_W1);
  k0_combo<<<1875, 256, SMEM_K0C>>>(gv_W2, gv_b2);
  k2s1_attn<<<64 + 2560, 256>>>(uids, u_user, u_user_item, u_item,
                                agg_W, agg_b, atti_W2, atti_b2);
  k2b_user<<<512, 256, SMEM_K2B>>>(u_user, user_table, attu_W1, attu_b1, attu_W2,
                                   attu_b2, aggn_W, aggn_b);
  k3_final<<<13, 256, SMEM_K3>>>(cm_W1, cm_b1, cm_W2, cm_b2, cm_W3, cm_b3, out);
}

// round 7
// speedup vs baseline: 1.4545x; 1.1098x over previous
#include <cuda_runtime.h>

#define EPSF 1e-10f
#define NI 100000
#define NU 100000
#define NR 6
#define BB 512
#define PP 100
#define QQ 40
#define P2 40
#define XS 12  // XT row stride (floats)

typedef unsigned long long ull;

// ---------------- persistent scratch (static device memory) -----------------
__device__ float g_iP[NI * 64];            // item_table @ W1_top
__device__ float g_uPA1[NU * 64];          // user_table @ A1_bot
__device__ float g_rP[NR * 64];            // rate_table @ W1_bot + gv_b1
__device__ float g_Wf[64 * 64];            // W2 @ A1_top
__device__ float g_bf[64];                 // b2 @ A1_top + b1a
__device__ float g_Wg[64 * 64];            // W2 @ agg_W
__device__ float g_bg[64];                 // b2 @ agg_W
__device__ float g_T12[(long)NR * NI * 128]; // interleaved: [0:64)=h1, [64:128)=T2
__device__ float g_hoI[BB * QQ * 64];
__device__ float g_hiI[BB * 64];
__device__ float g_hiS[BB * 64];

// ------------------------- f32x2 packed helpers ----------------------------
__device__ __forceinline__ ull pk2(float lo, float hi) {
  ull r; asm("mov.b64 %0, {%1,%2};" : "=l"(r) : "f"(lo), "f"(hi)); return r;
}
__device__ __forceinline__ void fma2(ull& d, ull a, ull b) {
  asm("fma.rn.f32x2 %0, %1, %2, %0;" : "+l"(d) : "l"(a), "l"(b));
}
__device__ __forceinline__ void upk(ull v, float& lo, float& hi) {
  asm("mov.b64 {%0,%1}, %2;" : "=f"(lo), "=f"(hi) : "l"(v));
}

// ---------------------------------------------------------------------------
// legacy warp GEMM (5 rows), used by tail kernels k2b / k3
// ---------------------------------------------------------------------------
template <int K>
__device__ __forceinline__ void wgemm(const float* __restrict__ sXT,
                                      const float* __restrict__ sW,
                                      int lane, float acc[5][2]) {
#pragma unroll 8
  for (int k = 0; k < K; k++) {
    float2 w = *reinterpret_cast<const float2*>(sW + k * 64 + 2 * lane);
    float4 x4 = *reinterpret_cast<const float4*>(sXT + k * 8);
    float x5 = sXT[k * 8 + 4];
    acc[0][0] = fmaf(x4.x, w.x, acc[0][0]); acc[0][1] = fmaf(x4.x, w.y, acc[0][1]);
    acc[1][0] = fmaf(x4.y, w.x, acc[1][0]); acc[1][1] = fmaf(x4.y, w.y, acc[1][1]);
    acc[2][0] = fmaf(x4.z, w.x, acc[2][0]); acc[2][1] = fmaf(x4.z, w.y, acc[2][1]);
    acc[3][0] = fmaf(x4.w, w.x, acc[3][0]); acc[3][1] = fmaf(x4.w, w.y, acc[3][1]);
    acc[4][0] = fmaf(x5,  w.x, acc[4][0]);  acc[4][1] = fmaf(x5,  w.y, acc[4][1]);
  }
}
__device__ __forceinline__ void wtrans(float* sT, int lane, const float acc[5][2]) {
#pragma unroll
  for (int j = 0; j < 5; j++) {
    sT[(2 * lane) * 8 + j]     = acc[j][0];
    sT[(2 * lane + 1) * 8 + j] = acc[j][1];
  }
}

// ---------------------------------------------------------------------------
// K0_pre: rP = rate@W1_bot + b1 ; Wf = W2@A1_top ; bf = b2@A1_top + b1a ;
//         Wg = W2@agg_W ; bg = b2@agg_W
// ---------------------------------------------------------------------------
__global__ __launch_bounds__(1024) void k0_pre(
    const float* __restrict__ rate_table, const float* __restrict__ gv_W1,
    const float* __restrict__ gv_b1, const float* __restrict__ gv_W2,
    const float* __restrict__ gv_b2, const float* __restrict__ atti_W1,
    const float* __restrict__ atti_b1, const float* __restrict__ agg_W) {
  int t = threadIdx.x;
  if (t < NR * 64) {
    int r = t >> 6, c = t & 63;
    float s = gv_b1[c];
    const float* W1b = gv_W1 + 4096;
#pragma unroll 8
    for (int k = 0; k < 64; k++) s = fmaf(rate_table[r * 64 + k], W1b[k * 64 + c], s);
    g_rP[t] = s;
  }
#pragma unroll
  for (int e = 0; e < 4; e++) {
    int idx = t + e * 1024;
    int k = idx >> 6, c = idx & 63;
    float s = 0.f, sg = 0.f;
#pragma unroll 8
    for (int j = 0; j < 64; j++) {
      s = fmaf(gv_W2[k * 64 + j], atti_W1[j * 64 + c], s);
      sg = fmaf(gv_W2[k * 64 + j], agg_W[j * 64 + c], sg);
    }
    g_Wf[idx] = s;
    g_Wg[idx] = sg;
  }
  if (t < 64) {
    float s = atti_b1[t], sg = 0.f;
#pragma unroll 8
    for (int j = 0; j < 64; j++) {
      s = fmaf(gv_b2[j], atti_W1[j * 64 + t], s);
      sg = fmaf(gv_b2[j], agg_W[j * 64 + t], sg);
    }
    g_bf[t] = s;
    g_bg[t] = sg;
  }
}

// ---------------------------------------------------------------------------
// K0_proj (FFMA2)
// ---------------------------------------------------------------------------
#define SMEM_K0P ((4096 + 4096 + 8 * 64 * XS) * 4)
__global__ __launch_bounds__(256) void k0_proj(
    const float* __restrict__ item_table, const float* __restrict__ user_table,
    const float* __restrict__ gv_W1, const float* __restrict__ atti_W1) {
  extern __shared__ float sm[];
  float* sWa = sm;
  float* sWb = sm + 4096;
  float* sXT = sm + 8192;

  int tid = threadIdx.x, lane = tid & 31, w = tid >> 5;
  for (int i = tid; i < 4096; i += 256) { sWa[i] = gv_W1[i]; sWb[i] = atti_W1[4096 + i]; }
  __syncthreads();
  float* myXT = sXT + w * (64 * XS);

  for (int it = 0; it < 5; it++) {
    int rid0 = blockIdx.x * 400 + it * 80 + w * 10;
    bool half2 = (rid0 >= NI);
    const float* src = half2 ? user_table : item_table;
    const float* sW = half2 ? sWb : sWa;
    float* dst = half2 ? g_uPA1 : g_iP;
    int base = half2 ? (rid0 - NI) : rid0;
#pragma unroll
    for (int j = 0; j < 10; j++) {
      const float* sp = src + (long)(base + j) * 64;
      myXT[lane * XS + j] = sp[lane];
      myXT[(lane + 32) * XS + j] = sp[lane + 32];
    }
    __syncwarp();
    ull a0[5], a1[5];
#pragma unroll
    for (int p = 0; p < 5; p++) { a0[p] = 0ull; a1[p] = 0ull; }
#pragma unroll 8
    for (int k = 0; k < 64; k++) {
      float4 xa = *reinterpret_cast<const float4*>(myXT + k * XS);
      float4 xb = *reinterpret_cast<const float4*>(myXT + k * XS + 4);
      float2 xc = *reinterpret_cast<const float2*>(myXT + k * XS + 8);
      ull xp0 = pk2(xa.x, xa.y), xp1 = pk2(xa.z, xa.w);
      ull xp2 = pk2(xb.x, xb.y), xp3 = pk2(xb.z, xb.w);
      ull xp4 = pk2(xc.x, xc.y);
      float2 wv = *reinterpret_cast<const float2*>(sW + k * 64 + 2 * lane);
      ull w0 = pk2(wv.x, wv.x), w1 = pk2(wv.y, wv.y);
      fma2(a0[0], xp0, w0); fma2(a1[0], xp0, w1);
      fma2(a0[1], xp1, w0); fma2(a1[1], xp1, w1);
      fma2(a0[2], xp2, w0); fma2(a1[2], xp2, w1);
      fma2(a0[3], xp3, w0); fma2(a1[3], xp3, w1);
      fma2(a0[4], xp4, w0); fma2(a1[4], xp4, w1);
    }
#pragma unroll
    for (int p = 0; p < 5; p++) {
      float r0c0, r1c0, r0c1, r1c1;
      upk(a0[p], r0c0, r1c0); upk(a1[p], r0c1, r1c1);
      *reinterpret_cast<float2*>(dst + (long)(base + 2 * p) * 64 + 2 * lane) =
          make_float2(r0c0, r0c1);
      *reinterpret_cast<float2*>(dst + (long)(base + 2 * p + 1) * 64 + 2 * lane) =
          make_float2(r1c0, r1c1);
    }
    __syncwarp();
  }
}

// ---------------------------------------------------------------------------
// K0_combo (FFMA2, single GEMM): for all 600000 (rate,item) combos:
//   h1 = relu(iP[i] + rP[r])        -> stored at g_T12[rid*128 + 0..63]
//   T2 = h1 @ Wf + bf               -> stored at g_T12[rid*128 + 64..127]
// grid 1875 x 256; 4 iters x 8 warps x 10 rows = 320 rows/CTA.
// ---------------------------------------------------------------------------
#define SMEM_K0C ((4096 + 8 * 64 * XS + 384 + 64) * 4)
__global__ __launch_bounds__(256) void k0_combo() {
  extern __shared__ float sm[];
  float* sWf = sm;                  // 4096
  float* sXT = sm + 4096;           // 6144
  float* srP = sm + 4096 + 6144;    // 384
  float* sbf = srP + 384;           // 64

  int tid = threadIdx.x, lane = tid & 31, w = tid >> 5;
  for (int i = tid; i < 4096; i += 256) sWf[i] = g_Wf[i];
  for (int i = tid; i < 384; i += 256) srP[i] = g_rP[i];
  if (tid < 64) sbf[tid] = g_bf[tid];
  __syncthreads();
  float* myXT = sXT + w * (64 * XS);

  float2 bb2 = *reinterpret_cast<const float2*>(sbf + 2 * lane);
  ull b20 = pk2(bb2.x, bb2.x), b21 = pk2(bb2.y, bb2.y);

  for (int it = 0; it < 4; it++) {
    int rid0 = blockIdx.x * 320 + it * 80 + w * 10;
    int r = rid0 / NI;
    int i0 = rid0 - r * NI;
    const float* rp = srP + r * 64;
    float rp0 = rp[lane], rp1 = rp[lane + 32];
#pragma unroll
    for (int j = 0; j < 10; j++) {
      const float* ip = g_iP + (long)(i0 + j) * 64;
      float v0 = fmaxf(ip[lane] + rp0, 0.f);
      float v1 = fmaxf(ip[lane + 32] + rp1, 0.f);
      myXT[lane * XS + j] = v0;
      myXT[(lane + 32) * XS + j] = v1;
      float* hp = g_T12 + (long)(rid0 + j) * 128;
      hp[lane] = v0;
      hp[lane + 32] = v1;
    }
    __syncwarp();
    ull a20[5], a21[5];
#pragma unroll
    for (int p = 0; p < 5; p++) { a20[p] = b20; a21[p] = b21; }
#pragma unroll 8
    for (int k = 0; k < 64; k++) {
      float4 xa = *reinterpret_cast<const float4*>(myXT + k * XS);
      float4 xb = *reinterpret_cast<const float4*>(myXT + k * XS + 4);
      float2 xc = *reinterpret_cast<const float2*>(myXT + k * XS + 8);
      ull xp0 = pk2(xa.x, xa.y), xp1 = pk2(xa.z, xa.w);
      ull xp2 = pk2(xb.x, xb.y), xp3 = pk2(xb.z, xb.w);
      ull xp4 = pk2(xc.x, xc.y);
      float2 w2v = *reinterpret_cast<const float2*>(sWf + k * 64 + 2 * lane);
      ull w20 = pk2(w2v.x, w2v.x), w21 = pk2(w2v.y, w2v.y);
      fma2(a20[0], xp0, w20); fma2(a21[0], xp0, w21);
      fma2(a20[1], xp1, w20); fma2(a21[1], xp1, w21);
      fma2(a20[2], xp2, w20); fma2(a21[2], xp2, w21);
      fma2(a20[3], xp3, w20); fma2(a21[3], xp3, w21);
      fma2(a20[4], xp4, w20); fma2(a21[4], xp4, w21);
    }
#pragma unroll
    for (int p = 0; p < 5; p++) {
      float r0c0, r1c0, r0c1, r1c1;
      long o0 = (long)(rid0 + 2 * p) * 128 + 64 + 2 * lane;
      long o1 = (long)(rid0 + 2 * p + 1) * 128 + 64 + 2 * lane;
      upk(a20[p], r0c0, r1c0); upk(a21[p], r0c1, r1c1);
      *reinterpret_cast<float2*>(g_T12 + o0) = make_float2(r0c0, r0c1);
      *reinterpret_cast<float2*>(g_T12 + o1) = make_float2(r1c0, r1c1);
    }
    __syncwarp();
  }
}

// ---------------------------------------------------------------------------
// K2s1: merged attention kernel (oct-slice phase A, coalesced phase B).
//  Epilogue uses Wg = W2@agg_W, bg = b2@agg_W:
//    out = relu( z@Wg + sigma*bg + agg_b ),  z = dinv*sum(alpha*h1),
//    sigma = den*dinv.
//  blocks [0,64): item branch, warp w -> b = bx*8+w (P=100).
//  blocks [64, 64+2560): social branch, warp w -> gid = (bx-64)*8+w (P=40).
// ---------------------------------------------------------------------------
__global__ __launch_bounds__(256) void k2s1_attn(
    const int* __restrict__ uids,
    const int* __restrict__ u_user, const int* __restrict__ u_user_item,
    const int* __restrict__ u_item,
    const float* __restrict__ agg_b,
    const float* __restrict__ atti_W2, const float* __restrict__ atti_b2) {
  __shared__ float sWg[4096];
  __shared__ float sbAgg[64];
  __shared__ float sbg[64];
  __shared__ float sA2[64];
  __shared__ float sAl[8][100];
  __shared__ int   sRid[8][100];
  __shared__ float sZ[8][64];

  int bx = blockIdx.x, tid = threadIdx.x, lane = tid & 31, w = tid >> 5;
  for (int i = tid; i < 4096; i += 256) sWg[i] = g_Wg[i];
  if (tid < 64) { sbAgg[tid] = agg_b[tid]; sbg[tid] = g_bg[tid]; sA2[tid] = atti_W2[tid]; }
  __syncthreads();
  float cb = atti_b2[0];

  bool item = (bx < 64);
  int unit = item ? (bx * 8 + w) : ((bx - 64) * 8 + w);  // b or gid
  int P = item ? PP : P2;
  int u = item ? uids[unit] : u_user[unit];
  const int2* ips = reinterpret_cast<const int2*>(
      item ? (u_item + (long)unit * (PP * 2)) : (u_user_item + (long)unit * (P2 * 2)));
  float* outp = item ? (g_hiI + (long)unit * 64) : (g_hoI + (long)unit * 64);

  int li = lane & 7, oct = lane >> 3;  // 8 lanes per row, 4 rows per iter
  const float* uP = g_uPA1 + (long)u * 64 + li * 8;
  float4 pcr0 = *reinterpret_cast<const float4*>(uP);
  float4 pcr1 = *reinterpret_cast<const float4*>(uP + 4);
  float4 a2r0 = *reinterpret_cast<const float4*>(sA2 + li * 8);
  float4 a2r1 = *reinterpret_cast<const float4*>(sA2 + li * 8 + 4);

  float den = 0.f;
  int niter = P >> 2;  // 40->10, 100->25 (exact)
  for (int it = 0; it < niter; it++) {
    int r = it * 4 + oct;
    int2 idx = ips[r];
    float m = (idx.x > 0) ? 1.f : 0.f;
    int rid = idx.y * NI + idx.x;
    const float4* t2p = reinterpret_cast<const float4*>(
        g_T12 + (long)rid * 128 + 64 + li * 8);
    float4 t2a = t2p[0], t2b = t2p[1];
    float s;
    s = fmaxf(fmaf(m, pcr0.x, t2a.x), 0.f) * a2r0.x;
    s = fmaf(fmaxf(fmaf(m, pcr0.y, t2a.y), 0.f), a2r0.y, s);
    s = fmaf(fmaxf(fmaf(m, pcr0.z, t2a.z), 0.f), a2r0.z, s);
    s = fmaf(fmaxf(fmaf(m, pcr0.w, t2a.w), 0.f), a2r0.w, s);
    s = fmaf(fmaxf(fmaf(m, pcr1.x, t2b.x), 0.f), a2r1.x, s);
    s = fmaf(fmaxf(fmaf(m, pcr1.y, t2b.y), 0.f), a2r1.y, s);
    s = fmaf(fmaxf(fmaf(m, pcr1.z, t2b.z), 0.f), a2r1.z, s);
    s = fmaf(fmaxf(fmaf(m, pcr1.w, t2b.w), 0.f), a2r1.w, s);
    s += __shfl_xor_sync(0xffffffffu, s, 1);
    s += __shfl_xor_sync(0xffffffffu, s, 2);
    s += __shfl_xor_sync(0xffffffffu, s, 4);
    if (li == 0) {
      float al = __expf(s + cb) * m;
      sAl[w][r] = al;
      sRid[w][r] = rid;
      den += al;
    }
  }
#pragma unroll
  for (int o = 16; o; o >>= 1) den += __shfl_xor_sync(0xffffffffu, den, o);
  float dinv = 1.f / (den + EPSF);
  float sig = den * dinv;
  __syncwarp();

  // Phase B: weighted h1 sum (coalesced, independent iterations)
  float ax = 0.f, ay = 0.f;
#pragma unroll 4
  for (int r = 0; r < P; r++) {
    float al = sAl[w][r];
    int rid = sRid[w][r];
    float2 h1 = *reinterpret_cast<const float2*>(g_T12 + (long)rid * 128 + 2 * lane);
    ax = fmaf(al, h1.x, ax); ay = fmaf(al, h1.y, ay);
  }
  sZ[w][2 * lane] = ax * dinv;
  sZ[w][2 * lane + 1] = ay * dinv;
  __syncwarp();

  // epilogue GEMV: out = relu(z@Wg + sig*bg + agg_b)
  float ox = fmaf(sig, sbg[2 * lane], sbAgg[2 * lane]);
  float oy = fmaf(sig, sbg[2 * lane + 1], sbAgg[2 * lane + 1]);
#pragma unroll 8
  for (int k = 0; k < 64; k++) {
    float zk = sZ[w][k];
    float2 wk = *reinterpret_cast<const float2*>(sWg + k * 64 + 2 * lane);
    ox = fmaf(zk, wk.x, ox); oy = fmaf(zk, wk.y, oy);
  }
  *reinterpret_cast<float2*>(outp + 2 * lane) =
      make_float2(fmaxf(ox, 0.f), fmaxf(oy, 0.f));
}

// ---------------------------------------------------------------------------
// K2b: beta attention over q + h_iS (unchanged).
// ---------------------------------------------------------------------------
#define SMEM_K2B (20784 * 4)
__global__ __launch_bounds__(256) void k2b_user(
    const int* __restrict__ u_user, const float* __restrict__ user_table,
    const float* __restrict__ attu_W1, const float* __restrict__ attu_b1,
    const float* __restrict__ attu_W2, const float* __restrict__ attu_b2,
    const float* __restrict__ aggn_W, const float* __restrict__ aggn_b) {
  extern __shared__ float sm[];
  float* sU1 = sm;             float* sAggn = sm + 8192;
  float* sw2u = sm + 12288;    float* sb1u = sm + 12352;
  float* sbAggn = sm + 12416;  float* sZ = sm + 12480;
  float* sBeta = sm + 12544;   float* sRed = sm + 12584;
  float* sXT = sm + 12592;

  int b = blockIdx.x, tid = threadIdx.x, lane = tid & 31, w = tid >> 5;
  for (int i = tid; i < 8192; i += 256) sU1[i] = attu_W1[i];
  for (int i = tid; i < 4096; i += 256) sAggn[i] = aggn_W[i];
  if (tid < 64) { sw2u[tid] = attu_W2[tid]; sb1u[tid] = attu_b1[tid]; sbAggn[tid] = aggn_b[tid]; }
  __syncthreads();
  float cb2u = attu_b2[0];
  float* myXT = sXT + w * 1024;
  int rowbase = w * 5;
  float msk[5];
#pragma unroll
  for (int j = 0; j < 5; j++) {
    int row = rowbase + j;
    int uq = u_user[b * 40 + row];
    msk[j] = (uq > 0) ? 1.f : 0.f;
    const float* hp = g_hoI + (long)(b * 40 + row) * 64;
    const float* up = user_table + (long)uq * 64;
    myXT[lane * 8 + j] = hp[lane]; myXT[(lane + 32) * 8 + j] = hp[lane + 32];
    myXT[(lane + 64) * 8 + j] = up[lane]; myXT[(lane + 96) * 8 + j] = up[lane + 32];
  }
  __syncwarp();
  float acc[5][2];
#pragma unroll
  for (int j = 0; j < 5; j++) { acc[j][0] = sb1u[2 * lane]; acc[j][1] = sb1u[2 * lane + 1]; }
  wgemm<128>(myXT, sU1, lane, acc);
  float w0 = sw2u[2 * lane], w1 = sw2u[2 * lane + 1];
#pragma unroll
  for (int j = 0; j < 5; j++) {
    float p = fmaf(fmaxf(acc[j][0], 0.f), w0, fmaxf(acc[j][1], 0.f) * w1);
#pragma unroll
    for (int o = 16; o; o >>= 1) p += __shfl_xor_sync(0xffffffffu, p, o);
    if (lane == 0) sBeta[rowbase + j] = expf(p + cb2u) * msk[j];
  }
  __syncthreads();
  if (tid < 32) {
    float s = 0.f;
    for (int r = lane; r < 40; r += 32) s += sBeta[r];
#pragma unroll
    for (int o = 16; o; o >>= 1) s += __shfl_xor_sync(0xffffffffu, s, o);
    if (lane == 0) sRed[0] = s;
  }
  __syncthreads();
  float dinv = 1.f / (sRed[0] + EPSF);
  if (tid < 64) {
    float s = 0.f;
    for (int r = 0; r < 40; r++) s = fmaf(sBeta[r], g_hoI[(long)(b * 40 + r) * 64 + tid], s);
    sZ[tid] = s * dinv;
  }
  __syncthreads();
  if (tid < 64) {
    float s = sbAggn[tid];
    for (int k = 0; k < 64; k++) s = fmaf(sZ[k], sAggn[k * 64 + tid], s);
    g_hiS[b * 64 + tid] = fmaxf(s, 0.f);
  }
}

// ---------------------------------------------------------------------------
// K3: final 3-layer combine MLP (unchanged).
// ---------------------------------------------------------------------------
#define SMEM_K3 (24768 * 4)
__global__ __launch_bounds__(256) void k3_final(
    const float* __restrict__ cm_W1, const float* __restrict__ cm_b1,
    const float* __restrict__ cm_W2, const float* __restrict__ cm_b2,
    const float* __restrict__ cm_W3, const float* __restrict__ cm_b3,
    float* __restrict__ out) {
  extern __shared__ float sm[];
  float* sC1 = sm;          float* sC2 = sm + 8192;   float* sC3 = sm + 12288;
  float* sb1 = sm + 16384;  float* sb2 = sm + 16448;  float* sb3 = sm + 16512;
  float* sXT = sm + 16576;

  int tid = threadIdx.x, lane = tid & 31, w = tid >> 5;
  for (int i = tid; i < 8192; i += 256) sC1[i] = cm_W1[i];
  for (int i = tid; i < 4096; i += 256) { sC2[i] = cm_W2[i]; sC3[i] = cm_W3[i]; }
  if (tid < 64) { sb1[tid] = cm_b1[tid]; sb2[tid] = cm_b2[tid]; sb3[tid] = cm_b3[tid]; }
  __syncthreads();
  float* myXT = sXT + w * 1024;
  int rowbase = blockIdx.x * 40 + w * 5;
#pragma unroll
  for (int j = 0; j < 5; j++) {
    int row = rowbase + j;
    float x0 = 0, x1 = 0, x2 = 0, x3 = 0;
    if (row < BB) {
      x0 = g_hiI[row * 64 + lane]; x1 = g_hiI[row * 64 + 32 + lane];
      x2 = g_hiS[row * 64 + lane]; x3 = g_hiS[row * 64 + 32 + lane];
    }
    myXT[lane * 8 + j] = x0; myXT[(lane + 32) * 8 + j] = x1;
    myXT[(lane + 64) * 8 + j] = x2; myXT[(lane + 96) * 8 + j] = x3;
  }
  __syncwarp();
  float acc[5][2];
#pragma unroll
  for (int j = 0; j < 5; j++) { acc[j][0] = sb1[2 * lane]; acc[j][1] = sb1[2 * lane + 1]; }
  wgemm<128>(myXT, sC1, lane, acc);
#pragma unroll
  for (int j = 0; j < 5; j++) { acc[j][0] = fmaxf(acc[j][0], 0.f); acc[j][1] = fmaxf(acc[j][1], 0.f); }
  __syncwarp(); wtrans(myXT, lane, acc); __syncwarp();
#pragma unroll
  for (int j = 0; j < 5; j++) { acc[j][0] = sb2[2 * lane]; acc[j][1] = sb2[2 * lane + 1]; }
  wgemm<64>(myXT, sC2, lane, acc);
#pragma unroll
  for (int j = 0; j < 5; j++) { acc[j][0] = fmaxf(acc[j][0], 0.f); acc[j][1] = fmaxf(acc[j][1], 0.f); }
  __syncwarp(); wtrans(myXT, lane, acc); __syncwarp();
#pragma unroll
  for (int j = 0; j < 5; j++) { acc[j][0] = sb3[2 * lane]; acc[j][1] = sb3[2 * lane + 1]; }
  wgemm<64>(myXT, sC3, lane, acc);
#pragma unroll
  for (int j = 0; j < 5; j++) {
    int row = rowbase + j;
    if (row < BB) {
      out[row * 64 + 2 * lane]     = fmaxf(acc[j][0], 0.f);
      out[row * 64 + 2 * lane + 1] = fmaxf(acc[j][1], 0.f);
    }
  }
}

// ---------------------------------------------------------------------------
extern "C" void kernel_launch(void* const* d_in, const int* in_sizes, int n_in,
                              void* d_out, int out_size) {
  const int* uids        = (const int*)d_in[0];
  const int* u_item      = (const int*)d_in[1];
  const int* u_user      = (const int*)d_in[2];
  const int* u_user_item = (const int*)d_in[3];
  const float* user_table = (const float*)d_in[4];
  const float* item_table = (const float*)d_in[5];
  const float* rate_table = (const float*)d_in[6];
  const float* gv_W1 = (const float*)d_in[7];   const float* gv_b1 = (const float*)d_in[8];
  const float* gv_W2 = (const float*)d_in[9];   const float* gv_b2 = (const float*)d_in[10];
  const float* atti_W1 = (const float*)d_in[11]; const float* atti_b1 = (const float*)d_in[12];
  const float* atti_W2 = (const float*)d_in[13]; const float* atti_b2 = (const float*)d_in[14];
  const float* agg_W = (const float*)d_in[15];   const float* agg_b = (const float*)d_in[16];
  const float* attu_W1 = (const float*)d_in[17]; const float* attu_b1 = (const float*)d_in[18];
  const float* attu_W2 = (const float*)d_in[19]; const float* attu_b2 = (const float*)d_in[20];
  const float* aggn_W = (const float*)d_in[21];  const float* aggn_b = (const float*)d_in[22];
  const float* cm_W1 = (const float*)d_in[23];   const float* cm_b1 = (const float*)d_in[24];
  const float* cm_W2 = (const float*)d_in[25];   const float* cm_b2 = (const float*)d_in[26];
  const float* cm_W3 = (const float*)d_in[27];   const float* cm_b3 = (const float*)d_in[28];
  float* out = (float*)d_out;

  cudaFuncSetAttribute(k0_proj,  cudaFuncAttributeMaxDynamicSharedMemorySize, SMEM_K0P);
  cudaFuncSetAttribute(k0_combo, cudaFuncAttributeMaxDynamicSharedMemorySize, SMEM_K0C);
  cudaFuncSetAttribute(k2b_user, cudaFuncAttributeMaxDynamicSharedMemorySize, SMEM_K2B);
  cudaFuncSetAttribute(k3_final, cudaFuncAttributeMaxDynamicSharedMemorySize, SMEM_K3);

  k0_pre<<<1, 1024>>>(rate_table, gv_W1, gv_b1, gv_W2, gv_b2, atti_W1, atti_b1, agg_W);
  k0_proj<<<500, 256, SMEM_K0P>>>(item_table, user_table, gv_W1, atti_W1);
  k0_combo<<<1875, 256, SMEM_K0C>>>();
  k2s1_attn<<<64 + 2560, 256>>>(uids, u_user, u_user_item, u_item,
                                agg_b, atti_W2, atti_b2);
  k2b_user<<<512, 256, SMEM_K2B>>>(u_user, user_table, attu_W1, attu_b1, attu_W2,
                                   attu_b2, aggn_W, aggn_b);
  k3_final<<<13, 256, SMEM_K3>>>(cm_W1, cm_b1, cm_W2, cm_b2, cm_W3, cm_b3, out);
}

// round 8
// speedup vs baseline: 1.5402x; 1.0589x over previous
#include <cuda_runtime.h>

#define EPSF 1e-10f
#define NI 100000
#define NU 100000
#define NR 6
#define BB 512
#define PP 100
#define QQ 40
#define P2 40
#define XS 12  // XT row stride (floats)

typedef unsigned long long ull;

// ---------------- persistent scratch (static device memory) -----------------
__device__ float g_iP[NI * 64];            // item_table @ W1_top
__device__ float g_uPA1[NU * 64];          // user_table @ A1_bot
__device__ float g_rP[NR * 64];            // rate_table @ W1_bot + gv_b1
__device__ float g_Wf[64 * 64];            // W2 @ A1_top
__device__ float g_bf[64];                 // b2 @ A1_top + b1a
__device__ float g_Wg[64 * 64];            // W2 @ agg_W
__device__ float g_bg[64];                 // b2 @ agg_W
__device__ float g_T2[(long)NR * NI * 64]; // T2 = h1@Wf + bf per (rate,item)
__device__ float g_hoI[BB * QQ * 64];
__device__ float g_hiI[BB * 64];
__device__ float g_hiS[BB * 64];

// ------------------------- f32x2 packed helpers ----------------------------
__device__ __forceinline__ ull pk2(float lo, float hi) {
  ull r; asm("mov.b64 %0, {%1,%2};" : "=l"(r) : "f"(lo), "f"(hi)); return r;
}
__device__ __forceinline__ void fma2(ull& d, ull a, ull b) {
  asm("fma.rn.f32x2 %0, %1, %2, %0;" : "+l"(d) : "l"(a), "l"(b));
}
__device__ __forceinline__ void upk(ull v, float& lo, float& hi) {
  asm("mov.b64 {%0,%1}, %2;" : "=f"(lo), "=f"(hi) : "l"(v));
}

// ---------------------------------------------------------------------------
// legacy warp GEMM (5 rows), used by tail kernels k2b / k3
// ---------------------------------------------------------------------------
template <int K>
__device__ __forceinline__ void wgemm(const float* __restrict__ sXT,
                                      const float* __restrict__ sW,
                                      int lane, float acc[5][2]) {
#pragma unroll 8
  for (int k = 0; k < K; k++) {
    float2 w = *reinterpret_cast<const float2*>(sW + k * 64 + 2 * lane);
    float4 x4 = *reinterpret_cast<const float4*>(sXT + k * 8);
    float x5 = sXT[k * 8 + 4];
    acc[0][0] = fmaf(x4.x, w.x, acc[0][0]); acc[0][1] = fmaf(x4.x, w.y, acc[0][1]);
    acc[1][0] = fmaf(x4.y, w.x, acc[1][0]); acc[1][1] = fmaf(x4.y, w.y, acc[1][1]);
    acc[2][0] = fmaf(x4.z, w.x, acc[2][0]); acc[2][1] = fmaf(x4.z, w.y, acc[2][1]);
    acc[3][0] = fmaf(x4.w, w.x, acc[3][0]); acc[3][1] = fmaf(x4.w, w.y, acc[3][1]);
    acc[4][0] = fmaf(x5,  w.x, acc[4][0]);  acc[4][1] = fmaf(x5,  w.y, acc[4][1]);
  }
}
__device__ __forceinline__ void wtrans(float* sT, int lane, const float acc[5][2]) {
#pragma unroll
  for (int j = 0; j < 5; j++) {
    sT[(2 * lane) * 8 + j]     = acc[j][0];
    sT[(2 * lane + 1) * 8 + j] = acc[j][1];
  }
}

// ---------------------------------------------------------------------------
// K0_pre: rP = rate@W1_bot + b1 ; Wf = W2@A1_top ; bf = b2@A1_top + b1a ;
//         Wg = W2@agg_W ; bg = b2@agg_W
// ---------------------------------------------------------------------------
__global__ __launch_bounds__(1024) void k0_pre(
    const float* __restrict__ rate_table, const float* __restrict__ gv_W1,
    const float* __restrict__ gv_b1, const float* __restrict__ gv_W2,
    const float* __restrict__ gv_b2, const float* __restrict__ atti_W1,
    const float* __restrict__ atti_b1, const float* __restrict__ agg_W) {
  int t = threadIdx.x;
  if (t < NR * 64) {
    int r = t >> 6, c = t & 63;
    float s = gv_b1[c];
    const float* W1b = gv_W1 + 4096;
#pragma unroll 8
    for (int k = 0; k < 64; k++) s = fmaf(rate_table[r * 64 + k], W1b[k * 64 + c], s);
    g_rP[t] = s;
  }
#pragma unroll
  for (int e = 0; e < 4; e++) {
    int idx = t + e * 1024;
    int k = idx >> 6, c = idx & 63;
    float s = 0.f, sg = 0.f;
#pragma unroll 8
    for (int j = 0; j < 64; j++) {
      s = fmaf(gv_W2[k * 64 + j], atti_W1[j * 64 + c], s);
      sg = fmaf(gv_W2[k * 64 + j], agg_W[j * 64 + c], sg);
    }
    g_Wf[idx] = s;
    g_Wg[idx] = sg;
  }
  if (t < 64) {
    float s = atti_b1[t], sg = 0.f;
#pragma unroll 8
    for (int j = 0; j < 64; j++) {
      s = fmaf(gv_b2[j], atti_W1[j * 64 + t], s);
      sg = fmaf(gv_b2[j], agg_W[j * 64 + t], sg);
    }
    g_bf[t] = s;
    g_bg[t] = sg;
  }
}

// ---------------------------------------------------------------------------
// K0_proj (FFMA2)
// ---------------------------------------------------------------------------
#define SMEM_K0P ((4096 + 4096 + 8 * 64 * XS) * 4)
__global__ __launch_bounds__(256) void k0_proj(
    const float* __restrict__ item_table, const float* __restrict__ user_table,
    const float* __restrict__ gv_W1, const float* __restrict__ atti_W1) {
  extern __shared__ float sm[];
  float* sWa = sm;
  float* sWb = sm + 4096;
  float* sXT = sm + 8192;

  int tid = threadIdx.x, lane = tid & 31, w = tid >> 5;
  for (int i = tid; i < 4096; i += 256) { sWa[i] = gv_W1[i]; sWb[i] = atti_W1[4096 + i]; }
  __syncthreads();
  float* myXT = sXT + w * (64 * XS);

  for (int it = 0; it < 5; it++) {
    int rid0 = blockIdx.x * 400 + it * 80 + w * 10;
    bool half2 = (rid0 >= NI);
    const float* src = half2 ? user_table : item_table;
    const float* sW = half2 ? sWb : sWa;
    float* dst = half2 ? g_uPA1 : g_iP;
    int base = half2 ? (rid0 - NI) : rid0;
#pragma unroll
    for (int j = 0; j < 10; j++) {
      const float* sp = src + (long)(base + j) * 64;
      myXT[lane * XS + j] = sp[lane];
      myXT[(lane + 32) * XS + j] = sp[lane + 32];
    }
    __syncwarp();
    ull a0[5], a1[5];
#pragma unroll
    for (int p = 0; p < 5; p++) { a0[p] = 0ull; a1[p] = 0ull; }
#pragma unroll 8
    for (int k = 0; k < 64; k++) {
      float4 xa = *reinterpret_cast<const float4*>(myXT + k * XS);
      float4 xb = *reinterpret_cast<const float4*>(myXT + k * XS + 4);
      float2 xc = *reinterpret_cast<const float2*>(myXT + k * XS + 8);
      ull xp0 = pk2(xa.x, xa.y), xp1 = pk2(xa.z, xa.w);
      ull xp2 = pk2(xb.x, xb.y), xp3 = pk2(xb.z, xb.w);
      ull xp4 = pk2(xc.x, xc.y);
      float2 wv = *reinterpret_cast<const float2*>(sW + k * 64 + 2 * lane);
      ull w0 = pk2(wv.x, wv.x), w1 = pk2(wv.y, wv.y);
      fma2(a0[0], xp0, w0); fma2(a1[0], xp0, w1);
      fma2(a0[1], xp1, w0); fma2(a1[1], xp1, w1);
      fma2(a0[2], xp2, w0); fma2(a1[2], xp2, w1);
      fma2(a0[3], xp3, w0); fma2(a1[3], xp3, w1);
      fma2(a0[4], xp4, w0); fma2(a1[4], xp4, w1);
    }
#pragma unroll
    for (int p = 0; p < 5; p++) {
      float r0c0, r1c0, r0c1, r1c1;
      upk(a0[p], r0c0, r1c0); upk(a1[p], r0c1, r1c1);
      *reinterpret_cast<float2*>(dst + (long)(base + 2 * p) * 64 + 2 * lane) =
          make_float2(r0c0, r0c1);
      *reinterpret_cast<float2*>(dst + (long)(base + 2 * p + 1) * 64 + 2 * lane) =
          make_float2(r1c0, r1c1);
    }
    __syncwarp();
  }
}

// ---------------------------------------------------------------------------
// K0_combo (FFMA2, single GEMM, T2 only):
//   h1 = relu(iP[i] + rP[r]) (transient)
//   T2 = h1 @ Wf + bf   -> g_T2[rid*64 ...]
// grid 1875 x 256; 4 iters x 8 warps x 10 rows = 320 rows/CTA.
// ---------------------------------------------------------------------------
#define SMEM_K0C ((4096 + 8 * 64 * XS + 384 + 64) * 4)
__global__ __launch_bounds__(256) void k0_combo() {
  extern __shared__ float sm[];
  float* sWf = sm;                  // 4096
  float* sXT = sm + 4096;           // 6144
  float* srP = sm + 4096 + 6144;    // 384
  float* sbf = srP + 384;           // 64

  int tid = threadIdx.x, lane = tid & 31, w = tid >> 5;
  for (int i = tid; i < 4096; i += 256) sWf[i] = g_Wf[i];
  for (int i = tid; i < 384; i += 256) srP[i] = g_rP[i];
  if (tid < 64) sbf[tid] = g_bf[tid];
  __syncthreads();
  float* myXT = sXT + w * (64 * XS);

  float2 bb2 = *reinterpret_cast<const float2*>(sbf + 2 * lane);
  ull b20 = pk2(bb2.x, bb2.x), b21 = pk2(bb2.y, bb2.y);

  for (int it = 0; it < 4; it++) {
    int rid0 = blockIdx.x * 320 + it * 80 + w * 10;
    int r = rid0 / NI;
    int i0 = rid0 - r * NI;
    const float* rp = srP + r * 64;
    float rp0 = rp[lane], rp1 = rp[lane + 32];
#pragma unroll
    for (int j = 0; j < 10; j++) {
      const float* ip = g_iP + (long)(i0 + j) * 64;
      myXT[lane * XS + j] = fmaxf(ip[lane] + rp0, 0.f);
      myXT[(lane + 32) * XS + j] = fmaxf(ip[lane + 32] + rp1, 0.f);
    }
    __syncwarp();
    ull a20[5], a21[5];
#pragma unroll
    for (int p = 0; p < 5; p++) { a20[p] = b20; a21[p] = b21; }
#pragma unroll 8
    for (int k = 0; k < 64; k++) {
      float4 xa = *reinterpret_cast<const float4*>(myXT + k * XS);
      float4 xb = *reinterpret_cast<const float4*>(myXT + k * XS + 4);
      float2 xc = *reinterpret_cast<const float2*>(myXT + k * XS + 8);
      ull xp0 = pk2(xa.x, xa.y), xp1 = pk2(xa.z, xa.w);
      ull xp2 = pk2(xb.x, xb.y), xp3 = pk2(xb.z, xb.w);
      ull xp4 = pk2(xc.x, xc.y);
      float2 w2v = *reinterpret_cast<const float2*>(sWf + k * 64 + 2 * lane);
      ull w20 = pk2(w2v.x, w2v.x), w21 = pk2(w2v.y, w2v.y);
      fma2(a20[0], xp0, w20); fma2(a21[0], xp0, w21);
      fma2(a20[1], xp1, w20); fma2(a21[1], xp1, w21);
      fma2(a20[2], xp2, w20); fma2(a21[2], xp2, w21);
      fma2(a20[3], xp3, w20); fma2(a21[3], xp3, w21);
      fma2(a20[4], xp4, w20); fma2(a21[4], xp4, w21);
    }
#pragma unroll
    for (int p = 0; p < 5; p++) {
      float r0c0, r1c0, r0c1, r1c1;
      long o0 = (long)(rid0 + 2 * p) * 64 + 2 * lane;
      long o1 = (long)(rid0 + 2 * p + 1) * 64 + 2 * lane;
      upk(a20[p], r0c0, r1c0); upk(a21[p], r0c1, r1c1);
      *reinterpret_cast<float2*>(g_T2 + o0) = make_float2(r0c0, r0c1);
      *reinterpret_cast<float2*>(g_T2 + o1) = make_float2(r1c0, r1c1);
    }
    __syncwarp();
  }
}

// ---------------------------------------------------------------------------
// K2s1: merged attention kernel.
//  Phase A: oct-slice over dense T2 rows (256 B each).
//  Phase B: recompute h1 = relu(iP[item] + rP[rate]) — iP is L2-resident,
//  rP in smem; packed (item | rate<<17) index stored from phase A.
//  Epilogue uses Wg = W2@agg_W, bg = b2@agg_W.
//  blocks [0,64): item branch, warp w -> b = bx*8+w (P=100).
//  blocks [64, 64+2560): social branch, warp w -> gid = (bx-64)*8+w (P=40).
// ---------------------------------------------------------------------------
__global__ __launch_bounds__(256) void k2s1_attn(
    const int* __restrict__ uids,
    const int* __restrict__ u_user, const int* __restrict__ u_user_item,
    const int* __restrict__ u_item,
    const float* __restrict__ agg_b,
    const float* __restrict__ atti_W2, const float* __restrict__ atti_b2) {
  __shared__ float sWg[4096];
  __shared__ float srP[384];
  __shared__ float sbAgg[64];
  __shared__ float sbg[64];
  __shared__ float sA2[64];
  __shared__ float sAl[8][100];
  __shared__ int   sPk[8][100];
  __shared__ float sZ[8][64];

  int bx = blockIdx.x, tid = threadIdx.x, lane = tid & 31, w = tid >> 5;
  for (int i = tid; i < 4096; i += 256) sWg[i] = g_Wg[i];
  for (int i = tid; i < 384; i += 256) srP[i] = g_rP[i];
  if (tid < 64) { sbAgg[tid] = agg_b[tid]; sbg[tid] = g_bg[tid]; sA2[tid] = atti_W2[tid]; }
  __syncthreads();
  float cb = atti_b2[0];

  bool item = (bx < 64);
  int unit = item ? (bx * 8 + w) : ((bx - 64) * 8 + w);  // b or gid
  int P = item ? PP : P2;
  int u = item ? uids[unit] : u_user[unit];
  const int2* ips = reinterpret_cast<const int2*>(
      item ? (u_item + (long)unit * (PP * 2)) : (u_user_item + (long)unit * (P2 * 2)));
  float* outp = item ? (g_hiI + (long)unit * 64) : (g_hoI + (long)unit * 64);

  int li = lane & 7, oct = lane >> 3;  // 8 lanes per row, 4 rows per iter
  const float* uP = g_uPA1 + (long)u * 64 + li * 8;
  float4 pcr0 = *reinterpret_cast<const float4*>(uP);
  float4 pcr1 = *reinterpret_cast<const float4*>(uP + 4);
  float4 a2r0 = *reinterpret_cast<const float4*>(sA2 + li * 8);
  float4 a2r1 = *reinterpret_cast<const float4*>(sA2 + li * 8 + 4);

  float den = 0.f;
  int niter = P >> 2;  // 40->10, 100->25 (exact)
#pragma unroll 2
  for (int it = 0; it < niter; it++) {
    int r = it * 4 + oct;
    int2 idx = ips[r];
    float m = (idx.x > 0) ? 1.f : 0.f;
    int rid = idx.y * NI + idx.x;
    const float4* t2p = reinterpret_cast<const float4*>(
        g_T2 + (long)rid * 64 + li * 8);
    float4 t2a = t2p[0], t2b = t2p[1];
    float s;
    s = fmaxf(fmaf(m, pcr0.x, t2a.x), 0.f) * a2r0.x;
    s = fmaf(fmaxf(fmaf(m, pcr0.y, t2a.y), 0.f), a2r0.y, s);
    s = fmaf(fmaxf(fmaf(m, pcr0.z, t2a.z), 0.f), a2r0.z, s);
    s = fmaf(fmaxf(fmaf(m, pcr0.w, t2a.w), 0.f), a2r0.w, s);
    s = fmaf(fmaxf(fmaf(m, pcr1.x, t2b.x), 0.f), a2r1.x, s);
    s = fmaf(fmaxf(fmaf(m, pcr1.y, t2b.y), 0.f), a2r1.y, s);
    s = fmaf(fmaxf(fmaf(m, pcr1.z, t2b.z), 0.f), a2r1.z, s);
    s = fmaf(fmaxf(fmaf(m, pcr1.w, t2b.w), 0.f), a2r1.w, s);
    s += __shfl_xor_sync(0xffffffffu, s, 1);
    s += __shfl_xor_sync(0xffffffffu, s, 2);
    s += __shfl_xor_sync(0xffffffffu, s, 4);
    if (li == 0) {
      float al = __expf(s + cb) * m;
      sAl[w][r] = al;
      sPk[w][r] = idx.x | (idx.y << 17);
      den += al;
    }
  }
#pragma unroll
  for (int o = 16; o; o >>= 1) den += __shfl_xor_sync(0xffffffffu, den, o);
  float dinv = 1.f / (den + EPSF);
  float sig = den * dinv;
  __syncwarp();

  // Phase B: weighted h1 sum; h1 recomputed from L2-resident iP + smem rP
  int c0 = 2 * lane;
  float rpx[NR], rpy[NR];
#pragma unroll
  for (int rr = 0; rr < NR; rr++) {
    float2 rv = *reinterpret_cast<const float2*>(srP + rr * 64 + c0);
    rpx[rr] = rv.x; rpy[rr] = rv.y;
  }
  float ax = 0.f, ay = 0.f;
#pragma unroll 4
  for (int r = 0; r < P; r++) {
    float al = sAl[w][r];
    int pk = sPk[w][r];
    int it2 = pk & 131071, rt = pk >> 17;
    float2 ip2 = *reinterpret_cast<const float2*>(g_iP + (long)it2 * 64 + c0);
    float h1x = fmaxf(ip2.x + rpx[rt], 0.f);
    float h1y = fmaxf(ip2.y + rpy[rt], 0.f);
    ax = fmaf(al, h1x, ax); ay = fmaf(al, h1y, ay);
  }
  sZ[w][c0] = ax * dinv;
  sZ[w][c0 + 1] = ay * dinv;
  __syncwarp();

  // epilogue GEMV: out = relu(z@Wg + sig*bg + agg_b)
  float ox = fmaf(sig, sbg[c0], sbAgg[c0]);
  float oy = fmaf(sig, sbg[c0 + 1], sbAgg[c0 + 1]);
#pragma unroll 8
  for (int k = 0; k < 64; k++) {
    float zk = sZ[w][k];
    float2 wk = *reinterpret_cast<const float2*>(sWg + k * 64 + c0);
    ox = fmaf(zk, wk.x, ox); oy = fmaf(zk, wk.y, oy);
  }
  *reinterpret_cast<float2*>(outp + c0) =
      make_float2(fmaxf(ox, 0.f), fmaxf(oy, 0.f));
}

// ---------------------------------------------------------------------------
// K2b: beta attention over q + h_iS (unchanged).
// ---------------------------------------------------------------------------
#define SMEM_K2B (20784 * 4)
__global__ __launch_bounds__(256) void k2b_user(
    const int* __restrict__ u_user, const float* __restrict__ user_table,
    const float* __restrict__ attu_W1, const float* __restrict__ attu_b1,
    const float* __restrict__ attu_W2, const float* __restrict__ attu_b2,
    const float* __restrict__ aggn_W, const float* __restrict__ aggn_b) {
  extern __shared__ float sm[];
  float* sU1 = sm;             float* sAggn = sm + 8192;
  float* sw2u = sm + 12288;    float* sb1u = sm + 12352;
  float* sbAggn = sm + 12416;  float* sZ = sm + 12480;
  float* sBeta = sm + 12544;   float* sRed = sm + 12584;
  float* sXT = sm + 12592;

  int b = blockIdx.x, tid = threadIdx.x, lane = tid & 31, w = tid >> 5;
  for (int i = tid; i < 8192; i += 256) sU1[i] = attu_W1[i];
  for (int i = tid; i < 4096; i += 256) sAggn[i] = aggn_W[i];
  if (tid < 64) { sw2u[tid] = attu_W2[tid]; sb1u[tid] = attu_b1[tid]; sbAggn[tid] = aggn_b[tid]; }
  __syncthreads();
  float cb2u = attu_b2[0];
  float* myXT = sXT + w * 1024;
  int rowbase = w * 5;
  float msk[5];
#pragma unroll
  for (int j = 0; j < 5; j++) {
    int row = rowbase + j;
    int uq = u_user[b * 40 + row];
    msk[j] = (uq > 0) ? 1.f : 0.f;
    const float* hp = g_hoI + (long)(b * 40 + row) * 64;
    const float* up = user_table + (long)uq * 64;
    myXT[lane * 8 + j] = hp[lane]; myXT[(lane + 32) * 8 + j] = hp[lane + 32];
    myXT[(lane + 64) * 8 + j] = up[lane]; myXT[(lane + 96) * 8 + j] = up[lane + 32];
  }
  __syncwarp();
  float acc[5][2];
#pragma unroll
  for (int j = 0; j < 5; j++) { acc[j][0] = sb1u[2 * lane]; acc[j][1] = sb1u[2 * lane + 1]; }
  wgemm<128>(myXT, sU1, lane, acc);
  float w0 = sw2u[2 * lane], w1 = sw2u[2 * lane + 1];
#pragma unroll
  for (int j = 0; j < 5; j++) {
    float p = fmaf(fmaxf(acc[j][0], 0.f), w0, fmaxf(acc[j][1], 0.f) * w1);
#pragma unroll
    for (int o = 16; o; o >>= 1) p += __shfl_xor_sync(0xffffffffu, p, o);
    if (lane == 0) sBeta[rowbase + j] = expf(p + cb2u) * msk[j];
  }
  __syncthreads();
  if (tid < 32) {
    float s = 0.f;
    for (int r = lane; r < 40; r += 32) s += sBeta[r];
#pragma unroll
    for (int o = 16; o; o >>= 1) s += __shfl_xor_sync(0xffffffffu, s, o);
    if (lane == 0) sRed[0] = s;
  }
  __syncthreads();
  float dinv = 1.f / (sRed[0] + EPSF);
  if (tid < 64) {
    float s = 0.f;
    for (int r = 0; r < 40; r++) s = fmaf(sBeta[r], g_hoI[(long)(b * 40 + r) * 64 + tid], s);
    sZ[tid] = s * dinv;
  }
  __syncthreads();
  if (tid < 64) {
    float s = sbAggn[tid];
    for (int k = 0; k < 64; k++) s = fmaf(sZ[k], sAggn[k * 64 + tid], s);
    g_hiS[b * 64 + tid] = fmaxf(s, 0.f);
  }
}

// ---------------------------------------------------------------------------
// K3: final 3-layer combine MLP (unchanged).
// ---------------------------------------------------------------------------
#define SMEM_K3 (24768 * 4)
__global__ __launch_bounds__(256) void k3_final(
    const float* __restrict__ cm_W1, const float* __restrict__ cm_b1,
    const float* __restrict__ cm_W2, const float* __restrict__ cm_b2,
    const float* __restrict__ cm_W3, const float* __restrict__ cm_b3,
    float* __restrict__ out) {
  extern __shared__ float sm[];
  float* sC1 = sm;          float* sC2 = sm + 8192;   float* sC3 = sm + 12288;
  float* sb1 = sm + 16384;  float* sb2 = sm + 16448;  float* sb3 = sm + 16512;
  float* sXT = sm + 16576;

  int tid = threadIdx.x, lane = tid & 31, w = tid >> 5;
  for (int i = tid; i < 8192; i += 256) sC1[i] = cm_W1[i];
  for (int i = tid; i < 4096; i += 256) { sC2[i] = cm_W2[i]; sC3[i] = cm_W3[i]; }
  if (tid < 64) { sb1[tid] = cm_b1[tid]; sb2[tid] = cm_b2[tid]; sb3[tid] = cm_b3[tid]; }
  __syncthreads();
  float* myXT = sXT + w * 1024;
  int rowbase = blockIdx.x * 40 + w * 5;
#pragma unroll
  for (int j = 0; j < 5; j++) {
    int row = rowbase + j;
    float x0 = 0, x1 = 0, x2 = 0, x3 = 0;
    if (row < BB) {
      x0 = g_hiI[row * 64 + lane]; x1 = g_hiI[row * 64 + 32 + lane];
      x2 = g_hiS[row * 64 + lane]; x3 = g_hiS[row * 64 + 32 + lane];
    }
    myXT[lane * 8 + j] = x0; myXT[(lane + 32) * 8 + j] = x1;
    myXT[(lane + 64) * 8 + j] = x2; myXT[(lane + 96) * 8 + j] = x3;
  }
  __syncwarp();
  float acc[5][2];
#pragma unroll
  for (int j = 0; j < 5; j++) { acc[j][0] = sb1[2 * lane]; acc[j][1] = sb1[2 * lane + 1]; }
  wgemm<128>(myXT, sC1, lane, acc);
#pragma unroll
  for (int j = 0; j < 5; j++) { acc[j][0] = fmaxf(acc[j][0], 0.f); acc[j][1] = fmaxf(acc[j][1], 0.f); }
  __syncwarp(); wtrans(myXT, lane, acc); __syncwarp();
#pragma unroll
  for (int j = 0; j < 5; j++) { acc[j][0] = sb2[2 * lane]; acc[j][1] = sb2[2 * lane + 1]; }
  wgemm<64>(myXT, sC2, lane, acc);
#pragma unroll
  for (int j = 0; j < 5; j++) { acc[j][0] = fmaxf(acc[j][0], 0.f); acc[j][1] = fmaxf(acc[j][1], 0.f); }
  __syncwarp(); wtrans(myXT, lane, acc); __syncwarp();
#pragma unroll
  for (int j = 0; j < 5; j++) { acc[j][0] = sb3[2 * lane]; acc[j][1] = sb3[2 * lane + 1]; }
  wgemm<64>(myXT, sC3, lane, acc);
#pragma unroll
  for (int j = 0; j < 5; j++) {
    int row = rowbase + j;
    if (row < BB) {
      out[row * 64 + 2 * lane]     = fmaxf(acc[j][0], 0.f);
      out[row * 64 + 2 * lane + 1] = fmaxf(acc[j][1], 0.f);
    }
  }
}

// ---------------------------------------------------------------------------
extern "C" void kernel_launch(void* const* d_in, const int* in_sizes, int n_in,
                              void* d_out, int out_size) {
  const int* uids        = (const int*)d_in[0];
  const int* u_item      = (const int*)d_in[1];
  const int* u_user      = (const int*)d_in[2];
  const int* u_user_item = (const int*)d_in[3];
  const float* user_table = (const float*)d_in[4];
  const float* item_table = (const float*)d_in[5];
  const float* rate_table = (const float*)d_in[6];
  const float* gv_W1 = (const float*)d_in[7];   const float* gv_b1 = (const float*)d_in[8];
  const float* gv_W2 = (const float*)d_in[9];   const float* gv_b2 = (const float*)d_in[10];
  const float* atti_W1 = (const float*)d_in[11]; const float* atti_b1 = (const float*)d_in[12];
  const float* atti_W2 = (const float*)d_in[13]; const float* atti_b2 = (const float*)d_in[14];
  const float* agg_W = (const float*)d_in[15];   const float* agg_b = (const float*)d_in[16];
  const float* attu_W1 = (const float*)d_in[17]; const float* attu_b1 = (const float*)d_in[18];
  const float* attu_W2 = (const float*)d_in[19]; const float* attu_b2 = (const float*)d_in[20];
  const float* aggn_W = (const float*)d_in[21];  const float* aggn_b = (const float*)d_in[22];
  const float* cm_W1 = (const float*)d_in[23];   const float* cm_b1 = (const float*)d_in[24];
  const float* cm_W2 = (const float*)d_in[25];   const float* cm_b2 = (const float*)d_in[26];
  const float* cm_W3 = (const float*)d_in[27];   const float* cm_b3 = (const float*)d_in[28];
  float* out = (float*)d_out;

  cudaFuncSetAttribute(k0_proj,  cudaFuncAttributeMaxDynamicSharedMemorySize, SMEM_K0P);
  cudaFuncSetAttribute(k0_combo, cudaFuncAttributeMaxDynamicSharedMemorySize, SMEM_K0C);
  cudaFuncSetAttribute(k2b_user, cudaFuncAttributeMaxDynamicSharedMemorySize, SMEM_K2B);
  cudaFuncSetAttribute(k3_final, cudaFuncAttributeMaxDynamicSharedMemorySize, SMEM_K3);

  k0_pre<<<1, 1024>>>(rate_table, gv_W1, gv_b1, gv_W2, gv_b2, atti_W1, atti_b1, agg_W);
  k0_proj<<<500, 256, SMEM_K0P>>>(item_table, user_table, gv_W1, atti_W1);
  k0_combo<<<1875, 256, SMEM_K0C>>>();
  k2s1_attn<<<64 + 2560, 256>>>(uids, u_user, u_user_item, u_item,
                                agg_b, atti_W2, atti_b2);
  k2b_user<<<512, 256, SMEM_K2B>>>(u_user, user_table, attu_W1, attu_b1, attu_W2,
                                   attu_b2, aggn_W, aggn_b);
  k3_final<<<13, 256, SMEM_K3>>>(cm_W1, cm_b1, cm_W2, cm_b2, cm_W3, cm_b3, out);
}

// round 9
// speedup vs baseline: 1.5921x; 1.0337x over previous
#include <cuda_runtime.h>

#define EPSF 1e-10f
#define NI 100000
#define NU 100000
#define NR 6
#define BB 512
#define PP 100
#define QQ 40
#define P2 40
#define XS 12  // XT row stride (floats)

typedef unsigned long long ull;

// ---------------- persistent scratch (static device memory) -----------------
__device__ float g_iP[NI * 64];            // item_table @ W1_top
__device__ float g_uPA1[NU * 64];          // user_table @ A1_bot
__device__ float g_rP[NR * 64];            // rate_table @ W1_bot + gv_b1
__device__ float g_Wf[64 * 64];            // W2 @ A1_top
__device__ float g_bf[64];                 // b2 @ A1_top + b1a
__device__ float g_Wg[64 * 64];            // W2 @ agg_W
__device__ float g_bg[64];                 // b2 @ agg_W
__device__ float g_T2[(long)NR * NI * 64]; // T2 = h1@Wf + bf per (rate,item)
__device__ float g_hoI[BB * QQ * 64];
__device__ float g_hiI[BB * 64];
__device__ float g_hiS[BB * 64];

// ------------------------- f32x2 packed helpers ----------------------------
__device__ __forceinline__ ull pk2(float lo, float hi) {
  ull r; asm("mov.b64 %0, {%1,%2};" : "=l"(r) : "f"(lo), "f"(hi)); return r;
}
__device__ __forceinline__ void fma2(ull& d, ull a, ull b) {
  asm("fma.rn.f32x2 %0, %1, %2, %0;" : "+l"(d) : "l"(a), "l"(b));
}
__device__ __forceinline__ void upk(ull v, float& lo, float& hi) {
  asm("mov.b64 {%0,%1}, %2;" : "=f"(lo), "=f"(hi) : "l"(v));
}

// ---------------------------------------------------------------------------
// legacy warp GEMM (5 rows), used by tail kernels k2b / k3
// ---------------------------------------------------------------------------
template <int K>
__device__ __forceinline__ void wgemm(const float* __restrict__ sXT,
                                      const float* __restrict__ sW,
                                      int lane, float acc[5][2]) {
#pragma unroll 8
  for (int k = 0; k < K; k++) {
    float2 w = *reinterpret_cast<const float2*>(sW + k * 64 + 2 * lane);
    float4 x4 = *reinterpret_cast<const float4*>(sXT + k * 8);
    float x5 = sXT[k * 8 + 4];
    acc[0][0] = fmaf(x4.x, w.x, acc[0][0]); acc[0][1] = fmaf(x4.x, w.y, acc[0][1]);
    acc[1][0] = fmaf(x4.y, w.x, acc[1][0]); acc[1][1] = fmaf(x4.y, w.y, acc[1][1]);
    acc[2][0] = fmaf(x4.z, w.x, acc[2][0]); acc[2][1] = fmaf(x4.z, w.y, acc[2][1]);
    acc[3][0] = fmaf(x4.w, w.x, acc[3][0]); acc[3][1] = fmaf(x4.w, w.y, acc[3][1]);
    acc[4][0] = fmaf(x5,  w.x, acc[4][0]);  acc[4][1] = fmaf(x5,  w.y, acc[4][1]);
  }
}
__device__ __forceinline__ void wtrans(float* sT, int lane, const float acc[5][2]) {
#pragma unroll
  for (int j = 0; j < 5; j++) {
    sT[(2 * lane) * 8 + j]     = acc[j][0];
    sT[(2 * lane + 1) * 8 + j] = acc[j][1];
  }
}

// ---------------------------------------------------------------------------
// K0_pre: rP = rate@W1_bot + b1 ; Wf = W2@A1_top ; bf = b2@A1_top + b1a ;
//         Wg = W2@agg_W ; bg = b2@agg_W
// ---------------------------------------------------------------------------
__global__ __launch_bounds__(1024) void k0_pre(
    const float* __restrict__ rate_table, const float* __restrict__ gv_W1,
    const float* __restrict__ gv_b1, const float* __restrict__ gv_W2,
    const float* __restrict__ gv_b2, const float* __restrict__ atti_W1,
    const float* __restrict__ atti_b1, const float* __restrict__ agg_W) {
  int t = threadIdx.x;
  if (t < NR * 64) {
    int r = t >> 6, c = t & 63;
    float s = gv_b1[c];
    const float* W1b = gv_W1 + 4096;
#pragma unroll 8
    for (int k = 0; k < 64; k++) s = fmaf(rate_table[r * 64 + k], W1b[k * 64 + c], s);
    g_rP[t] = s;
  }
#pragma unroll
  for (int e = 0; e < 4; e++) {
    int idx = t + e * 1024;
    int k = idx >> 6, c = idx & 63;
    float s = 0.f, sg = 0.f;
#pragma unroll 8
    for (int j = 0; j < 64; j++) {
      s = fmaf(gv_W2[k * 64 + j], atti_W1[j * 64 + c], s);
      sg = fmaf(gv_W2[k * 64 + j], agg_W[j * 64 + c], sg);
    }
    g_Wf[idx] = s;
    g_Wg[idx] = sg;
  }
  if (t < 64) {
    float s = atti_b1[t], sg = 0.f;
#pragma unroll 8
    for (int j = 0; j < 64; j++) {
      s = fmaf(gv_b2[j], atti_W1[j * 64 + t], s);
      sg = fmaf(gv_b2[j], agg_W[j * 64 + t], sg);
    }
    g_bf[t] = s;
    g_bg[t] = sg;
  }
}

// ---------------------------------------------------------------------------
// K0_proj (FFMA2)
// ---------------------------------------------------------------------------
#define SMEM_K0P ((4096 + 4096 + 8 * 64 * XS) * 4)
__global__ __launch_bounds__(256) void k0_proj(
    const float* __restrict__ item_table, const float* __restrict__ user_table,
    const float* __restrict__ gv_W1, const float* __restrict__ atti_W1) {
  extern __shared__ float sm[];
  float* sWa = sm;
  float* sWb = sm + 4096;
  float* sXT = sm + 8192;

  int tid = threadIdx.x, lane = tid & 31, w = tid >> 5;
  for (int i = tid; i < 4096; i += 256) { sWa[i] = gv_W1[i]; sWb[i] = atti_W1[4096 + i]; }
  __syncthreads();
  float* myXT = sXT + w * (64 * XS);

  for (int it = 0; it < 5; it++) {
    int rid0 = blockIdx.x * 400 + it * 80 + w * 10;
    bool half2 = (rid0 >= NI);
    const float* src = half2 ? user_table : item_table;
    const float* sW = half2 ? sWb : sWa;
    float* dst = half2 ? g_uPA1 : g_iP;
    int base = half2 ? (rid0 - NI) : rid0;
#pragma unroll
    for (int j = 0; j < 10; j++) {
      const float* sp = src + (long)(base + j) * 64;
      myXT[lane * XS + j] = sp[lane];
      myXT[(lane + 32) * XS + j] = sp[lane + 32];
    }
    __syncwarp();
    ull a0[5], a1[5];
#pragma unroll
    for (int p = 0; p < 5; p++) { a0[p] = 0ull; a1[p] = 0ull; }
#pragma unroll 8
    for (int k = 0; k < 64; k++) {
      float4 xa = *reinterpret_cast<const float4*>(myXT + k * XS);
      float4 xb = *reinterpret_cast<const float4*>(myXT + k * XS + 4);
      float2 xc = *reinterpret_cast<const float2*>(myXT + k * XS + 8);
      ull xp0 = pk2(xa.x, xa.y), xp1 = pk2(xa.z, xa.w);
      ull xp2 = pk2(xb.x, xb.y), xp3 = pk2(xb.z, xb.w);
      ull xp4 = pk2(xc.x, xc.y);
      float2 wv = *reinterpret_cast<const float2*>(sW + k * 64 + 2 * lane);
      ull w0 = pk2(wv.x, wv.x), w1 = pk2(wv.y, wv.y);
      fma2(a0[0], xp0, w0); fma2(a1[0], xp0, w1);
      fma2(a0[1], xp1, w0); fma2(a1[1], xp1, w1);
      fma2(a0[2], xp2, w0); fma2(a1[2], xp2, w1);
      fma2(a0[3], xp3, w0); fma2(a1[3], xp3, w1);
      fma2(a0[4], xp4, w0); fma2(a1[4], xp4, w1);
    }
#pragma unroll
    for (int p = 0; p < 5; p++) {
      float r0c0, r1c0, r0c1, r1c1;
      upk(a0[p], r0c0, r1c0); upk(a1[p], r0c1, r1c1);
      *reinterpret_cast<float2*>(dst + (long)(base + 2 * p) * 64 + 2 * lane) =
          make_float2(r0c0, r0c1);
      *reinterpret_cast<float2*>(dst + (long)(base + 2 * p + 1) * 64 + 2 * lane) =
          make_float2(r1c0, r1c1);
    }
    __syncwarp();
  }
}

// ---------------------------------------------------------------------------
// K0_combo (FFMA2, single GEMM, T2 only)
// ---------------------------------------------------------------------------
#define SMEM_K0C ((4096 + 8 * 64 * XS + 384 + 64) * 4)
__global__ __launch_bounds__(256) void k0_combo() {
  extern __shared__ float sm[];
  float* sWf = sm;                  // 4096
  float* sXT = sm + 4096;           // 6144
  float* srP = sm + 4096 + 6144;    // 384
  float* sbf = srP + 384;           // 64

  int tid = threadIdx.x, lane = tid & 31, w = tid >> 5;
  for (int i = tid; i < 4096; i += 256) sWf[i] = g_Wf[i];
  for (int i = tid; i < 384; i += 256) srP[i] = g_rP[i];
  if (tid < 64) sbf[tid] = g_bf[tid];
  __syncthreads();
  float* myXT = sXT + w * (64 * XS);

  float2 bb2 = *reinterpret_cast<const float2*>(sbf + 2 * lane);
  ull b20 = pk2(bb2.x, bb2.x), b21 = pk2(bb2.y, bb2.y);

  for (int it = 0; it < 4; it++) {
    int rid0 = blockIdx.x * 320 + it * 80 + w * 10;
    int r = rid0 / NI;
    int i0 = rid0 - r * NI;
    const float* rp = srP + r * 64;
    float rp0 = rp[lane], rp1 = rp[lane + 32];
#pragma unroll
    for (int j = 0; j < 10; j++) {
      const float* ip = g_iP + (long)(i0 + j) * 64;
      myXT[lane * XS + j] = fmaxf(ip[lane] + rp0, 0.f);
      myXT[(lane + 32) * XS + j] = fmaxf(ip[lane + 32] + rp1, 0.f);
    }
    __syncwarp();
    ull a20[5], a21[5];
#pragma unroll
    for (int p = 0; p < 5; p++) { a20[p] = b20; a21[p] = b21; }
#pragma unroll 8
    for (int k = 0; k < 64; k++) {
      float4 xa = *reinterpret_cast<const float4*>(myXT + k * XS);
      float4 xb = *reinterpret_cast<const float4*>(myXT + k * XS + 4);
      float2 xc = *reinterpret_cast<const float2*>(myXT + k * XS + 8);
      ull xp0 = pk2(xa.x, xa.y), xp1 = pk2(xa.z, xa.w);
      ull xp2 = pk2(xb.x, xb.y), xp3 = pk2(xb.z, xb.w);
      ull xp4 = pk2(xc.x, xc.y);
      float2 w2v = *reinterpret_cast<const float2*>(sWf + k * 64 + 2 * lane);
      ull w20 = pk2(w2v.x, w2v.x), w21 = pk2(w2v.y, w2v.y);
      fma2(a20[0], xp0, w20); fma2(a21[0], xp0, w21);
      fma2(a20[1], xp1, w20); fma2(a21[1], xp1, w21);
      fma2(a20[2], xp2, w20); fma2(a21[2], xp2, w21);
      fma2(a20[3], xp3, w20); fma2(a21[3], xp3, w21);
      fma2(a20[4], xp4, w20); fma2(a21[4], xp4, w21);
    }
#pragma unroll
    for (int p = 0; p < 5; p++) {
      float r0c0, r1c0, r0c1, r1c1;
      long o0 = (long)(rid0 + 2 * p) * 64 + 2 * lane;
      long o1 = (long)(rid0 + 2 * p + 1) * 64 + 2 * lane;
      upk(a20[p], r0c0, r1c0); upk(a21[p], r0c1, r1c1);
      *reinterpret_cast<float2*>(g_T2 + o0) = make_float2(r0c0, r0c1);
      *reinterpret_cast<float2*>(g_T2 + o1) = make_float2(r1c0, r1c1);
    }
    __syncwarp();
  }
}

// ---------------------------------------------------------------------------
// K2s1: merged attention kernel, FULLY FUSED oct-slice:
//  After the oct butterfly every lane holds the row score, computes alpha
//  locally, and immediately accumulates alpha-weighted h1 for its own 8
//  columns (h1 = relu(iP[item]+rP[rate]); iP L2-resident, rP in smem).
//  Partials combined across octs via one smem transpose at the end.
//  den accumulated on all 8 lanes (8x overcount, exact *0.125 fix).
//  blocks [0,64): item branch, warp w -> b = bx*8+w (P=100).
//  blocks [64, 64+2560): social branch, warp w -> gid = (bx-64)*8+w (P=40).
// ---------------------------------------------------------------------------
__global__ __launch_bounds__(256) void k2s1_attn(
    const int* __restrict__ uids,
    const int* __restrict__ u_user, const int* __restrict__ u_user_item,
    const int* __restrict__ u_item,
    const float* __restrict__ agg_b,
    const float* __restrict__ atti_W2, const float* __restrict__ atti_b2) {
  __shared__ float sWg[4096];
  __shared__ float srP[384];
  __shared__ float sbAgg[64];
  __shared__ float sbg[64];
  __shared__ float sA2[64];
  __shared__ float sPart[8][4][64];   // [warp][oct][col]
  __shared__ float sZ[8][64];

  int bx = blockIdx.x, tid = threadIdx.x, lane = tid & 31, w = tid >> 5;
  for (int i = tid; i < 4096; i += 256) sWg[i] = g_Wg[i];
  for (int i = tid; i < 384; i += 256) srP[i] = g_rP[i];
  if (tid < 64) { sbAgg[tid] = agg_b[tid]; sbg[tid] = g_bg[tid]; sA2[tid] = atti_W2[tid]; }
  __syncthreads();
  float cb = atti_b2[0];

  bool item = (bx < 64);
  int unit = item ? (bx * 8 + w) : ((bx - 64) * 8 + w);  // b or gid
  int P = item ? PP : P2;
  int u = item ? uids[unit] : u_user[unit];
  const int2* ips = reinterpret_cast<const int2*>(
      item ? (u_item + (long)unit * (PP * 2)) : (u_user_item + (long)unit * (P2 * 2)));
  float* outp = item ? (g_hiI + (long)unit * 64) : (g_hoI + (long)unit * 64);

  int li = lane & 7, oct = lane >> 3;  // 8 lanes per row, 4 rows per iter
  const float* uP = g_uPA1 + (long)u * 64 + li * 8;
  float4 pcr0 = *reinterpret_cast<const float4*>(uP);
  float4 pcr1 = *reinterpret_cast<const float4*>(uP + 4);
  float4 a2r0 = *reinterpret_cast<const float4*>(sA2 + li * 8);
  float4 a2r1 = *reinterpret_cast<const float4*>(sA2 + li * 8 + 4);

  float4 acca = make_float4(0.f, 0.f, 0.f, 0.f);
  float4 accb = make_float4(0.f, 0.f, 0.f, 0.f);
  float den = 0.f;
  int niter = P >> 2;  // 40->10, 100->25 (exact)
  for (int it = 0; it < niter; it++) {
    int r = it * 4 + oct;
    int2 idx = ips[r];
    float m = (idx.x > 0) ? 1.f : 0.f;
    long rid = (long)(idx.y * NI + idx.x);
    const float4* t2p = reinterpret_cast<const float4*>(g_T2 + rid * 64 + li * 8);
    float4 t2a = t2p[0], t2b = t2p[1];
    // prefetch h1 inputs while the score chain runs
    const float4* ipp = reinterpret_cast<const float4*>(g_iP + (long)idx.x * 64 + li * 8);
    float4 ipa = ipp[0], ipb = ipp[1];
    const float4* rpp = reinterpret_cast<const float4*>(srP + idx.y * 64 + li * 8);
    float4 rpa = rpp[0], rpb = rpp[1];
    float s;
    s = fmaxf(fmaf(m, pcr0.x, t2a.x), 0.f) * a2r0.x;
    s = fmaf(fmaxf(fmaf(m, pcr0.y, t2a.y), 0.f), a2r0.y, s);
    s = fmaf(fmaxf(fmaf(m, pcr0.z, t2a.z), 0.f), a2r0.z, s);
    s = fmaf(fmaxf(fmaf(m, pcr0.w, t2a.w), 0.f), a2r0.w, s);
    s = fmaf(fmaxf(fmaf(m, pcr1.x, t2b.x), 0.f), a2r1.x, s);
    s = fmaf(fmaxf(fmaf(m, pcr1.y, t2b.y), 0.f), a2r1.y, s);
    s = fmaf(fmaxf(fmaf(m, pcr1.z, t2b.z), 0.f), a2r1.z, s);
    s = fmaf(fmaxf(fmaf(m, pcr1.w, t2b.w), 0.f), a2r1.w, s);
    s += __shfl_xor_sync(0xffffffffu, s, 1);
    s += __shfl_xor_sync(0xffffffffu, s, 2);
    s += __shfl_xor_sync(0xffffffffu, s, 4);
    float al = __expf(s + cb) * m;
    den += al;
    acca.x = fmaf(al, fmaxf(ipa.x + rpa.x, 0.f), acca.x);
    acca.y = fmaf(al, fmaxf(ipa.y + rpa.y, 0.f), acca.y);
    acca.z = fmaf(al, fmaxf(ipa.z + rpa.z, 0.f), acca.z);
    acca.w = fmaf(al, fmaxf(ipa.w + rpa.w, 0.f), acca.w);
    accb.x = fmaf(al, fmaxf(ipb.x + rpb.x, 0.f), accb.x);
    accb.y = fmaf(al, fmaxf(ipb.y + rpb.y, 0.f), accb.y);
    accb.z = fmaf(al, fmaxf(ipb.z + rpb.z, 0.f), accb.z);
    accb.w = fmaf(al, fmaxf(ipb.w + rpb.w, 0.f), accb.w);
  }
#pragma unroll
  for (int o = 16; o; o >>= 1) den += __shfl_xor_sync(0xffffffffu, den, o);
  den *= 0.125f;  // each row's alpha counted 8x (once per oct lane)
  float dinv = 1.f / (den + EPSF);
  float sig = den * dinv;

  // combine oct partials: sPart[w][oct][col]
  *reinterpret_cast<float4*>(&sPart[w][oct][li * 8]) = acca;
  *reinterpret_cast<float4*>(&sPart[w][oct][li * 8 + 4]) = accb;
  __syncwarp();
  int c0 = 2 * lane;
  float zx = sPart[w][0][c0] + sPart[w][1][c0] + sPart[w][2][c0] + sPart[w][3][c0];
  float zy = sPart[w][0][c0 + 1] + sPart[w][1][c0 + 1] + sPart[w][2][c0 + 1] + sPart[w][3][c0 + 1];
  sZ[w][c0] = zx * dinv;
  sZ[w][c0 + 1] = zy * dinv;
  __syncwarp();

  // epilogue GEMV: out = relu(z@Wg + sig*bg + agg_b)
  float ox = fmaf(sig, sbg[c0], sbAgg[c0]);
  float oy = fmaf(sig, sbg[c0 + 1], sbAgg[c0 + 1]);
#pragma unroll 8
  for (int k = 0; k < 64; k++) {
    float zk = sZ[w][k];
    float2 wk = *reinterpret_cast<const float2*>(sWg + k * 64 + c0);
    ox = fmaf(zk, wk.x, ox); oy = fmaf(zk, wk.y, oy);
  }
  *reinterpret_cast<float2*>(outp + c0) =
      make_float2(fmaxf(ox, 0.f), fmaxf(oy, 0.f));
}

// ---------------------------------------------------------------------------
// K2b: beta attention over q + h_iS (unchanged).
// ---------------------------------------------------------------------------
#define SMEM_K2B (20784 * 4)
__global__ __launch_bounds__(256) void k2b_user(
    const int* __restrict__ u_user, const float* __restrict__ user_table,
    const float* __restrict__ attu_W1, const float* __restrict__ attu_b1,
    const float* __restrict__ attu_W2, const float* __restrict__ attu_b2,
    const float* __restrict__ aggn_W, const float* __restrict__ aggn_b) {
  extern __shared__ float sm[];
  float* sU1 = sm;             float* sAggn = sm + 8192;
  float* sw2u = sm + 12288;    float* sb1u = sm + 12352;
  float* sbAggn = sm + 12416;  float* sZ = sm + 12480;
  float* sBeta = sm + 12544;   float* sRed = sm + 12584;
  float* sXT = sm + 12592;

  int b = blockIdx.x, tid = threadIdx.x, lane = tid & 31, w = tid >> 5;
  for (int i = tid; i < 8192; i += 256) sU1[i] = attu_W1[i];
  for (int i = tid; i < 4096; i += 256) sAggn[i] = aggn_W[i];
  if (tid < 64) { sw2u[tid] = attu_W2[tid]; sb1u[tid] = attu_b1[tid]; sbAggn[tid] = aggn_b[tid]; }
  __syncthreads();
  float cb2u = attu_b2[0];
  float* myXT = sXT + w * 1024;
  int rowbase = w * 5;
  float msk[5];
#pragma unroll
  for (int j = 0; j < 5; j++) {
    int row = rowbase + j;
    int uq = u_user[b * 40 + row];
    msk[j] = (uq > 0) ? 1.f : 0.f;
    const float* hp = g_hoI + (long)(b * 40 + row) * 64;
    const float* up = user_table + (long)uq * 64;
    myXT[lane * 8 + j] = hp[lane]; myXT[(lane + 32) * 8 + j] = hp[lane + 32];
    myXT[(lane + 64) * 8 + j] = up[lane]; myXT[(lane + 96) * 8 + j] = up[lane + 32];
  }
  __syncwarp();
  float acc[5][2];
#pragma unroll
  for (int j = 0; j < 5; j++) { acc[j][0] = sb1u[2 * lane]; acc[j][1] = sb1u[2 * lane + 1]; }
  wgemm<128>(myXT, sU1, lane, acc);
  float w0 = sw2u[2 * lane], w1 = sw2u[2 * lane + 1];
#pragma unroll
  for (int j = 0; j < 5; j++) {
    float p = fmaf(fmaxf(acc[j][0], 0.f), w0, fmaxf(acc[j][1], 0.f) * w1);
#pragma unroll
    for (int o = 16; o; o >>= 1) p += __shfl_xor_sync(0xffffffffu, p, o);
    if (lane == 0) sBeta[rowbase + j] = expf(p + cb2u) * msk[j];
  }
  __syncthreads();
  if (tid < 32) {
    float s = 0.f;
    for (int r = lane; r < 40; r += 32) s += sBeta[r];
#pragma unroll
    for (int o = 16; o; o >>= 1) s += __shfl_xor_sync(0xffffffffu, s, o);
    if (lane == 0) sRed[0] = s;
  }
  __syncthreads();
  float dinv = 1.f / (sRed[0] + EPSF);
  if (tid < 64) {
    float s = 0.f;
    for (int r = 0; r < 40; r++) s = fmaf(sBeta[r], g_hoI[(long)(b * 40 + r) * 64 + tid], s);
    sZ[tid] = s * dinv;
  }
  __syncthreads();
  if (tid < 64) {
    float s = sbAggn[tid];
    for (int k = 0; k < 64; k++) s = fmaf(sZ[k], sAggn[k * 64 + tid], s);
    g_hiS[b * 64 + tid] = fmaxf(s, 0.f);
  }
}

// ---------------------------------------------------------------------------
// K3: final 3-layer combine MLP (unchanged).
// ---------------------------------------------------------------------------
#define SMEM_K3 (24768 * 4)
__global__ __launch_bounds__(256) void k3_final(
    const float* __restrict__ cm_W1, const float* __restrict__ cm_b1,
    const float* __restrict__ cm_W2, const float* __restrict__ cm_b2,
    const float* __restrict__ cm_W3, const float* __restrict__ cm_b3,
    float* __restrict__ out) {
  extern __shared__ float sm[];
  float* sC1 = sm;          float* sC2 = sm + 8192;   float* sC3 = sm + 12288;
  float* sb1 = sm + 16384;  float* sb2 = sm + 16448;  float* sb3 = sm + 16512;
  float* sXT = sm + 16576;

  int tid = threadIdx.x, lane = tid & 31, w = tid >> 5;
  for (int i = tid; i < 8192; i += 256) sC1[i] = cm_W1[i];
  for (int i = tid; i < 4096; i += 256) { sC2[i] = cm_W2[i]; sC3[i] = cm_W3[i]; }
  if (tid < 64) { sb1[tid] = cm_b1[tid]; sb2[tid] = cm_b2[tid]; sb3[tid] = cm_b3[tid]; }
  __syncthreads();
  float* myXT = sXT + w * 1024;
  int rowbase = blockIdx.x * 40 + w * 5;
#pragma unroll
  for (int j = 0; j < 5; j++) {
    int row = rowbase + j;
    float x0 = 0, x1 = 0, x2 = 0, x3 = 0;
    if (row < BB) {
      x0 = g_hiI[row * 64 + lane]; x1 = g_hiI[row * 64 + 32 + lane];
      x2 = g_hiS[row * 64 + lane]; x3 = g_hiS[row * 64 + 32 + lane];
    }
    myXT[lane * 8 + j] = x0; myXT[(lane + 32) * 8 + j] = x1;
    myXT[(lane + 64) * 8 + j] = x2; myXT[(lane + 96) * 8 + j] = x3;
  }
  __syncwarp();
  float acc[5][2];
#pragma unroll
  for (int j = 0; j < 5; j++) { acc[j][0] = sb1[2 * lane]; acc[j][1] = sb1[2 * lane + 1]; }
  wgemm<128>(myXT, sC1, lane, acc);
#pragma unroll
  for (int j = 0; j < 5; j++) { acc[j][0] = fmaxf(acc[j][0], 0.f); acc[j][1] = fmaxf(acc[j][1], 0.f); }
  __syncwarp(); wtrans(myXT, lane, acc); __syncwarp();
#pragma unroll
  for (int j = 0; j < 5; j++) { acc[j][0] = sb2[2 * lane]; acc[j][1] = sb2[2 * lane + 1]; }
  wgemm<64>(myXT, sC2, lane, acc);
#pragma unroll
  for (int j = 0; j < 5; j++) { acc[j][0] = fmaxf(acc[j][0], 0.f); acc[j][1] = fmaxf(acc[j][1], 0.f); }
  __syncwarp(); wtrans(myXT, lane, acc); __syncwarp();
#pragma unroll
  for (int j = 0; j < 5; j++) { acc[j][0] = sb3[2 * lane]; acc[j][1] = sb3[2 * lane + 1]; }
  wgemm<64>(myXT, sC3, lane, acc);
#pragma unroll
  for (int j = 0; j < 5; j++) {
    int row = rowbase + j;
    if (row < BB) {
      out[row * 64 + 2 * lane]     = fmaxf(acc[j][0], 0.f);
      out[row * 64 + 2 * lane + 1] = fmaxf(acc[j][1], 0.f);
    }
  }
}

// ---------------------------------------------------------------------------
extern "C" void kernel_launch(void* const* d_in, const int* in_sizes, int n_in,
                              void* d_out, int out_size) {
  const int* uids        = (const int*)d_in[0];
  const int* u_item      = (const int*)d_in[1];
  const int* u_user      = (const int*)d_in[2];
  const int* u_user_item = (const int*)d_in[3];
  const float* user_table = (const float*)d_in[4];
  const float* item_table = (const float*)d_in[5];
  const float* rate_table = (const float*)d_in[6];
  const float* gv_W1 = (const float*)d_in[7];   const float* gv_b1 = (const float*)d_in[8];
  const float* gv_W2 = (const float*)d_in[9];   const float* gv_b2 = (const float*)d_in[10];
  const float* atti_W1 = (const float*)d_in[11]; const float* atti_b1 = (const float*)d_in[12];
  const float* atti_W2 = (const float*)d_in[13]; const float* atti_b2 = (const float*)d_in[14];
  const float* agg_W = (const float*)d_in[15];   const float* agg_b = (const float*)d_in[16];
  const float* attu_W1 = (const float*)d_in[17]; const float* attu_b1 = (const float*)d_in[18];
  const float* attu_W2 = (const float*)d_in[19]; const float* attu_b2 = (const float*)d_in[20];
  const float* aggn_W = (const float*)d_in[21];  const float* aggn_b = (const float*)d_in[22];
  const float* cm_W1 = (const float*)d_in[23];   const float* cm_b1 = (const float*)d_in[24];
  const float* cm_W2 = (const float*)d_in[25];   const float* cm_b2 = (const float*)d_in[26];
  const float* cm_W3 = (const float*)d_in[27];   const float* cm_b3 = (const float*)d_in[28];
  float* out = (float*)d_out;

  cudaFuncSetAttribute(k0_proj,  cudaFuncAttributeMaxDynamicSharedMemorySize, SMEM_K0P);
  cudaFuncSetAttribute(k0_combo, cudaFuncAttributeMaxDynamicSharedMemorySize, SMEM_K0C);
  cudaFuncSetAttribute(k2b_user, cudaFuncAttributeMaxDynamicSharedMemorySize, SMEM_K2B);
  cudaFuncSetAttribute(k3_final, cudaFuncAttributeMaxDynamicSharedMemorySize, SMEM_K3);

  k0_pre<<<1, 1024>>>(rate_table, gv_W1, gv_b1, gv_W2, gv_b2, atti_W1, atti_b1, agg_W);
  k0_proj<<<500, 256, SMEM_K0P>>>(item_table, user_table, gv_W1, atti_W1);
  k0_combo<<<1875, 256, SMEM_K0C>>>();
  k2s1_attn<<<64 + 2560, 256>>>(uids, u_user, u_user_item, u_item,
                                agg_b, atti_W2, atti_b2);
  k2b_user<<<512, 256, SMEM_K2B>>>(u_user, user_table, attu_W1, attu_b1, attu_W2,
                                   attu_b2, aggn_W, aggn_b);
  k3_final<<<13, 256, SMEM_K3>>>(cm_W1, cm_b1, cm_W2, cm_b2, cm_W3, cm_b3, out);
}

// round 10
// speedup vs baseline: 1.6387x; 1.0292x over previous
#include <cuda_runtime.h>

#define EPSF 1e-10f
#define NI 100000
#define NU 100000
#define NR 6
#define BB 512
#define PP 100
#define QQ 40
#define P2 40
#define XS 12  // XT row stride (floats)

typedef unsigned long long ull;

// ---------------- persistent scratch (static device memory) -----------------
__device__ float g_iP[NI * 64];            // item_table @ W1_top
__device__ float g_uPA1[NU * 64];          // user_table @ A1_bot
__device__ float g_rP[NR * 64];            // rate_table @ W1_bot + gv_b1
__device__ float g_Wf[64 * 64];            // W2 @ A1_top
__device__ float g_bf[64];                 // b2 @ A1_top + b1a
__device__ float g_Wg[64 * 64];            // W2 @ agg_W
__device__ float g_bg[64];                 // b2 @ agg_W
__device__ float g_T2[(long)NR * NI * 64]; // T2 = h1@Wf + bf per (rate,item)
__device__ float g_hoI[BB * QQ * 64];
__device__ float g_hiI[BB * 64];
__device__ float g_hiS[BB * 64];

// ------------------------- f32x2 packed helpers ----------------------------
__device__ __forceinline__ ull pk2(float lo, float hi) {
  ull r; asm("mov.b64 %0, {%1,%2};" : "=l"(r) : "f"(lo), "f"(hi)); return r;
}
__device__ __forceinline__ void fma2(ull& d, ull a, ull b) {
  asm("fma.rn.f32x2 %0, %1, %2, %0;" : "+l"(d) : "l"(a), "l"(b));
}
__device__ __forceinline__ void upk(ull v, float& lo, float& hi) {
  asm("mov.b64 {%0,%1}, %2;" : "=f"(lo), "=f"(hi) : "l"(v));
}

// ---------------------------------------------------------------------------
// legacy warp GEMM (5 rows), used by tail kernels k2b / k3
// ---------------------------------------------------------------------------
template <int K>
__device__ __forceinline__ void wgemm(const float* __restrict__ sXT,
                                      const float* __restrict__ sW,
                                      int lane, float acc[5][2]) {
#pragma unroll 8
  for (int k = 0; k < K; k++) {
    float2 w = *reinterpret_cast<const float2*>(sW + k * 64 + 2 * lane);
    float4 x4 = *reinterpret_cast<const float4*>(sXT + k * 8);
    float x5 = sXT[k * 8 + 4];
    acc[0][0] = fmaf(x4.x, w.x, acc[0][0]); acc[0][1] = fmaf(x4.x, w.y, acc[0][1]);
    acc[1][0] = fmaf(x4.y, w.x, acc[1][0]); acc[1][1] = fmaf(x4.y, w.y, acc[1][1]);
    acc[2][0] = fmaf(x4.z, w.x, acc[2][0]); acc[2][1] = fmaf(x4.z, w.y, acc[2][1]);
    acc[3][0] = fmaf(x4.w, w.x, acc[3][0]); acc[3][1] = fmaf(x4.w, w.y, acc[3][1]);
    acc[4][0] = fmaf(x5,  w.x, acc[4][0]);  acc[4][1] = fmaf(x5,  w.y, acc[4][1]);
  }
}
__device__ __forceinline__ void wtrans(float* sT, int lane, const float acc[5][2]) {
#pragma unroll
  for (int j = 0; j < 5; j++) {
    sT[(2 * lane) * 8 + j]     = acc[j][0];
    sT[(2 * lane + 1) * 8 + j] = acc[j][1];
  }
}

// ---------------------------------------------------------------------------
// K0_pre (parallel): grid 33.
//  blocks [0,16): Wf chunk of 256 entries; blocks [16,32): Wg chunk;
//  block 32: rP + bf + bg.
// ---------------------------------------------------------------------------
__global__ __launch_bounds__(256) void k0_pre(
    const float* __restrict__ rate_table, const float* __restrict__ gv_W1,
    const float* __restrict__ gv_b1, const float* __restrict__ gv_W2,
    const float* __restrict__ gv_b2, const float* __restrict__ atti_W1,
    const float* __restrict__ atti_b1, const float* __restrict__ agg_W) {
  int b = blockIdx.x, t = threadIdx.x;
  if (b < 16) {
    int idx = b * 256 + t;
    int k = idx >> 6, c = idx & 63;
    float s = 0.f;
#pragma unroll 8
    for (int j = 0; j < 64; j++) s = fmaf(gv_W2[k * 64 + j], atti_W1[j * 64 + c], s);
    g_Wf[idx] = s;
  } else if (b < 32) {
    int idx = (b - 16) * 256 + t;
    int k = idx >> 6, c = idx & 63;
    float s = 0.f;
#pragma unroll 8
    for (int j = 0; j < 64; j++) s = fmaf(gv_W2[k * 64 + j], agg_W[j * 64 + c], s);
    g_Wg[idx] = s;
  } else {
    for (int i = t; i < NR * 64; i += 256) {
      int r = i >> 6, c = i & 63;
      float s = gv_b1[c];
      const float* W1b = gv_W1 + 4096;
#pragma unroll 8
      for (int k = 0; k < 64; k++) s = fmaf(rate_table[r * 64 + k], W1b[k * 64 + c], s);
      g_rP[i] = s;
    }
    if (t < 64) {
      float s = atti_b1[t], sg = 0.f;
#pragma unroll 8
      for (int j = 0; j < 64; j++) {
        s = fmaf(gv_b2[j], atti_W1[j * 64 + t], s);
        sg = fmaf(gv_b2[j], agg_W[j * 64 + t], sg);
      }
      g_bf[t] = s;
      g_bg[t] = sg;
    }
  }
}

// ---------------------------------------------------------------------------
// K0_proj (FFMA2, packed x loads — row pairs adjacent in XT, zero packs)
// ---------------------------------------------------------------------------
#define SMEM_K0P ((4096 + 4096 + 8 * 64 * XS) * 4)
__global__ __launch_bounds__(256) void k0_proj(
    const float* __restrict__ item_table, const float* __restrict__ user_table,
    const float* __restrict__ gv_W1, const float* __restrict__ atti_W1) {
  extern __shared__ float sm[];
  float* sWa = sm;
  float* sWb = sm + 4096;
  float* sXT = sm + 8192;

  int tid = threadIdx.x, lane = tid & 31, w = tid >> 5;
  for (int i = tid; i < 4096; i += 256) { sWa[i] = gv_W1[i]; sWb[i] = atti_W1[4096 + i]; }
  __syncthreads();
  float* myXT = sXT + w * (64 * XS);

  for (int it = 0; it < 5; it++) {
    int rid0 = blockIdx.x * 400 + it * 80 + w * 10;
    bool half2 = (rid0 >= NI);
    const float* src = half2 ? user_table : item_table;
    const float* sW = half2 ? sWb : sWa;
    float* dst = half2 ? g_uPA1 : g_iP;
    int base = half2 ? (rid0 - NI) : rid0;
#pragma unroll
    for (int j = 0; j < 10; j++) {
      const float* sp = src + (long)(base + j) * 64;
      myXT[lane * XS + j] = sp[lane];
      myXT[(lane + 32) * XS + j] = sp[lane + 32];
    }
    __syncwarp();
    ull a0[5], a1[5];
#pragma unroll
    for (int p = 0; p < 5; p++) { a0[p] = 0ull; a1[p] = 0ull; }
#pragma unroll 8
    for (int k = 0; k < 64; k++) {
      ulonglong2 xu0 = *reinterpret_cast<const ulonglong2*>(myXT + k * XS);
      ulonglong2 xu1 = *reinterpret_cast<const ulonglong2*>(myXT + k * XS + 4);
      ull xp4 = *reinterpret_cast<const ull*>(myXT + k * XS + 8);
      float2 wv = *reinterpret_cast<const float2*>(sW + k * 64 + 2 * lane);
      ull w0 = pk2(wv.x, wv.x), w1 = pk2(wv.y, wv.y);
      fma2(a0[0], xu0.x, w0); fma2(a1[0], xu0.x, w1);
      fma2(a0[1], xu0.y, w0); fma2(a1[1], xu0.y, w1);
      fma2(a0[2], xu1.x, w0); fma2(a1[2], xu1.x, w1);
      fma2(a0[3], xu1.y, w0); fma2(a1[3], xu1.y, w1);
      fma2(a0[4], xp4, w0);   fma2(a1[4], xp4, w1);
    }
#pragma unroll
    for (int p = 0; p < 5; p++) {
      float r0c0, r1c0, r0c1, r1c1;
      upk(a0[p], r0c0, r1c0); upk(a1[p], r0c1, r1c1);
      *reinterpret_cast<float2*>(dst + (long)(base + 2 * p) * 64 + 2 * lane) =
          make_float2(r0c0, r0c1);
      *reinterpret_cast<float2*>(dst + (long)(base + 2 * p + 1) * 64 + 2 * lane) =
          make_float2(r1c0, r1c1);
    }
    __syncwarp();
  }
}

// ---------------------------------------------------------------------------
// K0_combo (FFMA2, single GEMM, packed x loads)
// ---------------------------------------------------------------------------
#define SMEM_K0C ((4096 + 8 * 64 * XS + 384 + 64) * 4)
__global__ __launch_bounds__(256) void k0_combo() {
  extern __shared__ float sm[];
  float* sWf = sm;                  // 4096
  float* sXT = sm + 4096;           // 6144
  float* srP = sm + 4096 + 6144;    // 384
  float* sbf = srP + 384;           // 64

  int tid = threadIdx.x, lane = tid & 31, w = tid >> 5;
  for (int i = tid; i < 4096; i += 256) sWf[i] = g_Wf[i];
  for (int i = tid; i < 384; i += 256) srP[i] = g_rP[i];
  if (tid < 64) sbf[tid] = g_bf[tid];
  __syncthreads();
  float* myXT = sXT + w * (64 * XS);

  float2 bb2 = *reinterpret_cast<const float2*>(sbf + 2 * lane);
  ull b20 = pk2(bb2.x, bb2.x), b21 = pk2(bb2.y, bb2.y);

  for (int it = 0; it < 4; it++) {
    int rid0 = blockIdx.x * 320 + it * 80 + w * 10;
    int r = rid0 / NI;
    int i0 = rid0 - r * NI;
    const float* rp = srP + r * 64;
    float rp0 = rp[lane], rp1 = rp[lane + 32];
#pragma unroll
    for (int j = 0; j < 10; j++) {
      const float* ip = g_iP + (long)(i0 + j) * 64;
      myXT[lane * XS + j] = fmaxf(ip[lane] + rp0, 0.f);
      myXT[(lane + 32) * XS + j] = fmaxf(ip[lane + 32] + rp1, 0.f);
    }
    __syncwarp();
    ull a20[5], a21[5];
#pragma unroll
    for (int p = 0; p < 5; p++) { a20[p] = b20; a21[p] = b21; }
#pragma unroll 8
    for (int k = 0; k < 64; k++) {
      ulonglong2 xu0 = *reinterpret_cast<const ulonglong2*>(myXT + k * XS);
      ulonglong2 xu1 = *reinterpret_cast<const ulonglong2*>(myXT + k * XS + 4);
      ull xp4 = *reinterpret_cast<const ull*>(myXT + k * XS + 8);
      float2 w2v = *reinterpret_cast<const float2*>(sWf + k * 64 + 2 * lane);
      ull w20 = pk2(w2v.x, w2v.x), w21 = pk2(w2v.y, w2v.y);
      fma2(a20[0], xu0.x, w20); fma2(a21[0], xu0.x, w21);
      fma2(a20[1], xu0.y, w20); fma2(a21[1], xu0.y, w21);
      fma2(a20[2], xu1.x, w20); fma2(a21[2], xu1.x, w21);
      fma2(a20[3], xu1.y, w20); fma2(a21[3], xu1.y, w21);
      fma2(a20[4], xp4, w20);   fma2(a21[4], xp4, w21);
    }
#pragma unroll
    for (int p = 0; p < 5; p++) {
      float r0c0, r1c0, r0c1, r1c1;
      long o0 = (long)(rid0 + 2 * p) * 64 + 2 * lane;
      long o1 = (long)(rid0 + 2 * p + 1) * 64 + 2 * lane;
      upk(a20[p], r0c0, r1c0); upk(a21[p], r0c1, r1c1);
      *reinterpret_cast<float2*>(g_T2 + o0) = make_float2(r0c0, r0c1);
      *reinterpret_cast<float2*>(g_T2 + o1) = make_float2(r1c0, r1c1);
    }
    __syncwarp();
  }
}

// ---------------------------------------------------------------------------
// K2s1: merged attention kernel, fully fused oct-slice + idx prefetch.
//  blocks [0,64): item branch, warp w -> b = bx*8+w (P=100).
//  blocks [64, 64+2560): social branch, warp w -> gid = (bx-64)*8+w (P=40).
// ---------------------------------------------------------------------------
__global__ __launch_bounds__(256) void k2s1_attn(
    const int* __restrict__ uids,
    const int* __restrict__ u_user, const int* __restrict__ u_user_item,
    const int* __restrict__ u_item,
    const float* __restrict__ agg_b,
    const float* __restrict__ atti_W2, const float* __restrict__ atti_b2) {
  __shared__ float sWg[4096];
  __shared__ float srP[384];
  __shared__ float sbAgg[64];
  __shared__ float sbg[64];
  __shared__ float sA2[64];
  __shared__ float sPart[8][4][64];   // [warp][oct][col]
  __shared__ float sZ[8][64];

  int bx = blockIdx.x, tid = threadIdx.x, lane = tid & 31, w = tid >> 5;
  for (int i = tid; i < 4096; i += 256) sWg[i] = g_Wg[i];
  for (int i = tid; i < 384; i += 256) srP[i] = g_rP[i];
  if (tid < 64) { sbAgg[tid] = agg_b[tid]; sbg[tid] = g_bg[tid]; sA2[tid] = atti_W2[tid]; }
  __syncthreads();
  float cb = atti_b2[0];

  bool item = (bx < 64);
  int unit = item ? (bx * 8 + w) : ((bx - 64) * 8 + w);  // b or gid
  int P = item ? PP : P2;
  int u = item ? uids[unit] : u_user[unit];
  const int2* ips = reinterpret_cast<const int2*>(
      item ? (u_item + (long)unit * (PP * 2)) : (u_user_item + (long)unit * (P2 * 2)));
  float* outp = item ? (g_hiI + (long)unit * 64) : (g_hoI + (long)unit * 64);

  int li = lane & 7, oct = lane >> 3;  // 8 lanes per row, 4 rows per iter
  const float* uP = g_uPA1 + (long)u * 64 + li * 8;
  float4 pcr0 = *reinterpret_cast<const float4*>(uP);
  float4 pcr1 = *reinterpret_cast<const float4*>(uP + 4);
  float4 a2r0 = *reinterpret_cast<const float4*>(sA2 + li * 8);
  float4 a2r1 = *reinterpret_cast<const float4*>(sA2 + li * 8 + 4);

  float4 acca = make_float4(0.f, 0.f, 0.f, 0.f);
  float4 accb = make_float4(0.f, 0.f, 0.f, 0.f);
  float den = 0.f;
  int niter = P >> 2;  // 40->10, 100->25 (exact)
  int2 idx = ips[oct];
  for (int it = 0; it < niter; it++) {
    int rn = (it + 1) * 4 + oct;
    int2 idxn = ips[(rn < P) ? rn : oct];  // prefetch next iteration's index
    float m = (idx.x > 0) ? 1.f : 0.f;
    long rid = (long)(idx.y * NI + idx.x);
    const float4* t2p = reinterpret_cast<const float4*>(g_T2 + rid * 64 + li * 8);
    float4 t2a = t2p[0], t2b = t2p[1];
    const float4* ipp = reinterpret_cast<const float4*>(g_iP + (long)idx.x * 64 + li * 8);
    float4 ipa = ipp[0], ipb = ipp[1];
    const float4* rpp = reinterpret_cast<const float4*>(srP + idx.y * 64 + li * 8);
    float4 rpa = rpp[0], rpb = rpp[1];
    float s;
    s = fmaxf(fmaf(m, pcr0.x, t2a.x), 0.f) * a2r0.x;
    s = fmaf(fmaxf(fmaf(m, pcr0.y, t2a.y), 0.f), a2r0.y, s);
    s = fmaf(fmaxf(fmaf(m, pcr0.z, t2a.z), 0.f), a2r0.z, s);
    s = fmaf(fmaxf(fmaf(m, pcr0.w, t2a.w), 0.f), a2r0.w, s);
    s = fmaf(fmaxf(fmaf(m, pcr1.x, t2b.x), 0.f), a2r1.x, s);
    s = fmaf(fmaxf(fmaf(m, pcr1.y, t2b.y), 0.f), a2r1.y, s);
    s = fmaf(fmaxf(fmaf(m, pcr1.z, t2b.z), 0.f), a2r1.z, s);
    s = fmaf(fmaxf(fmaf(m, pcr1.w, t2b.w), 0.f), a2r1.w, s);
    s += __shfl_xor_sync(0xffffffffu, s, 1);
    s += __shfl_xor_sync(0xffffffffu, s, 2);
    s += __shfl_xor_sync(0xffffffffu, s, 4);
    float al = __expf(s + cb) * m;
    den += al;
    acca.x = fmaf(al, fmaxf(ipa.x + rpa.x, 0.f), acca.x);
    acca.y = fmaf(al, fmaxf(ipa.y + rpa.y, 0.f), acca.y);
    acca.z = fmaf(al, fmaxf(ipa.z + rpa.z, 0.f), acca.z);
    acca.w = fmaf(al, fmaxf(ipa.w + rpa.w, 0.f), acca.w);
    accb.x = fmaf(al, fmaxf(ipb.x + rpb.x, 0.f), accb.x);
    accb.y = fmaf(al, fmaxf(ipb.y + rpb.y, 0.f), accb.y);
    accb.z = fmaf(al, fmaxf(ipb.z + rpb.z, 0.f), accb.z);
    accb.w = fmaf(al, fmaxf(ipb.w + rpb.w, 0.f), accb.w);
    idx = idxn;
  }
#pragma unroll
  for (int o = 16; o; o >>= 1) den += __shfl_xor_sync(0xffffffffu, den, o);
  den *= 0.125f;  // each row's alpha counted 8x (once per oct lane)
  float dinv = 1.f / (den + EPSF);
  float sig = den * dinv;

  // combine oct partials: sPart[w][oct][col]
  *reinterpret_cast<float4*>(&sPart[w][oct][li * 8]) = acca;
  *reinterpret_cast<float4*>(&sPart[w][oct][li * 8 + 4]) = accb;
  __syncwarp();
  int c0 = 2 * lane;
  float zx = sPart[w][0][c0] + sPart[w][1][c0] + sPart[w][2][c0] + sPart[w][3][c0];
  float zy = sPart[w][0][c0 + 1] + sPart[w][1][c0 + 1] + sPart[w][2][c0 + 1] + sPart[w][3][c0 + 1];
  sZ[w][c0] = zx * dinv;
  sZ[w][c0 + 1] = zy * dinv;
  __syncwarp();

  // epilogue GEMV: out = relu(z@Wg + sig*bg + agg_b)
  float ox = fmaf(sig, sbg[c0], sbAgg[c0]);
  float oy = fmaf(sig, sbg[c0 + 1], sbAgg[c0 + 1]);
#pragma unroll 8
  for (int k = 0; k < 64; k++) {
    float zk = sZ[w][k];
    float2 wk = *reinterpret_cast<const float2*>(sWg + k * 64 + c0);
    ox = fmaf(zk, wk.x, ox); oy = fmaf(zk, wk.y, oy);
  }
  *reinterpret_cast<float2*>(outp + c0) =
      make_float2(fmaxf(ox, 0.f), fmaxf(oy, 0.f));
}

// ---------------------------------------------------------------------------
// K2b: beta attention over q + h_iS (unchanged).
// ---------------------------------------------------------------------------
#define SMEM_K2B (20784 * 4)
__global__ __launch_bounds__(256) void k2b_user(
    const int* __restrict__ u_user, const float* __restrict__ user_table,
    const float* __restrict__ attu_W1, const float* __restrict__ attu_b1,
    const float* __restrict__ attu_W2, const float* __restrict__ attu_b2,
    const float* __restrict__ aggn_W, const float* __restrict__ aggn_b) {
  extern __shared__ float sm[];
  float* sU1 = sm;             float* sAggn = sm + 8192;
  float* sw2u = sm + 12288;    float* sb1u = sm + 12352;
  float* sbAggn = sm + 12416;  float* sZ = sm + 12480;
  float* sBeta = sm + 12544;   float* sRed = sm + 12584;
  float* sXT = sm + 12592;

  int b = blockIdx.x, tid = threadIdx.x, lane = tid & 31, w = tid >> 5;
  for (int i = tid; i < 8192; i += 256) sU1[i] = attu_W1[i];
  for (int i = tid; i < 4096; i += 256) sAggn[i] = aggn_W[i];
  if (tid < 64) { sw2u[tid] = attu_W2[tid]; sb1u[tid] = attu_b1[tid]; sbAggn[tid] = aggn_b[tid]; }
  __syncthreads();
  float cb2u = attu_b2[0];
  float* myXT = sXT + w * 1024;
  int rowbase = w * 5;
  float msk[5];
#pragma unroll
  for (int j = 0; j < 5; j++) {
    int row = rowbase + j;
    int uq = u_user[b * 40 + row];
    msk[j] = (uq > 0) ? 1.f : 0.f;
    const float* hp = g_hoI + (long)(b * 40 + row) * 64;
    const float* up = user_table + (long)uq * 64;
    myXT[lane * 8 + j] = hp[lane]; myXT[(lane + 32) * 8 + j] = hp[lane + 32];
    myXT[(lane + 64) * 8 + j] = up[lane]; myXT[(lane + 96) * 8 + j] = up[lane + 32];
  }
  __syncwarp();
  float acc[5][2];
#pragma unroll
  for (int j = 0; j < 5; j++) { acc[j][0] = sb1u[2 * lane]; acc[j][1] = sb1u[2 * lane + 1]; }
  wgemm<128>(myXT, sU1, lane, acc);
  float w0 = sw2u[2 * lane], w1 = sw2u[2 * lane + 1];
#pragma unroll
  for (int j = 0; j < 5; j++) {
    float p = fmaf(fmaxf(acc[j][0], 0.f), w0, fmaxf(acc[j][1], 0.f) * w1);
#pragma unroll
    for (int o = 16; o; o >>= 1) p += __shfl_xor_sync(0xffffffffu, p, o);
    if (lane == 0) sBeta[rowbase + j] = expf(p + cb2u) * msk[j];
  }
  __syncthreads();
  if (tid < 32) {
    float s = 0.f;
    for (int r = lane; r < 40; r += 32) s += sBeta[r];
#pragma unroll
    for (int o = 16; o; o >>= 1) s += __shfl_xor_sync(0xffffffffu, s, o);
    if (lane == 0) sRed[0] = s;
  }
  __syncthreads();
  float dinv = 1.f / (sRed[0] + EPSF);
  if (tid < 64) {
    float s = 0.f;
    for (int r = 0; r < 40; r++) s = fmaf(sBeta[r], g_hoI[(long)(b * 40 + r) * 64 + tid], s);
    sZ[tid] = s * dinv;
  }
  __syncthreads();
  if (tid < 64) {
    float s = sbAggn[tid];
    for (int k = 0; k < 64; k++) s = fmaf(sZ[k], sAggn[k * 64 + tid], s);
    g_hiS[b * 64 + tid] = fmaxf(s, 0.f);
  }
}

// ---------------------------------------------------------------------------
// K3: final 3-layer combine MLP (unchanged).
// ---------------------------------------------------------------------------
#define SMEM_K3 (24768 * 4)
__global__ __launch_bounds__(256) void k3_final(
    const float* __restrict__ cm_W1, const float* __restrict__ cm_b1,
    const float* __restrict__ cm_W2, const float* __restrict__ cm_b2,
    const float* __restrict__ cm_W3, const float* __restrict__ cm_b3,
    float* __restrict__ out) {
  extern __shared__ float sm[];
  float* sC1 = sm;          float* sC2 = sm + 8192;   float* sC3 = sm + 12288;
  float* sb1 = sm + 16384;  float* sb2 = sm + 16448;  float* sb3 = sm + 16512;
  float* sXT = sm + 16576;

  int tid = threadIdx.x, lane = tid & 31, w = tid >> 5;
  for (int i = tid; i < 8192; i += 256) sC1[i] = cm_W1[i];
  for (int i = tid; i < 4096; i += 256) { sC2[i] = cm_W2[i]; sC3[i] = cm_W3[i]; }
  if (tid < 64) { sb1[tid] = cm_b1[tid]; sb2[tid] = cm_b2[tid]; sb3[tid] = cm_b3[tid]; }
  __syncthreads();
  float* myXT = sXT + w * 1024;
  int rowbase = blockIdx.x * 40 + w * 5;
#pragma unroll
  for (int j = 0; j < 5; j++) {
    int row = rowbase + j;
    float x0 = 0, x1 = 0, x2 = 0, x3 = 0;
    if (row < BB) {
      x0 = g_hiI[row * 64 + lane]; x1 = g_hiI[row * 64 + 32 + lane];
      x2 = g_hiS[row * 64 + lane]; x3 = g_hiS[row * 64 + 32 + lane];
    }
    myXT[lane * 8 + j] = x0; myXT[(lane + 32) * 8 + j] = x1;
    myXT[(lane + 64) * 8 + j] = x2; myXT[(lane + 96) * 8 + j] = x3;
  }
  __syncwarp();
  float acc[5][2];
#pragma unroll
  for (int j = 0; j < 5; j++) { acc[j][0] = sb1[2 * lane]; acc[j][1] = sb1[2 * lane + 1]; }
  wgemm<128>(myXT, sC1, lane, acc);
#pragma unroll
  for (int j = 0; j < 5; j++) { acc[j][0] = fmaxf(acc[j][0], 0.f); acc[j][1] = fmaxf(acc[j][1], 0.f); }
  __syncwarp(); wtrans(myXT, lane, acc); __syncwarp();
#pragma unroll
  for (int j = 0; j < 5; j++) { acc[j][0] = sb2[2 * lane]; acc[j][1] = sb2[2 * lane + 1]; }
  wgemm<64>(myXT, sC2, lane, acc);
#pragma unroll
  for (int j = 0; j < 5; j++) { acc[j][0] = fmaxf(acc[j][0], 0.f); acc[j][1] = fmaxf(acc[j][1], 0.f); }
  __syncwarp(); wtrans(myXT, lane, acc); __syncwarp();
#pragma unroll
  for (int j = 0; j < 5; j++) { acc[j][0] = sb3[2 * lane]; acc[j][1] = sb3[2 * lane + 1]; }
  wgemm<64>(myXT, sC3, lane, acc);
#pragma unroll
  for (int j = 0; j < 5; j++) {
    int row = rowbase + j;
    if (row < BB) {
      out[row * 64 + 2 * lane]     = fmaxf(acc[j][0], 0.f);
      out[row * 64 + 2 * lane + 1] = fmaxf(acc[j][1], 0.f);
    }
  }
}

// ---------------------------------------------------------------------------
extern "C" void kernel_launch(void* const* d_in, const int* in_sizes, int n_in,
                              void* d_out, int out_size) {
  const int* uids        = (const int*)d_in[0];
  const int* u_item      = (const int*)d_in[1];
  const int* u_user      = (const int*)d_in[2];
  const int* u_user_item = (const int*)d_in[3];
  const float* user_table = (const float*)d_in[4];
  const float* item_table = (const float*)d_in[5];
  const float* rate_table = (const float*)d_in[6];
  const float* gv_W1 = (const float*)d_in[7];   const float* gv_b1 = (const float*)d_in[8];
  const float* gv_W2 = (const float*)d_in[9];   const float* gv_b2 = (const float*)d_in[10];
  const float* atti_W1 = (const float*)d_in[11]; const float* atti_b1 = (const float*)d_in[12];
  const float* atti_W2 = (const float*)d_in[13]; const float* atti_b2 = (const float*)d_in[14];
  const float* agg_W = (const float*)d_in[15];   const float* agg_b = (const float*)d_in[16];
  const float* attu_W1 = (const float*)d_in[17]; const float* attu_b1 = (const float*)d_in[18];
  const float* attu_W2 = (const float*)d_in[19]; const float* attu_b2 = (const float*)d_in[20];
  const float* aggn_W = (const float*)d_in[21];  const float* aggn_b = (const float*)d_in[22];
  const float* cm_W1 = (const float*)d_in[23];   const float* cm_b1 = (const float*)d_in[24];
  const float* cm_W2 = (const float*)d_in[25];   const float* cm_b2 = (const float*)d_in[26];
  const float* cm_W3 = (const float*)d_in[27];   const float* cm_b3 = (const float*)d_in[28];
  float* out = (float*)d_out;

  cudaFuncSetAttribute(k0_proj,  cudaFuncAttributeMaxDynamicSharedMemorySize, SMEM_K0P);
  cudaFuncSetAttribute(k0_combo, cudaFuncAttributeMaxDynamicSharedMemorySize, SMEM_K0C);
  cudaFuncSetAttribute(k2b_user, cudaFuncAttributeMaxDynamicSharedMemorySize, SMEM_K2B);
  cudaFuncSetAttribute(k3_final, cudaFuncAttributeMaxDynamicSharedMemorySize, SMEM_K3);

  k0_pre<<<33, 256>>>(rate_table, gv_W1, gv_b1, gv_W2, gv_b2, atti_W1, atti_b1, agg_W);
  k0_proj<<<500, 256, SMEM_K0P>>>(item_table, user_table, gv_W1, atti_W1);
  k0_combo<<<1875, 256, SMEM_K0C>>>();
  k2s1_attn<<<64 + 2560, 256>>>(uids, u_user, u_user_item, u_item,
                                agg_b, atti_W2, atti_b2);
  k2b_user<<<512, 256, SMEM_K2B>>>(u_user, user_table, attu_W1, attu_b1, attu_W2,
                                   attu_b2, aggn_W, aggn_b);
  k3_final<<<13, 256, SMEM_K3>>>(cm_W1, cm_b1, cm_W2, cm_b2, cm_W3, cm_b3, out);
}

// round 11
// speedup vs baseline: 1.6670x; 1.0173x over previous
#include <cuda_runtime.h>

#define EPSF 1e-10f
#define NI 100000
#define NU 100000
#define NR 6
#define BB 512
#define PP 100
#define QQ 40
#define P2 40
#define XS 12  // XT row stride (floats)

typedef unsigned long long ull;

// ---------------- persistent scratch (static device memory) -----------------
__device__ float g_iP[NI * 64];            // item_table @ W1_top
__device__ float g_uPA1[NU * 64];          // user_table @ A1_bot
__device__ float g_rP[NR * 64];            // rate_table @ W1_bot + gv_b1
__device__ float g_Wf[64 * 64];            // W2 @ A1_top
__device__ float g_bf[64];                 // b2 @ A1_top + b1a
__device__ float g_Wg[64 * 64];            // W2 @ agg_W
__device__ float g_bg[64];                 // b2 @ agg_W
__device__ float g_T2[(long)NR * NI * 64]; // T2 = h1@Wf + bf per (rate,item)
__device__ float g_hoI[BB * QQ * 64];
__device__ float g_hiI[BB * 64];
__device__ float g_hiS[BB * 64];

// ------------------------- f32x2 packed helpers ----------------------------
__device__ __forceinline__ ull pk2(float lo, float hi) {
  ull r; asm("mov.b64 %0, {%1,%2};" : "=l"(r) : "f"(lo), "f"(hi)); return r;
}
__device__ __forceinline__ void fma2(ull& d, ull a, ull b) {
  asm("fma.rn.f32x2 %0, %1, %2, %0;" : "+l"(d) : "l"(a), "l"(b));
}
__device__ __forceinline__ void upk(ull v, float& lo, float& hi) {
  asm("mov.b64 {%0,%1}, %2;" : "=f"(lo), "=f"(hi) : "l"(v));
}

// ---------------------------------------------------------------------------
// packed 5-row warp GEMM (XT stride 8): rows 0-3 as two f32x2 pairs, row 4
// scalar. Bitwise identical to the scalar version.
// ---------------------------------------------------------------------------
template <int K>
__device__ __forceinline__ void wgemm2(const float* __restrict__ sXT,
                                       const float* __restrict__ sW, int lane,
                                       ull a0[2], ull a1[2], float& s40, float& s41) {
#pragma unroll 8
  for (int k = 0; k < K; k++) {
    ulonglong2 xu = *reinterpret_cast<const ulonglong2*>(sXT + k * 8); // rows 0..3
    float x5 = sXT[k * 8 + 4];
    float2 wv = *reinterpret_cast<const float2*>(sW + k * 64 + 2 * lane);
    ull w0 = pk2(wv.x, wv.x), w1 = pk2(wv.y, wv.y);
    fma2(a0[0], xu.x, w0); fma2(a1[0], xu.x, w1);
    fma2(a0[1], xu.y, w0); fma2(a1[1], xu.y, w1);
    s40 = fmaf(x5, wv.x, s40); s41 = fmaf(x5, wv.y, s41);
  }
}
__device__ __forceinline__ void unpack5(const ull a0[2], const ull a1[2],
                                        float s40, float s41, float acc[5][2]) {
  upk(a0[0], acc[0][0], acc[1][0]); upk(a0[1], acc[2][0], acc[3][0]);
  upk(a1[0], acc[0][1], acc[1][1]); upk(a1[1], acc[2][1], acc[3][1]);
  acc[4][0] = s40; acc[4][1] = s41;
}
__device__ __forceinline__ void wtrans(float* sT, int lane, const float acc[5][2]) {
#pragma unroll
  for (int j = 0; j < 5; j++) {
    sT[(2 * lane) * 8 + j]     = acc[j][0];
    sT[(2 * lane + 1) * 8 + j] = acc[j][1];
  }
}

// ---------------------------------------------------------------------------
// K0_pre (parallel): grid 33.
// ---------------------------------------------------------------------------
__global__ __launch_bounds__(256) void k0_pre(
    const float* __restrict__ rate_table, const float* __restrict__ gv_W1,
    const float* __restrict__ gv_b1, const float* __restrict__ gv_W2,
    const float* __restrict__ gv_b2, const float* __restrict__ atti_W1,
    const float* __restrict__ atti_b1, const float* __restrict__ agg_W) {
  int b = blockIdx.x, t = threadIdx.x;
  if (b < 16) {
    int idx = b * 256 + t;
    int k = idx >> 6, c = idx & 63;
    float s = 0.f;
#pragma unroll 8
    for (int j = 0; j < 64; j++) s = fmaf(gv_W2[k * 64 + j], atti_W1[j * 64 + c], s);
    g_Wf[idx] = s;
  } else if (b < 32) {
    int idx = (b - 16) * 256 + t;
    int k = idx >> 6, c = idx & 63;
    float s = 0.f;
#pragma unroll 8
    for (int j = 0; j < 64; j++) s = fmaf(gv_W2[k * 64 + j], agg_W[j * 64 + c], s);
    g_Wg[idx] = s;
  } else {
    for (int i = t; i < NR * 64; i += 256) {
      int r = i >> 6, c = i & 63;
      float s = gv_b1[c];
      const float* W1b = gv_W1 + 4096;
#pragma unroll 8
      for (int k = 0; k < 64; k++) s = fmaf(rate_table[r * 64 + k], W1b[k * 64 + c], s);
      g_rP[i] = s;
    }
    if (t < 64) {
      float s = atti_b1[t], sg = 0.f;
#pragma unroll 8
      for (int j = 0; j < 64; j++) {
        s = fmaf(gv_b2[j], atti_W1[j * 64 + t], s);
        sg = fmaf(gv_b2[j], agg_W[j * 64 + t], sg);
      }
      g_bf[t] = s;
      g_bg[t] = sg;
    }
  }
}

// ---------------------------------------------------------------------------
// K0_proj (FFMA2, packed x loads)
// ---------------------------------------------------------------------------
#define SMEM_K0P ((4096 + 4096 + 8 * 64 * XS) * 4)
__global__ __launch_bounds__(256) void k0_proj(
    const float* __restrict__ item_table, const float* __restrict__ user_table,
    const float* __restrict__ gv_W1, const float* __restrict__ atti_W1) {
  extern __shared__ float sm[];
  float* sWa = sm;
  float* sWb = sm + 4096;
  float* sXT = sm + 8192;

  int tid = threadIdx.x, lane = tid & 31, w = tid >> 5;
  for (int i = tid; i < 4096; i += 256) { sWa[i] = gv_W1[i]; sWb[i] = atti_W1[4096 + i]; }
  __syncthreads();
  float* myXT = sXT + w * (64 * XS);

  for (int it = 0; it < 5; it++) {
    int rid0 = blockIdx.x * 400 + it * 80 + w * 10;
    bool half2 = (rid0 >= NI);
    const float* src = half2 ? user_table : item_table;
    const float* sW = half2 ? sWb : sWa;
    float* dst = half2 ? g_uPA1 : g_iP;
    int base = half2 ? (rid0 - NI) : rid0;
#pragma unroll
    for (int j = 0; j < 10; j++) {
      const float* sp = src + (long)(base + j) * 64;
      myXT[lane * XS + j] = sp[lane];
      myXT[(lane + 32) * XS + j] = sp[lane + 32];
    }
    __syncwarp();
    ull a0[5], a1[5];
#pragma unroll
    for (int p = 0; p < 5; p++) { a0[p] = 0ull; a1[p] = 0ull; }
#pragma unroll 8
    for (int k = 0; k < 64; k++) {
      ulonglong2 xu0 = *reinterpret_cast<const ulonglong2*>(myXT + k * XS);
      ulonglong2 xu1 = *reinterpret_cast<const ulonglong2*>(myXT + k * XS + 4);
      ull xp4 = *reinterpret_cast<const ull*>(myXT + k * XS + 8);
      float2 wv = *reinterpret_cast<const float2*>(sW + k * 64 + 2 * lane);
      ull w0 = pk2(wv.x, wv.x), w1 = pk2(wv.y, wv.y);
      fma2(a0[0], xu0.x, w0); fma2(a1[0], xu0.x, w1);
      fma2(a0[1], xu0.y, w0); fma2(a1[1], xu0.y, w1);
      fma2(a0[2], xu1.x, w0); fma2(a1[2], xu1.x, w1);
      fma2(a0[3], xu1.y, w0); fma2(a1[3], xu1.y, w1);
      fma2(a0[4], xp4, w0);   fma2(a1[4], xp4, w1);
    }
#pragma unroll
    for (int p = 0; p < 5; p++) {
      float r0c0, r1c0, r0c1, r1c1;
      upk(a0[p], r0c0, r1c0); upk(a1[p], r0c1, r1c1);
      *reinterpret_cast<float2*>(dst + (long)(base + 2 * p) * 64 + 2 * lane) =
          make_float2(r0c0, r0c1);
      *reinterpret_cast<float2*>(dst + (long)(base + 2 * p + 1) * 64 + 2 * lane) =
          make_float2(r1c0, r1c1);
    }
    __syncwarp();
  }
}

// ---------------------------------------------------------------------------
// K0_combo (FFMA2, single GEMM, packed x loads)
// ---------------------------------------------------------------------------
#define SMEM_K0C ((4096 + 8 * 64 * XS + 384 + 64) * 4)
__global__ __launch_bounds__(256) void k0_combo() {
  extern __shared__ float sm[];
  float* sWf = sm;                  // 4096
  float* sXT = sm + 4096;           // 6144
  float* srP = sm + 4096 + 6144;    // 384
  float* sbf = srP + 384;           // 64

  int tid = threadIdx.x, lane = tid & 31, w = tid >> 5;
  for (int i = tid; i < 4096; i += 256) sWf[i] = g_Wf[i];
  for (int i = tid; i < 384; i += 256) srP[i] = g_rP[i];
  if (tid < 64) sbf[tid] = g_bf[tid];
  __syncthreads();
  float* myXT = sXT + w * (64 * XS);

  float2 bb2 = *reinterpret_cast<const float2*>(sbf + 2 * lane);
  ull b20 = pk2(bb2.x, bb2.x), b21 = pk2(bb2.y, bb2.y);

  for (int it = 0; it < 4; it++) {
    int rid0 = blockIdx.x * 320 + it * 80 + w * 10;
    int r = rid0 / NI;
    int i0 = rid0 - r * NI;
    const float* rp = srP + r * 64;
    float rp0 = rp[lane], rp1 = rp[lane + 32];
#pragma unroll
    for (int j = 0; j < 10; j++) {
      const float* ip = g_iP + (long)(i0 + j) * 64;
      myXT[lane * XS + j] = fmaxf(ip[lane] + rp0, 0.f);
      myXT[(lane + 32) * XS + j] = fmaxf(ip[lane + 32] + rp1, 0.f);
    }
    __syncwarp();
    ull a20[5], a21[5];
#pragma unroll
    for (int p = 0; p < 5; p++) { a20[p] = b20; a21[p] = b21; }
#pragma unroll 8
    for (int k = 0; k < 64; k++) {
      ulonglong2 xu0 = *reinterpret_cast<const ulonglong2*>(myXT + k * XS);
      ulonglong2 xu1 = *reinterpret_cast<const ulonglong2*>(myXT + k * XS + 4);
      ull xp4 = *reinterpret_cast<const ull*>(myXT + k * XS + 8);
      float2 w2v = *reinterpret_cast<const float2*>(sWf + k * 64 + 2 * lane);
      ull w20 = pk2(w2v.x, w2v.x), w21 = pk2(w2v.y, w2v.y);
      fma2(a20[0], xu0.x, w20); fma2(a21[0], xu0.x, w21);
      fma2(a20[1], xu0.y, w20); fma2(a21[1], xu0.y, w21);
      fma2(a20[2], xu1.x, w20); fma2(a21[2], xu1.x, w21);
      fma2(a20[3], xu1.y, w20); fma2(a21[3], xu1.y, w21);
      fma2(a20[4], xp4, w20);   fma2(a21[4], xp4, w21);
    }
#pragma unroll
    for (int p = 0; p < 5; p++) {
      float r0c0, r1c0, r0c1, r1c1;
      long o0 = (long)(rid0 + 2 * p) * 64 + 2 * lane;
      long o1 = (long)(rid0 + 2 * p + 1) * 64 + 2 * lane;
      upk(a20[p], r0c0, r1c0); upk(a21[p], r0c1, r1c1);
      *reinterpret_cast<float2*>(g_T2 + o0) = make_float2(r0c0, r0c1);
      *reinterpret_cast<float2*>(g_T2 + o1) = make_float2(r1c0, r1c1);
    }
    __syncwarp();
  }
}

// ---------------------------------------------------------------------------
// K2s1: merged attention kernel, fused oct-slice, 5 CTAs/SM target.
//  pc kept in smem (broadcast LDS per iter) to cut register pressure.
//  blocks [0,64): item branch; blocks [64, 64+2560): social branch.
// ---------------------------------------------------------------------------
__global__ __launch_bounds__(256, 5) void k2s1_attn(
    const int* __restrict__ uids,
    const int* __restrict__ u_user, const int* __restrict__ u_user_item,
    const int* __restrict__ u_item,
    const float* __restrict__ agg_b,
    const float* __restrict__ atti_W2, const float* __restrict__ atti_b2) {
  __shared__ float sWg[4096];
  __shared__ float srP[384];
  __shared__ float sbAgg[64];
  __shared__ float sbg[64];
  __shared__ float sA2[64];
  __shared__ float sPC[8][64];
  __shared__ float sPart[8][4][64];   // [warp][oct][col]
  __shared__ float sZ[8][64];

  int bx = blockIdx.x, tid = threadIdx.x, lane = tid & 31, w = tid >> 5;
  for (int i = tid; i < 4096; i += 256) sWg[i] = g_Wg[i];
  for (int i = tid; i < 384; i += 256) srP[i] = g_rP[i];
  if (tid < 64) { sbAgg[tid] = agg_b[tid]; sbg[tid] = g_bg[tid]; sA2[tid] = atti_W2[tid]; }
  __syncthreads();
  float cb = atti_b2[0];

  bool item = (bx < 64);
  int unit = item ? (bx * 8 + w) : ((bx - 64) * 8 + w);  // b or gid
  int P = item ? PP : P2;
  int u = item ? uids[unit] : u_user[unit];
  const int2* ips = reinterpret_cast<const int2*>(
      item ? (u_item + (long)unit * (PP * 2)) : (u_user_item + (long)unit * (P2 * 2)));
  float* outp = item ? (g_hiI + (long)unit * 64) : (g_hoI + (long)unit * 64);

  // stage pc for this unit into smem (per-warp row)
  sPC[w][lane] = g_uPA1[(long)u * 64 + lane];
  sPC[w][lane + 32] = g_uPA1[(long)u * 64 + 32 + lane];
  __syncwarp();

  int li = lane & 7, oct = lane >> 3;  // 8 lanes per row, 4 rows per iter
  float4 a2r0 = *reinterpret_cast<const float4*>(sA2 + li * 8);
  float4 a2r1 = *reinterpret_cast<const float4*>(sA2 + li * 8 + 4);

  float4 acca = make_float4(0.f, 0.f, 0.f, 0.f);
  float4 accb = make_float4(0.f, 0.f, 0.f, 0.f);
  float den = 0.f;
  int niter = P >> 2;  // 40->10, 100->25 (exact)
  for (int it = 0; it < niter; it++) {
    int r = it * 4 + oct;
    int2 idx = ips[r];
    float m = (idx.x > 0) ? 1.f : 0.f;
    long rid = (long)(idx.y * NI + idx.x);
    const float4* t2p = reinterpret_cast<const float4*>(g_T2 + rid * 64 + li * 8);
    float4 t2a = t2p[0], t2b = t2p[1];
    const float4* ipp = reinterpret_cast<const float4*>(g_iP + (long)idx.x * 64 + li * 8);
    float4 ipa = ipp[0], ipb = ipp[1];
    const float4* rpp = reinterpret_cast<const float4*>(srP + idx.y * 64 + li * 8);
    float4 rpa = rpp[0], rpb = rpp[1];
    const float4* pcp = reinterpret_cast<const float4*>(&sPC[w][li * 8]);
    float4 pcr0 = pcp[0], pcr1 = pcp[1];
    float s;
    s = fmaxf(fmaf(m, pcr0.x, t2a.x), 0.f) * a2r0.x;
    s = fmaf(fmaxf(fmaf(m, pcr0.y, t2a.y), 0.f), a2r0.y, s);
    s = fmaf(fmaxf(fmaf(m, pcr0.z, t2a.z), 0.f), a2r0.z, s);
    s = fmaf(fmaxf(fmaf(m, pcr0.w, t2a.w), 0.f), a2r0.w, s);
    s = fmaf(fmaxf(fmaf(m, pcr1.x, t2b.x), 0.f), a2r1.x, s);
    s = fmaf(fmaxf(fmaf(m, pcr1.y, t2b.y), 0.f), a2r1.y, s);
    s = fmaf(fmaxf(fmaf(m, pcr1.z, t2b.z), 0.f), a2r1.z, s);
    s = fmaf(fmaxf(fmaf(m, pcr1.w, t2b.w), 0.f), a2r1.w, s);
    s += __shfl_xor_sync(0xffffffffu, s, 1);
    s += __shfl_xor_sync(0xffffffffu, s, 2);
    s += __shfl_xor_sync(0xffffffffu, s, 4);
    float al = __expf(s + cb) * m;
    den += al;
    acca.x = fmaf(al, fmaxf(ipa.x + rpa.x, 0.f), acca.x);
    acca.y = fmaf(al, fmaxf(ipa.y + rpa.y, 0.f), acca.y);
    acca.z = fmaf(al, fmaxf(ipa.z + rpa.z, 0.f), acca.z);
    acca.w = fmaf(al, fmaxf(ipa.w + rpa.w, 0.f), acca.w);
    accb.x = fmaf(al, fmaxf(ipb.x + rpb.x, 0.f), accb.x);
    accb.y = fmaf(al, fmaxf(ipb.y + rpb.y, 0.f), accb.y);
    accb.z = fmaf(al, fmaxf(ipb.z + rpb.z, 0.f), accb.z);
    accb.w = fmaf(al, fmaxf(ipb.w + rpb.w, 0.f), accb.w);
  }
#pragma unroll
  for (int o = 16; o; o >>= 1) den += __shfl_xor_sync(0xffffffffu, den, o);
  den *= 0.125f;  // each row's alpha counted 8x (once per oct lane)
  float dinv = 1.f / (den + EPSF);
  float sig = den * dinv;

  // combine oct partials: sPart[w][oct][col]
  *reinterpret_cast<float4*>(&sPart[w][oct][li * 8]) = acca;
  *reinterpret_cast<float4*>(&sPart[w][oct][li * 8 + 4]) = accb;
  __syncwarp();
  int c0 = 2 * lane;
  float zx = sPart[w][0][c0] + sPart[w][1][c0] + sPart[w][2][c0] + sPart[w][3][c0];
  float zy = sPart[w][0][c0 + 1] + sPart[w][1][c0 + 1] + sPart[w][2][c0 + 1] + sPart[w][3][c0 + 1];
  sZ[w][c0] = zx * dinv;
  sZ[w][c0 + 1] = zy * dinv;
  __syncwarp();

  // epilogue GEMV: out = relu(z@Wg + sig*bg + agg_b)
  float ox = fmaf(sig, sbg[c0], sbAgg[c0]);
  float oy = fmaf(sig, sbg[c0 + 1], sbAgg[c0 + 1]);
#pragma unroll 8
  for (int k = 0; k < 64; k++) {
    float zk = sZ[w][k];
    float2 wk = *reinterpret_cast<const float2*>(sWg + k * 64 + c0);
    ox = fmaf(zk, wk.x, ox); oy = fmaf(zk, wk.y, oy);
  }
  *reinterpret_cast<float2*>(outp + c0) =
      make_float2(fmaxf(ox, 0.f), fmaxf(oy, 0.f));
}

// ---------------------------------------------------------------------------
// K2b: beta attention over q + h_iS. FFMA2 GEMM, 2 batch elements per CTA.
// grid 256.
// ---------------------------------------------------------------------------
#define SMEM_K2B (20784 * 4)
__global__ __launch_bounds__(256) void k2b_user(
    const int* __restrict__ u_user, const float* __restrict__ user_table,
    const float* __restrict__ attu_W1, const float* __restrict__ attu_b1,
    const float* __restrict__ attu_W2, const float* __restrict__ attu_b2,
    const float* __restrict__ aggn_W, const float* __restrict__ aggn_b) {
  extern __shared__ float sm[];
  float* sU1 = sm;             float* sAggn = sm + 8192;
  float* sw2u = sm + 12288;    float* sb1u = sm + 12352;
  float* sbAggn = sm + 12416;  float* sZ = sm + 12480;
  float* sBeta = sm + 12544;   float* sRed = sm + 12584;
  float* sXT = sm + 12592;

  int tid = threadIdx.x, lane = tid & 31, w = tid >> 5;
  for (int i = tid; i < 8192; i += 256) sU1[i] = attu_W1[i];
  for (int i = tid; i < 4096; i += 256) sAggn[i] = aggn_W[i];
  if (tid < 64) { sw2u[tid] = attu_W2[tid]; sb1u[tid] = attu_b1[tid]; sbAggn[tid] = aggn_b[tid]; }
  __syncthreads();
  float cb2u = attu_b2[0];
  float* myXT = sXT + w * 1024;
  int rowbase = w * 5;

  for (int bi = 0; bi < 2; bi++) {
    int b = blockIdx.x * 2 + bi;
    __syncthreads();
    float msk[5];
#pragma unroll
    for (int j = 0; j < 5; j++) {
      int row = rowbase + j;
      int uq = u_user[b * 40 + row];
      msk[j] = (uq > 0) ? 1.f : 0.f;
      const float* hp = g_hoI + (long)(b * 40 + row) * 64;
      const float* up = user_table + (long)uq * 64;
      myXT[lane * 8 + j] = hp[lane]; myXT[(lane + 32) * 8 + j] = hp[lane + 32];
      myXT[(lane + 64) * 8 + j] = up[lane]; myXT[(lane + 96) * 8 + j] = up[lane + 32];
    }
    __syncwarp();
    float bc0 = sb1u[2 * lane], bc1 = sb1u[2 * lane + 1];
    ull a0[2], a1[2]; float s40 = bc0, s41 = bc1;
    a0[0] = a0[1] = pk2(bc0, bc0); a1[0] = a1[1] = pk2(bc1, bc1);
    wgemm2<128>(myXT, sU1, lane, a0, a1, s40, s41);
    float acc[5][2];
    unpack5(a0, a1, s40, s41, acc);
    float w0 = sw2u[2 * lane], w1 = sw2u[2 * lane + 1];
#pragma unroll
    for (int j = 0; j < 5; j++) {
      float p = fmaf(fmaxf(acc[j][0], 0.f), w0, fmaxf(acc[j][1], 0.f) * w1);
#pragma unroll
      for (int o = 16; o; o >>= 1) p += __shfl_xor_sync(0xffffffffu, p, o);
      if (lane == 0) sBeta[rowbase + j] = expf(p + cb2u) * msk[j];
    }
    __syncthreads();
    if (tid < 32) {
      float s = 0.f;
      for (int r = lane; r < 40; r += 32) s += sBeta[r];
#pragma unroll
      for (int o = 16; o; o >>= 1) s += __shfl_xor_sync(0xffffffffu, s, o);
      if (lane == 0) sRed[0] = s;
    }
    __syncthreads();
    float dinv = 1.f / (sRed[0] + EPSF);
    if (tid < 64) {
      float s = 0.f;
      for (int r = 0; r < 40; r++) s = fmaf(sBeta[r], g_hoI[(long)(b * 40 + r) * 64 + tid], s);
      sZ[tid] = s * dinv;
    }
    __syncthreads();
    if (tid < 64) {
      float s = sbAggn[tid];
      for (int k = 0; k < 64; k++) s = fmaf(sZ[k], sAggn[k * 64 + tid], s);
      g_hiS[b * 64 + tid] = fmaxf(s, 0.f);
    }
  }
}

// ---------------------------------------------------------------------------
// K3: final 3-layer combine MLP (FFMA2).
// ---------------------------------------------------------------------------
#define SMEM_K3 (24768 * 4)
__global__ __launch_bounds__(256) void k3_final(
    const float* __restrict__ cm_W1, const float* __restrict__ cm_b1,
    const float* __restrict__ cm_W2, const float* __restrict__ cm_b2,
    const float* __restrict__ cm_W3, const float* __restrict__ cm_b3,
    float* __restrict__ out) {
  extern __shared__ float sm[];
  float* sC1 = sm;          float* sC2 = sm + 8192;   float* sC3 = sm + 12288;
  float* sb1 = sm + 16384;  float* sb2 = sm + 16448;  float* sb3 = sm + 16512;
  float* sXT = sm + 16576;

  int tid = threadIdx.x, lane = tid & 31, w = tid >> 5;
  for (int i = tid; i < 8192; i += 256) sC1[i] = cm_W1[i];
  for (int i = tid; i < 4096; i += 256) { sC2[i] = cm_W2[i]; sC3[i] = cm_W3[i]; }
  if (tid < 64) { sb1[tid] = cm_b1[tid]; sb2[tid] = cm_b2[tid]; sb3[tid] = cm_b3[tid]; }
  __syncthreads();
  float* myXT = sXT + w * 1024;
  int rowbase = blockIdx.x * 40 + w * 5;
#pragma unroll
  for (int j = 0; j < 5; j++) {
    int row = rowbase + j;
    float x0 = 0, x1 = 0, x2 = 0, x3 = 0;
    if (row < BB) {
      x0 = g_hiI[row * 64 + lane]; x1 = g_hiI[row * 64 + 32 + lane];
      x2 = g_hiS[row * 64 + lane]; x3 = g_hiS[row * 64 + 32 + lane];
    }
    myXT[lane * 8 + j] = x0; myXT[(lane + 32) * 8 + j] = x1;
    myXT[(lane + 64) * 8 + j] = x2; myXT[(lane + 96) * 8 + j] = x3;
  }
  __syncwarp();
  float acc[5][2];
  {
    float bc0 = sb1[2 * lane], bc1 = sb1[2 * lane + 1];
    ull a0[2], a1[2]; float s40 = bc0, s41 = bc1;
    a0[0] = a0[1] = pk2(bc0, bc0); a1[0] = a1[1] = pk2(bc1, bc1);
    wgemm2<128>(myXT, sC1, lane, a0, a1, s40, s41);
    unpack5(a0, a1, s40, s41, acc);
  }
#pragma unroll
  for (int j = 0; j < 5; j++) { acc[j][0] = fmaxf(acc[j][0], 0.f); acc[j][1] = fmaxf(acc[j][1], 0.f); }
  __syncwarp(); wtrans(myXT, lane, acc); __syncwarp();
  {
    float bc0 = sb2[2 * lane], bc1 = sb2[2 * lane + 1];
    ull a0[2], a1[2]; float s40 = bc0, s41 = bc1;
    a0[0] = a0[1] = pk2(bc0, bc0); a1[0] = a1[1] = pk2(bc1, bc1);
    wgemm2<64>(myXT, sC2, lane, a0, a1, s40, s41);
    unpack5(a0, a1, s40, s41, acc);
  }
#pragma unroll
  for (int j = 0; j < 5; j++) { acc[j][0] = fmaxf(acc[j][0], 0.f); acc[j][1] = fmaxf(acc[j][1], 0.f); }
  __syncwarp(); wtrans(myXT, lane, acc); __syncwarp();
  {
    float bc0 = sb3[2 * lane], bc1 = sb3[2 * lane + 1];
    ull a0[2], a1[2]; float s40 = bc0, s41 = bc1;
    a0[0] = a0[1] = pk2(bc0, bc0); a1[0] = a1[1] = pk2(bc1, bc1);
    wgemm2<64>(myXT, sC3, lane, a0, a1, s40, s41);
    unpack5(a0, a1, s40, s41, acc);
  }
#pragma unroll
  for (int j = 0; j < 5; j++) {
    int row = rowbase + j;
    if (row < BB) {
      out[row * 64 + 2 * lane]     = fmaxf(acc[j][0], 0.f);
      out[row * 64 + 2 * lane + 1] = fmaxf(acc[j][1], 0.f);
    }
  }
}

// ---------------------------------------------------------------------------
extern "C" void kernel_launch(void* const* d_in, const int* in_sizes, int n_in,
                              void* d_out, int out_size) {
  const int* uids        = (const int*)d_in[0];
  const int* u_item      = (const int*)d_in[1];
  const int* u_user      = (const int*)d_in[2];
  const int* u_user_item = (const int*)d_in[3];
  const float* user_table = (const float*)d_in[4];
  const float* item_table = (const float*)d_in[5];
  const float* rate_table = (const float*)d_in[6];
  const float* gv_W1 = (const float*)d_in[7];   const float* gv_b1 = (const float*)d_in[8];
  const float* gv_W2 = (const float*)d_in[9];   const float* gv_b2 = (const float*)d_in[10];
  const float* atti_W1 = (const float*)d_in[11]; const float* atti_b1 = (const float*)d_in[12];
  const float* atti_W2 = (const float*)d_in[13]; const float* atti_b2 = (const float*)d_in[14];
  const float* agg_W = (const float*)d_in[15];   const float* agg_b = (const float*)d_in[16];
  const float* attu_W1 = (const float*)d_in[17]; const float* attu_b1 = (const float*)d_in[18];
  const float* attu_W2 = (const float*)d_in[19]; const float* attu_b2 = (const float*)d_in[20];
  const float* aggn_W = (const float*)d_in[21];  const float* aggn_b = (const float*)d_in[22];
  const float* cm_W1 = (const float*)d_in[23];   const float* cm_b1 = (const float*)d_in[24];
  const float* cm_W2 = (const float*)d_in[25];   const float* cm_b2 = (const float*)d_in[26];
  const float* cm_W3 = (const float*)d_in[27];   const float* cm_b3 = (const float*)d_in[28];
  float* out = (float*)d_out;

  cudaFuncSetAttribute(k0_proj,  cudaFuncAttributeMaxDynamicSharedMemorySize, SMEM_K0P);
  cudaFuncSetAttribute(k0_combo, cudaFuncAttributeMaxDynamicSharedMemorySize, SMEM_K0C);
  cudaFuncSetAttribute(k2b_user, cudaFuncAttributeMaxDynamicSharedMemorySize, SMEM_K2B);
  cudaFuncSetAttribute(k3_final, cudaFuncAttributeMaxDynamicSharedMemorySize, SMEM_K3);

  k0_pre<<<33, 256>>>(rate_table, gv_W1, gv_b1, gv_W2, gv_b2, atti_W1, atti_b1, agg_W);
  k0_proj<<<500, 256, SMEM_K0P>>>(item_table, user_table, gv_W1, atti_W1);
  k0_combo<<<1875, 256, SMEM_K0C>>>();
  k2s1_attn<<<64 + 2560, 256>>>(uids, u_user, u_user_item, u_item,
                                agg_b, atti_W2, atti_b2);
  k2b_user<<<256, 256, SMEM_K2B>>>(u_user, user_table, attu_W1, attu_b1, attu_W2,
                                   attu_b2, aggn_W, aggn_b);
  k3_final<<<13, 256, SMEM_K3>>>(cm_W1, cm_b1, cm_W2, cm_b2, cm_W3, cm_b3, out);
}